// round 1
// baseline (speedup 1.0000x reference)
#include <cuda_runtime.h>
#include <math.h>

// Problem constants
#define LSEQ   8192
#define NFFT   16384
#define CH     1024
#define BATCH  2
#define MTOT   (BATCH*LSEQ)      // 16384 rows

// ---------------- scratch (device globals; no allocations allowed) ----------
__device__ float g_Vrow [MTOT*CH];     // in_proj v branch, row-major [m][c]
__device__ float g_X2row[MTOT*CH];     // in_proj x2 branch, row-major [m][c]
__device__ float g_Vt   [CH*MTOT];     // short-conv'd v, channel-major [c][b*L+l]
__device__ float g_X2t  [CH*MTOT];     // x2, channel-major
__device__ float g_H2   [LSEQ*128];    // filter MLP hidden (L x 128)
__device__ float g_COEF [LSEQ*CH];     // filter coefs order-1, row-major [l][c]
__device__ float g_COEFt[CH*LSEQ];     // channel-major [c][l]
__device__ float g_Gt   [CH*MTOT];     // gated conv output, K-major [c][m]

// ---------------- helpers ---------------------------------------------------
__device__ __forceinline__ float gelu_exact(float x) {
    return 0.5f * x * (1.0f + erff(x * 0.70710678118654752f));
}
__device__ __forceinline__ float2 cmulf(float2 a, float2 b) {
    return make_float2(a.x*b.x - a.y*b.y, a.x*b.y + a.y*b.x);
}

// ============================================================================
// GEMM 1: proj = x @ in_proj_w (gathered columns {3c, 3c+2}) + bias
// M=16384, N=2048 (virtual), K=1024.  Split epilogue -> g_Vrow / g_X2row.
// ============================================================================
__global__ __launch_bounds__(256) void gemm_inproj(
    const float* __restrict__ A, const float* __restrict__ W,
    const float* __restrict__ bias)
{
    __shared__ float As[8][128];
    __shared__ float Bs[8][128];
    const int tid = threadIdx.x;
    const int tx = tid & 15, ty = tid >> 4;
    const int m0 = blockIdx.y * 128;
    const int n0 = blockIdx.x * 128;

    float acc[8][8];
    #pragma unroll
    for (int i = 0; i < 8; i++)
        #pragma unroll
        for (int j = 0; j < 8; j++) acc[i][j] = 0.f;

    const int arow = tid >> 1, akq = (tid & 1) * 4;
    const int bn = tid & 127;
    const int ng = n0 + bn;
    const int jmap = 3 * (ng >> 1) + (ng & 1) * 2;   // column gather into 3072-wide W
    const int kk0 = (tid >> 7) * 4;                  // 0 or 4

    for (int k0 = 0; k0 < 1024; k0 += 8) {
        float4 av = *(const float4*)&A[(size_t)(m0 + arow) * 1024 + k0 + akq];
        As[akq+0][arow] = av.x; As[akq+1][arow] = av.y;
        As[akq+2][arow] = av.z; As[akq+3][arow] = av.w;
        #pragma unroll
        for (int r = 0; r < 4; r++)
            Bs[kk0 + r][bn] = W[(size_t)(k0 + kk0 + r) * 3072 + jmap];
        __syncthreads();
        #pragma unroll
        for (int kk = 0; kk < 8; kk++) {
            float a[8], b[8];
            #pragma unroll
            for (int i = 0; i < 8; i++) a[i] = As[kk][ty*8 + i];
            #pragma unroll
            for (int j = 0; j < 8; j++) b[j] = Bs[kk][tx*8 + j];
            #pragma unroll
            for (int i = 0; i < 8; i++)
                #pragma unroll
                for (int j = 0; j < 8; j++) acc[i][j] += a[i] * b[j];
        }
        __syncthreads();
    }

    const int cbase = (n0 >> 1) + tx * 4;
    float bv[4], bx[4];
    #pragma unroll
    for (int r = 0; r < 4; r++) {
        bv[r] = bias[3*(cbase+r)];
        bx[r] = bias[3*(cbase+r) + 2];
    }
    #pragma unroll
    for (int i = 0; i < 8; i++) {
        int m = m0 + ty*8 + i;
        float4 v4 = make_float4(acc[i][0]+bv[0], acc[i][2]+bv[1],
                                acc[i][4]+bv[2], acc[i][6]+bv[3]);
        float4 x4 = make_float4(acc[i][1]+bx[0], acc[i][3]+bx[1],
                                acc[i][5]+bx[2], acc[i][7]+bx[3]);
        *(float4*)&g_Vrow [(size_t)m*CH + cbase] = v4;
        *(float4*)&g_X2row[(size_t)m*CH + cbase] = x4;
    }
}

// ============================================================================
// Depthwise short conv (k=3, pad 1, per batch) fused with transpose to [c][m]
// ============================================================================
__global__ void shortconv_transpose(const float* __restrict__ sw,
                                    const float* __restrict__ sb)
{
    __shared__ float s[32][33];
    const int c0 = blockIdx.x * 32;
    const int m0 = blockIdx.y * 32;
    const int b  = m0 / LSEQ;
    const int l0 = m0 - b * LSEQ;
    const int tx = threadIdx.x, ty = threadIdx.y;
    const int c = c0 + tx;
    const int l = l0 + ty;

    size_t base = (size_t)(b*LSEQ + l) * CH + c;
    float vc = g_Vrow[base];
    float vm = (l > 0)       ? g_Vrow[base - CH] : 0.f;
    float vp = (l < LSEQ-1)  ? g_Vrow[base + CH] : 0.f;
    float w0 = sw[c*3], w1 = sw[c*3+1], w2 = sw[c*3+2];
    s[ty][tx] = w0*vm + w1*vc + w2*vp + sb[c];
    __syncthreads();
    g_Vt[(size_t)(c0 + ty) * MTOT + b*LSEQ + l0 + tx] = s[tx][ty];
}

// generic [M][1024] -> [1024][M] transposes (fixed src/dst to avoid symbol APIs)
__global__ void transpose_x2() {
    __shared__ float s[32][33];
    const int c0 = blockIdx.x * 32, m0 = blockIdx.y * 32;
    const int tx = threadIdx.x, ty = threadIdx.y;
    s[ty][tx] = g_X2row[(size_t)(m0+ty)*CH + c0 + tx];
    __syncthreads();
    g_X2t[(size_t)(c0+ty)*MTOT + m0 + tx] = s[tx][ty];
}
__global__ void transpose_coef() {
    __shared__ float s[32][33];
    const int c0 = blockIdx.x * 32, m0 = blockIdx.y * 32;
    const int tx = threadIdx.x, ty = threadIdx.y;
    s[ty][tx] = g_COEF[(size_t)(m0+ty)*CH + c0 + tx];
    __syncthreads();
    g_COEFt[(size_t)(c0+ty)*LSEQ + m0 + tx] = s[tx][ty];
}

// ============================================================================
// Filter MLP part 1: h2[l][t] for t in [0,128)
// ============================================================================
__global__ void filter_h2(const float* __restrict__ fw1, const float* __restrict__ fb1,
                          const float* __restrict__ fw2, const float* __restrict__ fb2)
{
    __shared__ float h1[64];
    const int l = blockIdx.x;
    const int t = threadIdx.x;
    const float pos = (float)l / (float)(LSEQ - 1);
    if (t < 64) h1[t] = gelu_exact(pos * fw1[t] + fb1[t]);
    __syncthreads();
    float s = fb2[t];
    #pragma unroll 8
    for (int j = 0; j < 64; j++) s += h1[j] * fw2[j*128 + t];
    g_H2[(size_t)l*128 + t] = gelu_exact(s);
}

// ============================================================================
// GEMM coef: COEF[l][c] = h2 @ fw3[:, 2c+1] + fb3[2c+1]
// M=8192, N=1024, K=128
// ============================================================================
__global__ __launch_bounds__(256) void gemm_coef(
    const float* __restrict__ fw3, const float* __restrict__ fb3)
{
    __shared__ float As[8][128];
    __shared__ float Bs[8][128];
    const int tid = threadIdx.x;
    const int tx = tid & 15, ty = tid >> 4;
    const int m0 = blockIdx.y * 128;
    const int n0 = blockIdx.x * 128;

    float acc[8][8];
    #pragma unroll
    for (int i = 0; i < 8; i++)
        #pragma unroll
        for (int j = 0; j < 8; j++) acc[i][j] = 0.f;

    const int arow = tid >> 1, akq = (tid & 1) * 4;
    const int bn = tid & 127;
    const int jm = 2 * (n0 + bn) + 1;
    const int kk0 = (tid >> 7) * 4;

    for (int k0 = 0; k0 < 128; k0 += 8) {
        float4 av = *(const float4*)&g_H2[(size_t)(m0 + arow) * 128 + k0 + akq];
        As[akq+0][arow] = av.x; As[akq+1][arow] = av.y;
        As[akq+2][arow] = av.z; As[akq+3][arow] = av.w;
        #pragma unroll
        for (int r = 0; r < 4; r++)
            Bs[kk0 + r][bn] = fw3[(size_t)(k0 + kk0 + r) * 2048 + jm];
        __syncthreads();
        #pragma unroll
        for (int kk = 0; kk < 8; kk++) {
            float a[8], b[8];
            #pragma unroll
            for (int i = 0; i < 8; i++) a[i] = As[kk][ty*8 + i];
            #pragma unroll
            for (int j = 0; j < 8; j++) b[j] = Bs[kk][tx*8 + j];
            #pragma unroll
            for (int i = 0; i < 8; i++)
                #pragma unroll
                for (int j = 0; j < 8; j++) acc[i][j] += a[i] * b[j];
        }
        __syncthreads();
    }

    float bo[8];
    #pragma unroll
    for (int j = 0; j < 8; j++) bo[j] = fb3[2*(n0 + tx*8 + j) + 1];
    #pragma unroll
    for (int i = 0; i < 8; i++) {
        int m = m0 + ty*8 + i;
        float4 o0 = make_float4(acc[i][0]+bo[0], acc[i][1]+bo[1],
                                acc[i][2]+bo[2], acc[i][3]+bo[3]);
        float4 o1 = make_float4(acc[i][4]+bo[4], acc[i][5]+bo[5],
                                acc[i][6]+bo[6], acc[i][7]+bo[7]);
        *(float4*)&g_COEF[(size_t)m*CH + n0 + tx*8]     = o0;
        *(float4*)&g_COEF[(size_t)m*CH + n0 + tx*8 + 4] = o1;
    }
}

// ============================================================================
// FFT convolution per channel.  One CTA per channel.
// smem: Z[16384] complex, Hs[8193(+pad)] complex, quarter twiddle table[4096].
// Forward DIT (bit-rev in), inverse DIF (bit-rev out).
// Packs v(batch0)+i*v(batch1) in one FFT; both convs from one inverse FFT.
// ============================================================================
#define FFT_T   512
#define HS_OFF  16384
#define WT_OFF  (16384 + 8208)
#define FFT_SMEM ((16384 + 8208 + 4096) * 8)

__device__ __forceinline__ float2 twid(const float2* Wt, int k) {
    // W[k] = exp(-2*pi*i*k/N), k in [0, 8192); quarter table [0,4096)
    if (k < 4096) return Wt[k];
    float2 w = Wt[k - 4096];
    return make_float2(w.y, -w.x);      // multiply by -i
}

__device__ void fft_dit(float2* Z, const float2* Wt, int tid) {
    int loglen = 1;
    for (int len = 2; len <= NFFT; len <<= 1, loglen++) {
        const int half = len >> 1;
        for (int b = tid; b < NFFT/2; b += FFT_T) {
            const int p  = b & (half - 1);
            const int i0 = 2*b - p;
            const int i1 = i0 + half;
            float2 w = twid(Wt, p << (14 - loglen));
            float2 u = Z[i0];
            float2 t = cmulf(Z[i1], w);
            Z[i0] = make_float2(u.x + t.x, u.y + t.y);
            Z[i1] = make_float2(u.x - t.x, u.y - t.y);
        }
        __syncthreads();
    }
}

__device__ void ifft_dif(float2* Z, const float2* Wt, int tid) {
    int loglen = 14;
    for (int len = NFFT; len >= 2; len >>= 1, loglen--) {
        const int half = len >> 1;
        for (int b = tid; b < NFFT/2; b += FFT_T) {
            const int p  = b & (half - 1);
            const int i0 = 2*b - p;
            const int i1 = i0 + half;
            float2 u = Z[i0], v = Z[i1];
            Z[i0] = make_float2(u.x + v.x, u.y + v.y);
            float2 d = make_float2(u.x - v.x, u.y - v.y);
            float2 w = twid(Wt, p << (14 - loglen));
            // d * conj(w)
            Z[i1] = make_float2(d.x*w.x + d.y*w.y, d.y*w.x - d.x*w.y);
        }
        __syncthreads();
    }
}

__global__ __launch_bounds__(FFT_T, 1) void fft_conv_kernel() {
    extern __shared__ float2 sm[];
    float2* Z  = sm;
    float2* Hs = sm + HS_OFF;
    float2* Wt = sm + WT_OFF;
    const int c   = blockIdx.x;
    const int tid = threadIdx.x;

    // build quarter twiddle table: W[k] = (cos(2pik/N), -sin(2pik/N))
    for (int k = tid; k < 4096; k += FFT_T) {
        float ang = 3.834951969714103e-4f * (float)k;   // 2*pi/16384 * k
        float sv, cv;
        sincosf(ang, &sv, &cv);
        Wt[k] = make_float2(cv, -sv);
    }

    // ---- forward FFT of filter h (zero-padded), bit-reversed load ----
    const float* hsrc = g_COEFt + (size_t)c * LSEQ;
    for (int i = tid; i < NFFT; i += FFT_T) {
        float re = (i < LSEQ) ? hsrc[i] : 0.f;
        Z[__brev((unsigned)i) >> 18] = make_float2(re, 0.f);
    }
    __syncthreads();
    fft_dit(Z, Wt, tid);

    // stash half-spectrum of H
    for (int k = tid; k <= NFFT/2; k += FFT_T) Hs[k] = Z[k];
    __syncthreads();

    // ---- forward FFT of v (batch0 in re, batch1 in im) ----
    const float* v0 = g_Vt + (size_t)c * MTOT;
    const float* v1 = v0 + LSEQ;
    for (int i = tid; i < NFFT; i += FFT_T) {
        float re = (i < LSEQ) ? v0[i] : 0.f;
        float im = (i < LSEQ) ? v1[i] : 0.f;
        Z[__brev((unsigned)i) >> 18] = make_float2(re, im);
    }
    __syncthreads();
    fft_dit(Z, Wt, tid);

    // ---- unpack spectra, multiply by H, repack for inverse ----
    for (int k = tid; k <= NFFT/2; k += FFT_T) {
        const int k2 = (NFFT - k) & (NFFT - 1);
        float2 Zk = Z[k], Zn = Z[k2];
        float2 V0 = make_float2(0.5f*(Zk.x + Zn.x), 0.5f*(Zk.y - Zn.y));
        float2 V1 = make_float2(0.5f*(Zk.y + Zn.y), 0.5f*(Zn.x - Zk.x));
        float2 H  = Hs[k];
        float2 C0 = cmulf(V0, H);
        float2 C1 = cmulf(V1, H);
        Z[k]  = make_float2(C0.x - C1.y, C0.y + C1.x);
        Z[k2] = make_float2(C0.x + C1.y, C1.x - C0.y);
    }
    __syncthreads();

    // ---- inverse FFT (natural in, bit-reversed out) ----
    ifft_dif(Z, Wt, tid);

    // ---- gate with x2 and store (K-major for the output GEMM) ----
    const float* x2 = g_X2t + (size_t)c * MTOT;
    float* go = g_Gt + (size_t)c * MTOT;
    const float scale = 1.0f / (float)NFFT;
    for (int l = tid; l < LSEQ; l += FFT_T) {
        float2 d0 = Z[__brev((unsigned)l) >> 18];
        go[l]        = x2[l]        * (d0.x * scale);
        go[LSEQ + l] = x2[LSEQ + l] * (d0.y * scale);
    }
}

// ============================================================================
// GEMM out: out[m][n] = sum_c Gt[c][m] * out_w[c][n] + out_b[n]
// A is K-major (Gt), M=16384, N=1024, K=1024
// ============================================================================
__global__ __launch_bounds__(256) void gemm_out(
    const float* __restrict__ W, const float* __restrict__ bias,
    float* __restrict__ out)
{
    __shared__ float As[8][128];
    __shared__ float Bs[8][128];
    const int tid = threadIdx.x;
    const int tx = tid & 15, ty = tid >> 4;
    const int m0 = blockIdx.y * 128;
    const int n0 = blockIdx.x * 128;

    float acc[8][8];
    #pragma unroll
    for (int i = 0; i < 8; i++)
        #pragma unroll
        for (int j = 0; j < 8; j++) acc[i][j] = 0.f;

    const int lkk = tid >> 5;          // 0..7
    const int lx4 = (tid & 31) * 4;    // 0..124

    for (int k0 = 0; k0 < 1024; k0 += 8) {
        float4 av = *(const float4*)&g_Gt[(size_t)(k0 + lkk) * MTOT + m0 + lx4];
        *(float4*)&As[lkk][lx4] = av;
        float4 bvv = *(const float4*)&W[(size_t)(k0 + lkk) * CH + n0 + lx4];
        *(float4*)&Bs[lkk][lx4] = bvv;
        __syncthreads();
        #pragma unroll
        for (int kk = 0; kk < 8; kk++) {
            float a[8], b[8];
            #pragma unroll
            for (int i = 0; i < 8; i++) a[i] = As[kk][ty*8 + i];
            #pragma unroll
            for (int j = 0; j < 8; j++) b[j] = Bs[kk][tx*8 + j];
            #pragma unroll
            for (int i = 0; i < 8; i++)
                #pragma unroll
                for (int j = 0; j < 8; j++) acc[i][j] += a[i] * b[j];
        }
        __syncthreads();
    }

    float bo[8];
    #pragma unroll
    for (int j = 0; j < 8; j++) bo[j] = bias[n0 + tx*8 + j];
    #pragma unroll
    for (int i = 0; i < 8; i++) {
        int m = m0 + ty*8 + i;
        float4 o0 = make_float4(acc[i][0]+bo[0], acc[i][1]+bo[1],
                                acc[i][2]+bo[2], acc[i][3]+bo[3]);
        float4 o1 = make_float4(acc[i][4]+bo[4], acc[i][5]+bo[5],
                                acc[i][6]+bo[6], acc[i][7]+bo[7]);
        *(float4*)&out[(size_t)m*CH + n0 + tx*8]     = o0;
        *(float4*)&out[(size_t)m*CH + n0 + tx*8 + 4] = o1;
    }
}

// ============================================================================
extern "C" void kernel_launch(void* const* d_in, const int* in_sizes, int n_in,
                              void* d_out, int out_size)
{
    const float* x   = (const float*)d_in[0];
    const float* ipw = (const float*)d_in[1];
    const float* ipb = (const float*)d_in[2];
    const float* sw  = (const float*)d_in[3];
    const float* sb  = (const float*)d_in[4];
    const float* fw1 = (const float*)d_in[5];
    const float* fb1 = (const float*)d_in[6];
    const float* fw2 = (const float*)d_in[7];
    const float* fb2 = (const float*)d_in[8];
    const float* fw3 = (const float*)d_in[9];
    const float* fb3 = (const float*)d_in[10];
    const float* ow  = (const float*)d_in[11];
    const float* ob  = (const float*)d_in[12];
    float* out = (float*)d_out;

    cudaFuncSetAttribute(fft_conv_kernel,
                         cudaFuncAttributeMaxDynamicSharedMemorySize, FFT_SMEM);

    // 1) in_proj GEMM (only v and x2 branches; x1 is dead in the reference)
    gemm_inproj<<<dim3(16, 128), 256>>>(x, ipw, ipb);
    // 2) depthwise short conv + transpose to channel-major
    shortconv_transpose<<<dim3(32, 512), dim3(32, 32)>>>(sw, sb);
    // 3) x2 transpose
    transpose_x2<<<dim3(32, 512), dim3(32, 32)>>>();
    // 4) filter MLP hidden
    filter_h2<<<LSEQ, 128>>>(fw1, fb1, fw2, fb2);
    // 5) filter coef GEMM (only order index 1 survives the reference loop)
    gemm_coef<<<dim3(8, 64), 256>>>(fw3, fb3);
    // 6) coef transpose
    transpose_coef<<<dim3(32, 256), dim3(32, 32)>>>();
    // 7) FFT long conv + gating (one CTA per channel)
    fft_conv_kernel<<<CH, FFT_T, FFT_SMEM>>>();
    // 8) output projection GEMM
    gemm_out<<<dim3(8, 128), 256>>>(ow, ob, out);
}

// round 2
// speedup vs baseline: 1.0752x; 1.0752x over previous
#include <cuda_runtime.h>
#include <math.h>
#include <stdint.h>

// Problem constants
#define LSEQ   8192
#define NFFT   16384
#define CH     1024
#define BATCH  2
#define MTOT   (BATCH*LSEQ)      // 16384 rows

// ---------------- scratch (device globals; no allocations allowed) ----------
__device__ float g_Vrow [MTOT*CH];     // in_proj v branch, row-major [m][c]
__device__ float g_X2row[MTOT*CH];     // in_proj x2 branch, row-major [m][c]
__device__ float g_Vt   [CH*MTOT];     // short-conv'd v, channel-major [c][b*L+l]
__device__ float g_X2t  [CH*MTOT];     // x2, channel-major
__device__ float g_H2   [LSEQ*128];    // filter MLP hidden (L x 128)
__device__ float g_COEF [LSEQ*CH];     // filter coefs order-1, row-major [l][c]
__device__ float g_COEFt[CH*LSEQ];     // channel-major [c][l]
__device__ float g_Gt   [CH*MTOT];     // gated conv output, K-major [c][m]

// ---------------- helpers ---------------------------------------------------
__device__ __forceinline__ float gelu_exact(float x) {
    return 0.5f * x * (1.0f + erff(x * 0.70710678118654752f));
}
__device__ __forceinline__ float2 cmulf(float2 a, float2 b) {
    return make_float2(a.x*b.x - a.y*b.y, a.x*b.y + a.y*b.x);
}
__device__ __forceinline__ void split_tf32(float v, uint32_t &hi, uint32_t &lo) {
    asm("cvt.rna.tf32.f32 %0, %1;" : "=r"(hi) : "f"(v));
    float r = v - __uint_as_float(hi);
    asm("cvt.rna.tf32.f32 %0, %1;" : "=r"(lo) : "f"(r));
}
__device__ __forceinline__ void mma4(float c[4], const uint32_t a[4], const uint32_t b[2]) {
    asm volatile("mma.sync.aligned.m16n8k8.row.col.f32.tf32.tf32.f32 "
        "{%0,%1,%2,%3}, {%4,%5,%6,%7}, {%8,%9}, {%0,%1,%2,%3};"
        : "+f"(c[0]), "+f"(c[1]), "+f"(c[2]), "+f"(c[3])
        : "r"(a[0]), "r"(a[1]), "r"(a[2]), "r"(a[3]), "r"(b[0]), "r"(b[1]));
}

#define SA 136   // smem row stride (floats): (8k + m) % 32 -> conflict-free frags

// ============================================================================
// GEMM 1 (tensor core, 3xTF32): proj = x @ in_proj_w (cols {3c, 3c+2}) + bias
// M=16384, N=2048 (virtual), K=1024.  Split epilogue -> g_Vrow / g_X2row.
// ============================================================================
__global__ __launch_bounds__(256) void gemm_inproj_tc(
    const float* __restrict__ A, const float* __restrict__ W,
    const float* __restrict__ bias)
{
    __shared__ uint32_t Ah[16][SA], Al[16][SA], Bh[16][SA], Bl[16][SA];
    const int tid  = threadIdx.x;
    const int lane = tid & 31;
    const int wid  = tid >> 5;
    const int wm   = wid >> 1;        // 0..3  (32 rows each)
    const int wn   = wid & 1;         // 0..1  (64 cols each)
    const int m0   = blockIdx.y * 128;
    const int n0   = blockIdx.x * 128;

    // staging indices
    const int arow = tid >> 1;
    const int akc  = (tid & 1) * 8;
    const int bn   = tid & 127;
    const int ng   = n0 + bn;
    const int jmap = 3 * (ng >> 1) + (ng & 1) * 2;
    const int bkr  = (tid >> 7) * 8;

    float acc[2][8][4];
    #pragma unroll
    for (int i = 0; i < 2; i++)
        #pragma unroll
        for (int j = 0; j < 8; j++)
            #pragma unroll
            for (int q = 0; q < 4; q++) acc[i][j][q] = 0.f;

    float4 pa0, pa1;
    float  pb[8];
    pa0 = *(const float4*)&A[(size_t)(m0 + arow) * 1024 + akc];
    pa1 = *(const float4*)&A[(size_t)(m0 + arow) * 1024 + akc + 4];
    #pragma unroll
    for (int r = 0; r < 8; r++) pb[r] = W[(size_t)(bkr + r) * 3072 + jmap];

    for (int it = 0; it < 64; ++it) {
        {   // split + stage
            float av[8] = {pa0.x, pa0.y, pa0.z, pa0.w, pa1.x, pa1.y, pa1.z, pa1.w};
            #pragma unroll
            for (int j = 0; j < 8; j++) {
                uint32_t h, l; split_tf32(av[j], h, l);
                Ah[akc + j][arow] = h; Al[akc + j][arow] = l;
            }
            #pragma unroll
            for (int r = 0; r < 8; r++) {
                uint32_t h, l; split_tf32(pb[r], h, l);
                Bh[bkr + r][bn] = h; Bl[bkr + r][bn] = l;
            }
        }
        __syncthreads();
        if (it < 63) {
            const int k0 = (it + 1) * 16;
            pa0 = *(const float4*)&A[(size_t)(m0 + arow) * 1024 + k0 + akc];
            pa1 = *(const float4*)&A[(size_t)(m0 + arow) * 1024 + k0 + akc + 4];
            #pragma unroll
            for (int r = 0; r < 8; r++)
                pb[r] = W[(size_t)(k0 + bkr + r) * 3072 + jmap];
        }
        #pragma unroll
        for (int ks = 0; ks < 2; ks++) {
            const int kq = ks * 8 + (lane & 3);
            uint32_t ah[2][4], al[2][4], bh[8][2], bl[8][2];
            #pragma unroll
            for (int mt = 0; mt < 2; mt++) {
                const int mo = wm * 32 + mt * 16 + (lane >> 2);
                ah[mt][0] = Ah[kq][mo];     ah[mt][1] = Ah[kq][mo + 8];
                ah[mt][2] = Ah[kq + 4][mo]; ah[mt][3] = Ah[kq + 4][mo + 8];
                al[mt][0] = Al[kq][mo];     al[mt][1] = Al[kq][mo + 8];
                al[mt][2] = Al[kq + 4][mo]; al[mt][3] = Al[kq + 4][mo + 8];
            }
            #pragma unroll
            for (int nt = 0; nt < 8; nt++) {
                const int no = wn * 64 + nt * 8 + (lane >> 2);
                bh[nt][0] = Bh[kq][no]; bh[nt][1] = Bh[kq + 4][no];
                bl[nt][0] = Bl[kq][no]; bl[nt][1] = Bl[kq + 4][no];
            }
            #pragma unroll
            for (int mt = 0; mt < 2; mt++)
                #pragma unroll
                for (int nt = 0; nt < 8; nt++) {
                    mma4(acc[mt][nt], ah[mt], bh[nt]);
                    mma4(acc[mt][nt], ah[mt], bl[nt]);
                    mma4(acc[mt][nt], al[mt], bh[nt]);
                }
        }
        __syncthreads();
    }

    #pragma unroll
    for (int mt = 0; mt < 2; mt++) {
        const int r0 = m0 + wm * 32 + mt * 16 + (lane >> 2);
        #pragma unroll
        for (int nt = 0; nt < 8; nt++) {
            const int vn = n0 + wn * 64 + nt * 8 + 2 * (lane & 3);  // even
            const int ch = vn >> 1;
            const float bv = bias[3 * ch];
            const float bx = bias[3 * ch + 2];
            g_Vrow [(size_t)r0 * CH + ch]       = acc[mt][nt][0] + bv;
            g_X2row[(size_t)r0 * CH + ch]       = acc[mt][nt][1] + bx;
            g_Vrow [(size_t)(r0 + 8) * CH + ch] = acc[mt][nt][2] + bv;
            g_X2row[(size_t)(r0 + 8) * CH + ch] = acc[mt][nt][3] + bx;
        }
    }
}

// ============================================================================
// GEMM out (tensor core, 3xTF32): out[m][n] = sum_c Gt[c][m]*W[c][n] + b[n]
// A K-major (g_Gt).  M=16384, N=1024, K=1024
// ============================================================================
__global__ __launch_bounds__(256) void gemm_out_tc(
    const float* __restrict__ W, const float* __restrict__ bias,
    float* __restrict__ out)
{
    __shared__ uint32_t Ah[16][SA], Al[16][SA], Bh[16][SA], Bl[16][SA];
    const int tid  = threadIdx.x;
    const int lane = tid & 31;
    const int wid  = tid >> 5;
    const int wm   = wid >> 1;
    const int wn   = wid & 1;
    const int m0   = blockIdx.y * 128;
    const int n0   = blockIdx.x * 128;

    // staging: thread handles float4 elements f = tid*2 + {0,1} of 512
    const int f0 = tid * 2;
    const int ka0 = f0 >> 5,        ka1 = (f0 + 1) >> 5;
    const int ma0 = (f0 & 31) * 4,  ma1 = ((f0 + 1) & 31) * 4;

    float acc[2][8][4];
    #pragma unroll
    for (int i = 0; i < 2; i++)
        #pragma unroll
        for (int j = 0; j < 8; j++)
            #pragma unroll
            for (int q = 0; q < 4; q++) acc[i][j][q] = 0.f;

    float4 pa0, pa1, pb0, pb1;
    pa0 = *(const float4*)&g_Gt[(size_t)ka0 * MTOT + m0 + ma0];
    pa1 = *(const float4*)&g_Gt[(size_t)ka1 * MTOT + m0 + ma1];
    pb0 = *(const float4*)&W[(size_t)ka0 * CH + n0 + ma0];
    pb1 = *(const float4*)&W[(size_t)ka1 * CH + n0 + ma1];

    for (int it = 0; it < 64; ++it) {
        {
            float a0[4] = {pa0.x, pa0.y, pa0.z, pa0.w};
            float a1[4] = {pa1.x, pa1.y, pa1.z, pa1.w};
            float b0[4] = {pb0.x, pb0.y, pb0.z, pb0.w};
            float b1[4] = {pb1.x, pb1.y, pb1.z, pb1.w};
            #pragma unroll
            for (int j = 0; j < 4; j++) {
                uint32_t h, l;
                split_tf32(a0[j], h, l); Ah[ka0][ma0 + j] = h; Al[ka0][ma0 + j] = l;
                split_tf32(a1[j], h, l); Ah[ka1][ma1 + j] = h; Al[ka1][ma1 + j] = l;
                split_tf32(b0[j], h, l); Bh[ka0][ma0 + j] = h; Bl[ka0][ma0 + j] = l;
                split_tf32(b1[j], h, l); Bh[ka1][ma1 + j] = h; Bl[ka1][ma1 + j] = l;
            }
        }
        __syncthreads();
        if (it < 63) {
            const int k0 = (it + 1) * 16;
            pa0 = *(const float4*)&g_Gt[(size_t)(k0 + ka0) * MTOT + m0 + ma0];
            pa1 = *(const float4*)&g_Gt[(size_t)(k0 + ka1) * MTOT + m0 + ma1];
            pb0 = *(const float4*)&W[(size_t)(k0 + ka0) * CH + n0 + ma0];
            pb1 = *(const float4*)&W[(size_t)(k0 + ka1) * CH + n0 + ma1];
        }
        #pragma unroll
        for (int ks = 0; ks < 2; ks++) {
            const int kq = ks * 8 + (lane & 3);
            uint32_t ah[2][4], al[2][4], bh[8][2], bl[8][2];
            #pragma unroll
            for (int mt = 0; mt < 2; mt++) {
                const int mo = wm * 32 + mt * 16 + (lane >> 2);
                ah[mt][0] = Ah[kq][mo];     ah[mt][1] = Ah[kq][mo + 8];
                ah[mt][2] = Ah[kq + 4][mo]; ah[mt][3] = Ah[kq + 4][mo + 8];
                al[mt][0] = Al[kq][mo];     al[mt][1] = Al[kq][mo + 8];
                al[mt][2] = Al[kq + 4][mo]; al[mt][3] = Al[kq + 4][mo + 8];
            }
            #pragma unroll
            for (int nt = 0; nt < 8; nt++) {
                const int no = wn * 64 + nt * 8 + (lane >> 2);
                bh[nt][0] = Bh[kq][no]; bh[nt][1] = Bh[kq + 4][no];
                bl[nt][0] = Bl[kq][no]; bl[nt][1] = Bl[kq + 4][no];
            }
            #pragma unroll
            for (int mt = 0; mt < 2; mt++)
                #pragma unroll
                for (int nt = 0; nt < 8; nt++) {
                    mma4(acc[mt][nt], ah[mt], bh[nt]);
                    mma4(acc[mt][nt], ah[mt], bl[nt]);
                    mma4(acc[mt][nt], al[mt], bh[nt]);
                }
        }
        __syncthreads();
    }

    #pragma unroll
    for (int mt = 0; mt < 2; mt++) {
        const int r0 = m0 + wm * 32 + mt * 16 + (lane >> 2);
        #pragma unroll
        for (int nt = 0; nt < 8; nt++) {
            const int n = n0 + wn * 64 + nt * 8 + 2 * (lane & 3);
            const float b0 = bias[n], b1 = bias[n + 1];
            *(float2*)&out[(size_t)r0 * CH + n] =
                make_float2(acc[mt][nt][0] + b0, acc[mt][nt][1] + b1);
            *(float2*)&out[(size_t)(r0 + 8) * CH + n] =
                make_float2(acc[mt][nt][2] + b0, acc[mt][nt][3] + b1);
        }
    }
}

// ============================================================================
// Depthwise short conv (k=3, pad 1, per batch) fused with transpose to [c][m]
// ============================================================================
__global__ void shortconv_transpose(const float* __restrict__ sw,
                                    const float* __restrict__ sb)
{
    __shared__ float s[32][33];
    const int c0 = blockIdx.x * 32;
    const int m0 = blockIdx.y * 32;
    const int b  = m0 / LSEQ;
    const int l0 = m0 - b * LSEQ;
    const int tx = threadIdx.x, ty = threadIdx.y;
    const int c = c0 + tx;
    const int l = l0 + ty;

    size_t base = (size_t)(b*LSEQ + l) * CH + c;
    float vc = g_Vrow[base];
    float vm = (l > 0)       ? g_Vrow[base - CH] : 0.f;
    float vp = (l < LSEQ-1)  ? g_Vrow[base + CH] : 0.f;
    float w0 = sw[c*3], w1 = sw[c*3+1], w2 = sw[c*3+2];
    s[ty][tx] = w0*vm + w1*vc + w2*vp + sb[c];
    __syncthreads();
    g_Vt[(size_t)(c0 + ty) * MTOT + b*LSEQ + l0 + tx] = s[tx][ty];
}

__global__ void transpose_x2() {
    __shared__ float s[32][33];
    const int c0 = blockIdx.x * 32, m0 = blockIdx.y * 32;
    const int tx = threadIdx.x, ty = threadIdx.y;
    s[ty][tx] = g_X2row[(size_t)(m0+ty)*CH + c0 + tx];
    __syncthreads();
    g_X2t[(size_t)(c0+ty)*MTOT + m0 + tx] = s[tx][ty];
}
__global__ void transpose_coef() {
    __shared__ float s[32][33];
    const int c0 = blockIdx.x * 32, m0 = blockIdx.y * 32;
    const int tx = threadIdx.x, ty = threadIdx.y;
    s[ty][tx] = g_COEF[(size_t)(m0+ty)*CH + c0 + tx];
    __syncthreads();
    g_COEFt[(size_t)(c0+ty)*LSEQ + m0 + tx] = s[tx][ty];
}

// ============================================================================
// Filter MLP part 1: h2[l][t] for t in [0,128)
// ============================================================================
__global__ void filter_h2(const float* __restrict__ fw1, const float* __restrict__ fb1,
                          const float* __restrict__ fw2, const float* __restrict__ fb2)
{
    __shared__ float h1[64];
    const int l = blockIdx.x;
    const int t = threadIdx.x;
    const float pos = (float)l / (float)(LSEQ - 1);
    if (t < 64) h1[t] = gelu_exact(pos * fw1[t] + fb1[t]);
    __syncthreads();
    float s = fb2[t];
    #pragma unroll 8
    for (int j = 0; j < 64; j++) s += h1[j] * fw2[j*128 + t];
    g_H2[(size_t)l*128 + t] = gelu_exact(s);
}

// ============================================================================
// GEMM coef (SIMT, small): COEF[l][c] = h2 @ fw3[:, 2c+1] + fb3[2c+1]
// M=8192, N=1024, K=128
// ============================================================================
__global__ __launch_bounds__(256) void gemm_coef(
    const float* __restrict__ fw3, const float* __restrict__ fb3)
{
    __shared__ float As[8][128];
    __shared__ float Bs[8][128];
    const int tid = threadIdx.x;
    const int tx = tid & 15, ty = tid >> 4;
    const int m0 = blockIdx.y * 128;
    const int n0 = blockIdx.x * 128;

    float acc[8][8];
    #pragma unroll
    for (int i = 0; i < 8; i++)
        #pragma unroll
        for (int j = 0; j < 8; j++) acc[i][j] = 0.f;

    const int arow = tid >> 1, akq = (tid & 1) * 4;
    const int bn = tid & 127;
    const int jm = 2 * (n0 + bn) + 1;
    const int kk0 = (tid >> 7) * 4;

    for (int k0 = 0; k0 < 128; k0 += 8) {
        float4 av = *(const float4*)&g_H2[(size_t)(m0 + arow) * 128 + k0 + akq];
        As[akq+0][arow] = av.x; As[akq+1][arow] = av.y;
        As[akq+2][arow] = av.z; As[akq+3][arow] = av.w;
        #pragma unroll
        for (int r = 0; r < 4; r++)
            Bs[kk0 + r][bn] = fw3[(size_t)(k0 + kk0 + r) * 2048 + jm];
        __syncthreads();
        #pragma unroll
        for (int kk = 0; kk < 8; kk++) {
            float a[8], b[8];
            #pragma unroll
            for (int i = 0; i < 8; i++) a[i] = As[kk][ty*8 + i];
            #pragma unroll
            for (int j = 0; j < 8; j++) b[j] = Bs[kk][tx*8 + j];
            #pragma unroll
            for (int i = 0; i < 8; i++)
                #pragma unroll
                for (int j = 0; j < 8; j++) acc[i][j] += a[i] * b[j];
        }
        __syncthreads();
    }

    float bo[8];
    #pragma unroll
    for (int j = 0; j < 8; j++) bo[j] = fb3[2*(n0 + tx*8 + j) + 1];
    #pragma unroll
    for (int i = 0; i < 8; i++) {
        int m = m0 + ty*8 + i;
        float4 o0 = make_float4(acc[i][0]+bo[0], acc[i][1]+bo[1],
                                acc[i][2]+bo[2], acc[i][3]+bo[3]);
        float4 o1 = make_float4(acc[i][4]+bo[4], acc[i][5]+bo[5],
                                acc[i][6]+bo[6], acc[i][7]+bo[7]);
        *(float4*)&g_COEF[(size_t)m*CH + n0 + tx*8]     = o0;
        *(float4*)&g_COEF[(size_t)m*CH + n0 + tx*8 + 4] = o1;
    }
}

// ============================================================================
// FFT convolution per channel.  One CTA per channel.  (unchanged, correct)
// ============================================================================
#define FFT_T   512
#define HS_OFF  16384
#define WT_OFF  (16384 + 8208)
#define FFT_SMEM ((16384 + 8208 + 4096) * 8)

__device__ __forceinline__ float2 twid(const float2* Wt, int k) {
    if (k < 4096) return Wt[k];
    float2 w = Wt[k - 4096];
    return make_float2(w.y, -w.x);      // multiply by -i
}

__device__ void fft_dit(float2* Z, const float2* Wt, int tid) {
    int loglen = 1;
    for (int len = 2; len <= NFFT; len <<= 1, loglen++) {
        const int half = len >> 1;
        for (int b = tid; b < NFFT/2; b += FFT_T) {
            const int p  = b & (half - 1);
            const int i0 = 2*b - p;
            const int i1 = i0 + half;
            float2 w = twid(Wt, p << (14 - loglen));
            float2 u = Z[i0];
            float2 t = cmulf(Z[i1], w);
            Z[i0] = make_float2(u.x + t.x, u.y + t.y);
            Z[i1] = make_float2(u.x - t.x, u.y - t.y);
        }
        __syncthreads();
    }
}

__device__ void ifft_dif(float2* Z, const float2* Wt, int tid) {
    int loglen = 14;
    for (int len = NFFT; len >= 2; len >>= 1, loglen--) {
        const int half = len >> 1;
        for (int b = tid; b < NFFT/2; b += FFT_T) {
            const int p  = b & (half - 1);
            const int i0 = 2*b - p;
            const int i1 = i0 + half;
            float2 u = Z[i0], v = Z[i1];
            Z[i0] = make_float2(u.x + v.x, u.y + v.y);
            float2 d = make_float2(u.x - v.x, u.y - v.y);
            float2 w = twid(Wt, p << (14 - loglen));
            Z[i1] = make_float2(d.x*w.x + d.y*w.y, d.y*w.x - d.x*w.y);
        }
        __syncthreads();
    }
}

__global__ __launch_bounds__(FFT_T, 1) void fft_conv_kernel() {
    extern __shared__ float2 sm[];
    float2* Z  = sm;
    float2* Hs = sm + HS_OFF;
    float2* Wt = sm + WT_OFF;
    const int c   = blockIdx.x;
    const int tid = threadIdx.x;

    for (int k = tid; k < 4096; k += FFT_T) {
        float ang = 3.834951969714103e-4f * (float)k;   // 2*pi/16384 * k
        float sv, cv;
        sincosf(ang, &sv, &cv);
        Wt[k] = make_float2(cv, -sv);
    }

    const float* hsrc = g_COEFt + (size_t)c * LSEQ;
    for (int i = tid; i < NFFT; i += FFT_T) {
        float re = (i < LSEQ) ? hsrc[i] : 0.f;
        Z[__brev((unsigned)i) >> 18] = make_float2(re, 0.f);
    }
    __syncthreads();
    fft_dit(Z, Wt, tid);

    for (int k = tid; k <= NFFT/2; k += FFT_T) Hs[k] = Z[k];
    __syncthreads();

    const float* v0 = g_Vt + (size_t)c * MTOT;
    const float* v1 = v0 + LSEQ;
    for (int i = tid; i < NFFT; i += FFT_T) {
        float re = (i < LSEQ) ? v0[i] : 0.f;
        float im = (i < LSEQ) ? v1[i] : 0.f;
        Z[__brev((unsigned)i) >> 18] = make_float2(re, im);
    }
    __syncthreads();
    fft_dit(Z, Wt, tid);

    for (int k = tid; k <= NFFT/2; k += FFT_T) {
        const int k2 = (NFFT - k) & (NFFT - 1);
        float2 Zk = Z[k], Zn = Z[k2];
        float2 V0 = make_float2(0.5f*(Zk.x + Zn.x), 0.5f*(Zk.y - Zn.y));
        float2 V1 = make_float2(0.5f*(Zk.y + Zn.y), 0.5f*(Zn.x - Zk.x));
        float2 H  = Hs[k];
        float2 C0 = cmulf(V0, H);
        float2 C1 = cmulf(V1, H);
        Z[k]  = make_float2(C0.x - C1.y, C0.y + C1.x);
        Z[k2] = make_float2(C0.x + C1.y, C1.x - C0.y);
    }
    __syncthreads();

    ifft_dif(Z, Wt, tid);

    const float* x2 = g_X2t + (size_t)c * MTOT;
    float* go = g_Gt + (size_t)c * MTOT;
    const float scale = 1.0f / (float)NFFT;
    for (int l = tid; l < LSEQ; l += FFT_T) {
        float2 d0 = Z[__brev((unsigned)l) >> 18];
        go[l]        = x2[l]        * (d0.x * scale);
        go[LSEQ + l] = x2[LSEQ + l] * (d0.y * scale);
    }
}

// ============================================================================
extern "C" void kernel_launch(void* const* d_in, const int* in_sizes, int n_in,
                              void* d_out, int out_size)
{
    const float* x   = (const float*)d_in[0];
    const float* ipw = (const float*)d_in[1];
    const float* ipb = (const float*)d_in[2];
    const float* sw  = (const float*)d_in[3];
    const float* sb  = (const float*)d_in[4];
    const float* fw1 = (const float*)d_in[5];
    const float* fb1 = (const float*)d_in[6];
    const float* fw2 = (const float*)d_in[7];
    const float* fb2 = (const float*)d_in[8];
    const float* fw3 = (const float*)d_in[9];
    const float* fb3 = (const float*)d_in[10];
    const float* ow  = (const float*)d_in[11];
    const float* ob  = (const float*)d_in[12];
    float* out = (float*)d_out;

    cudaFuncSetAttribute(fft_conv_kernel,
                         cudaFuncAttributeMaxDynamicSharedMemorySize, FFT_SMEM);

    // 1) in_proj GEMM on tensor cores (v + x2 branches only; x1 is dead)
    gemm_inproj_tc<<<dim3(16, 128), 256>>>(x, ipw, ipb);
    // 2) depthwise short conv + transpose to channel-major
    shortconv_transpose<<<dim3(32, 512), dim3(32, 32)>>>(sw, sb);
    // 3) x2 transpose
    transpose_x2<<<dim3(32, 512), dim3(32, 32)>>>();
    // 4) filter MLP hidden
    filter_h2<<<LSEQ, 128>>>(fw1, fb1, fw2, fb2);
    // 5) filter coef GEMM (only order index 1 survives the reference loop)
    gemm_coef<<<dim3(8, 64), 256>>>(fw3, fb3);
    // 6) coef transpose
    transpose_coef<<<dim3(32, 256), dim3(32, 32)>>>();
    // 7) FFT long conv + gating (one CTA per channel)
    fft_conv_kernel<<<CH, FFT_T, FFT_SMEM>>>();
    // 8) output projection GEMM on tensor cores
    gemm_out_tc<<<dim3(8, 128), 256>>>(ow, ob, out);
}

// round 4
// speedup vs baseline: 1.6560x; 1.5402x over previous
#include <cuda_runtime.h>
#include <cuda_bf16.h>
#include <math.h>
#include <stdint.h>

// Problem constants
#define LSEQ   8192
#define NFFT   16384
#define CH     1024
#define BATCH  2
#define MTOT   (BATCH*LSEQ)      // 16384 rows

// ---------------- scratch (device globals; no allocations allowed) ----------
__device__ float g_Vrow [MTOT*CH];     // short-conv input, row-major [m][c]
__device__ float g_X2row[MTOT*CH];     // x2 branch, row-major [m][c]
__device__ float g_Vt   [CH*MTOT];     // short-conv'd v, channel-major [c][b*L+l]
__device__ float g_X2t  [CH*MTOT];     // x2, channel-major
__device__ float g_H2   [LSEQ*128];    // filter MLP hidden (L x 128)
__device__ float g_COEF [LSEQ*CH];     // filter coefs order-1, row-major [l][c]
__device__ float g_COEFt[CH*LSEQ];     // channel-major [c][l]
__device__ float g_Gt   [CH*MTOT];     // gated conv output, [c][m]

// bf16 split operands for the tensor-core GEMMs
__device__ __nv_bfloat16 g_Xh [MTOT*CH], g_Xl [MTOT*CH];     // x, [m][k]
__device__ __nv_bfloat16 g_Gh [MTOT*CH], g_Gl [MTOT*CH];     // gated, [m][k]
__device__ __nv_bfloat16 g_Wih[2048*CH], g_Wil[2048*CH];     // in_proj cols, [n][k]
__device__ __nv_bfloat16 g_Woh[CH*CH],   g_Wol[CH*CH];       // out_w^T, [n][k]

// ---------------- generic helpers -------------------------------------------
__device__ __forceinline__ float gelu_exact(float x) {
    return 0.5f * x * (1.0f + erff(x * 0.70710678118654752f));
}
__device__ __forceinline__ float2 cmulf(float2 a, float2 b) {
    return make_float2(a.x*b.x - a.y*b.y, a.x*b.y + a.y*b.x);
}
__device__ __forceinline__ void bf16_split(float v, __nv_bfloat16 &h, __nv_bfloat16 &l) {
    h = __float2bfloat16(v);
    l = __float2bfloat16(v - __bfloat162float(h));
}
__device__ __forceinline__ uint32_t smem_u32(const void* p) {
    uint32_t a;
    asm("{ .reg .u64 t; cvta.to.shared.u64 t, %1; cvt.u32.u64 %0, t; }"
        : "=r"(a) : "l"(p));
    return a;
}

#define CP_ASYNC16(sm, gp) \
    asm volatile("cp.async.cg.shared.global [%0], [%1], 16;" \
                 :: "r"(sm), "l"(__cvta_generic_to_global(gp)) : "memory")
#define CP_COMMIT() asm volatile("cp.async.commit_group;" ::: "memory")
#define CP_WAIT0()  asm volatile("cp.async.wait_group 0;" ::: "memory")

#define LDSM4(r0, r1, r2, r3, ad) \
    asm volatile("ldmatrix.sync.aligned.m8n8.x4.shared.b16 {%0,%1,%2,%3}, [%4];" \
                 : "=r"(r0), "=r"(r1), "=r"(r2), "=r"(r3) : "r"(ad))

__device__ __forceinline__ void mma_bf16(float* c, const uint32_t* a, const uint32_t* b) {
    asm volatile("mma.sync.aligned.m16n8k16.row.col.f32.bf16.bf16.f32 "
        "{%0,%1,%2,%3}, {%4,%5,%6,%7}, {%8,%9}, {%0,%1,%2,%3};"
        : "+f"(c[0]), "+f"(c[1]), "+f"(c[2]), "+f"(c[3])
        : "r"(a[0]), "r"(a[1]), "r"(a[2]), "r"(a[3]), "r"(b[0]), "r"(b[1]));
}

// ============================================================================
// convert/split kernels
// ============================================================================
__global__ __launch_bounds__(256) void convert_x_split(const float* __restrict__ x) {
    size_t i = ((size_t)blockIdx.x * 256 + threadIdx.x) * 4;
    float4 v = *(const float4*)&x[i];
    __nv_bfloat16 h[4], l[4];
    bf16_split(v.x, h[0], l[0]); bf16_split(v.y, h[1], l[1]);
    bf16_split(v.z, h[2], l[2]); bf16_split(v.w, h[3], l[3]);
    *(__nv_bfloat162*)&g_Xh[i]   = __nv_bfloat162(h[0], h[1]);
    *(__nv_bfloat162*)&g_Xh[i+2] = __nv_bfloat162(h[2], h[3]);
    *(__nv_bfloat162*)&g_Xl[i]   = __nv_bfloat162(l[0], l[1]);
    *(__nv_bfloat162*)&g_Xl[i+2] = __nv_bfloat162(l[2], l[3]);
}

// in_proj weight: virtual row n -> gmem column jmap(n); output [n][k] bf16 hi/lo
// n < 1024: v weights (col 3n).  n >= 1024: x2 weights (col 3(n-1024)+2)
__global__ __launch_bounds__(128) void convert_wip_split(const float* __restrict__ ipw) {
    const int n  = blockIdx.x;
    const int j  = (n < 1024) ? 3*n : 3*(n - 1024) + 2;
    const int k0 = threadIdx.x * 8;
    __nv_bfloat16 h[8], l[8];
    #pragma unroll
    for (int u = 0; u < 8; u++)
        bf16_split(ipw[(size_t)(k0 + u) * 3072 + j], h[u], l[u]);
    #pragma unroll
    for (int u = 0; u < 8; u += 2) {
        *(__nv_bfloat162*)&g_Wih[(size_t)n*1024 + k0 + u] = __nv_bfloat162(h[u], h[u+1]);
        *(__nv_bfloat162*)&g_Wil[(size_t)n*1024 + k0 + u] = __nv_bfloat162(l[u], l[u+1]);
    }
}

__global__ __launch_bounds__(128) void convert_wout_split(const float* __restrict__ ow) {
    const int n  = blockIdx.x;
    const int k0 = threadIdx.x * 8;
    __nv_bfloat16 h[8], l[8];
    #pragma unroll
    for (int u = 0; u < 8; u++)
        bf16_split(ow[(size_t)(k0 + u) * CH + n], h[u], l[u]);
    #pragma unroll
    for (int u = 0; u < 8; u += 2) {
        *(__nv_bfloat162*)&g_Woh[(size_t)n*1024 + k0 + u] = __nv_bfloat162(h[u], h[u+1]);
        *(__nv_bfloat162*)&g_Wol[(size_t)n*1024 + k0 + u] = __nv_bfloat162(l[u], l[u+1]);
    }
}

// g_Gt [c][m] f32 -> g_Gh/g_Gl [m][c] bf16 (tiled transpose + split)
__global__ void convert_gt_split() {
    __shared__ float s[32][33];
    const int c0 = blockIdx.x * 32, m0 = blockIdx.y * 32;
    const int tx = threadIdx.x, ty = threadIdx.y;
    s[ty][tx] = g_Gt[(size_t)(c0 + ty) * MTOT + m0 + tx];
    __syncthreads();
    __nv_bfloat16 h, l;
    bf16_split(s[tx][ty], h, l);
    g_Gh[(size_t)(m0 + ty) * CH + c0 + tx] = h;
    g_Gl[(size_t)(m0 + ty) * CH + c0 + tx] = l;
}

// ============================================================================
// bf16 mma.sync GEMM, 2-term split, ldmatrix + cp.async.
// Block 128x128, 8 warps (4m x 2n), warp tile 32x64, K chunk 64.
// MODE 0: in_proj  (A=g_Xh/l, B=g_Wih/l, epilogue -> g_Vrow / g_X2row + bias)
// MODE 1: out proj (A=g_Gh/l, B=g_Woh/l, epilogue -> out + bias)
// smem: AH[128][64] | AL | BH | BL  (16KB each, SW128-swizzled rows of 128B)
// ============================================================================
#define GSM_BYTES 65536

template<int MODE>
__global__ __launch_bounds__(256, 2) void gemm_bf16_tc(
    const float* __restrict__ bias, float* __restrict__ out)
{
    extern __shared__ char dsm[];
    const uint32_t sb  = smem_u32(dsm);
    const uint32_t sAh = sb, sAl = sb + 16384, sBh = sb + 32768, sBl = sb + 49152;

    const int tid  = threadIdx.x;
    const int lane = tid & 31;
    const int wid  = tid >> 5;
    const int wm   = wid >> 1;          // 0..3 -> 32 rows each
    const int wn   = wid & 1;           // 0..1 -> 64 cols each
    const int m0   = blockIdx.y * 128;
    const int bx   = blockIdx.x;
    const int n0   = bx * 128;

    const __nv_bfloat16* Ah = (MODE == 0) ? g_Xh : g_Gh;
    const __nv_bfloat16* Al = (MODE == 0) ? g_Xl : g_Gl;
    const __nv_bfloat16* Bh = (MODE == 0) ? g_Wih : g_Woh;
    const __nv_bfloat16* Bl = (MODE == 0) ? g_Wil : g_Wol;

    float acc[2][8][4];
    #pragma unroll
    for (int i = 0; i < 2; i++)
        #pragma unroll
        for (int j = 0; j < 8; j++)
            #pragma unroll
            for (int q = 0; q < 4; q++) acc[i][j][q] = 0.f;

    // loader indices: 4 x (row, seg) per thread per operand array
    const int lrow = tid >> 3;          // 0..31 (+32*u)
    const int lseg = tid & 7;           // 16B segment within 128B row

    for (int it = 0; it < 16; ++it) {
        const size_t kc0 = (size_t)it * 64;
        #pragma unroll
        for (int u = 0; u < 4; u++) {
            const int row = lrow + u * 32;
            const uint32_t so = (uint32_t)(row * 128 + ((lseg * 16) ^ ((row & 7) << 4)));
            const size_t ga = (size_t)(m0 + row) * 1024 + kc0 + lseg * 8;
            const size_t gb = (size_t)(n0 + row) * 1024 + kc0 + lseg * 8;
            CP_ASYNC16(sAh + so, Ah + ga);
            CP_ASYNC16(sAl + so, Al + ga);
            CP_ASYNC16(sBh + so, Bh + gb);
            CP_ASYNC16(sBl + so, Bl + gb);
        }
        CP_COMMIT();
        CP_WAIT0();
        __syncthreads();

        #pragma unroll
        for (int ks = 0; ks < 4; ks++) {
            uint32_t ah[2][4], al[2][4];
            #pragma unroll
            for (int mt = 0; mt < 2; mt++) {
                const int row = wm * 32 + mt * 16 + (lane & 15);
                const uint32_t r4 = (row & 7) << 4;
                const uint32_t cb = (uint32_t)(ks * 32 + ((lane >> 4) << 4));
                const uint32_t ad = sAh + row * 128 + (cb ^ r4);
                LDSM4(ah[mt][0], ah[mt][1], ah[mt][2], ah[mt][3], ad);
                LDSM4(al[mt][0], al[mt][1], al[mt][2], al[mt][3], ad + 16384);
            }
            uint32_t bh[8][2], bl[8][2];
            #pragma unroll
            for (int nt2 = 0; nt2 < 4; nt2++) {
                const int n = wn * 64 + nt2 * 16 + (lane & 7) + ((lane >> 4) << 3);
                const uint32_t r4 = (n & 7) << 4;
                const uint32_t cb = (uint32_t)(ks * 32 + (((lane >> 3) & 1) << 4));
                const uint32_t ad = sBh + n * 128 + (cb ^ r4);
                LDSM4(bh[2*nt2][0], bh[2*nt2][1], bh[2*nt2+1][0], bh[2*nt2+1][1], ad);
                LDSM4(bl[2*nt2][0], bl[2*nt2][1], bl[2*nt2+1][0], bl[2*nt2+1][1], ad + 16384);
            }
            #pragma unroll
            for (int mt = 0; mt < 2; mt++)
                #pragma unroll
                for (int nt = 0; nt < 8; nt++) {
                    mma_bf16(acc[mt][nt], ah[mt], bh[nt]);
                    mma_bf16(acc[mt][nt], ah[mt], bl[nt]);
                    mma_bf16(acc[mt][nt], al[mt], bh[nt]);
                }
        }
        __syncthreads();
    }

    // epilogue: c frag rows = lane>>2 (+8), cols = 2*(lane&3) (+1)
    #pragma unroll
    for (int mt = 0; mt < 2; mt++) {
        const int r = m0 + wm * 32 + mt * 16 + (lane >> 2);
        #pragma unroll
        for (int nt = 0; nt < 8; nt++) {
            const int nl = wn * 64 + nt * 8 + ((lane & 3) << 1);   // local col in tile
            if (MODE == 0) {
                const bool is_v = (bx < 8);
                const int c = (is_v ? bx : bx - 8) * 128 + nl;
                const float b0 = is_v ? bias[3*c]     : bias[3*c + 2];
                const float b1 = is_v ? bias[3*(c+1)] : bias[3*(c+1) + 2];
                float* dst = (is_v ? g_Vrow : g_X2row);
                *(float2*)&dst[(size_t)r * CH + c] =
                    make_float2(acc[mt][nt][0] + b0, acc[mt][nt][1] + b1);
                *(float2*)&dst[(size_t)(r + 8) * CH + c] =
                    make_float2(acc[mt][nt][2] + b0, acc[mt][nt][3] + b1);
            } else {
                const int c = n0 + nl;
                const float b0 = bias[c], b1 = bias[c + 1];
                *(float2*)&out[(size_t)r * CH + c] =
                    make_float2(acc[mt][nt][0] + b0, acc[mt][nt][1] + b1);
                *(float2*)&out[(size_t)(r + 8) * CH + c] =
                    make_float2(acc[mt][nt][2] + b0, acc[mt][nt][3] + b1);
            }
        }
    }
}

// ============================================================================
// Depthwise short conv (k=3, pad 1, per batch) fused with transpose to [c][m]
// ============================================================================
__global__ void shortconv_transpose(const float* __restrict__ sw,
                                    const float* __restrict__ sb)
{
    __shared__ float s[32][33];
    const int c0 = blockIdx.x * 32;
    const int m0 = blockIdx.y * 32;
    const int b  = m0 / LSEQ;
    const int l0 = m0 - b * LSEQ;
    const int tx = threadIdx.x, ty = threadIdx.y;
    const int c = c0 + tx;
    const int l = l0 + ty;

    size_t base = (size_t)(b*LSEQ + l) * CH + c;
    float vc = g_Vrow[base];
    float vm = (l > 0)       ? g_Vrow[base - CH] : 0.f;
    float vp = (l < LSEQ-1)  ? g_Vrow[base + CH] : 0.f;
    float w0 = sw[c*3], w1 = sw[c*3+1], w2 = sw[c*3+2];
    s[ty][tx] = w0*vm + w1*vc + w2*vp + sb[c];
    __syncthreads();
    g_Vt[(size_t)(c0 + ty) * MTOT + b*LSEQ + l0 + tx] = s[tx][ty];
}

__global__ void transpose_x2() {
    __shared__ float s[32][33];
    const int c0 = blockIdx.x * 32, m0 = blockIdx.y * 32;
    const int tx = threadIdx.x, ty = threadIdx.y;
    s[ty][tx] = g_X2row[(size_t)(m0+ty)*CH + c0 + tx];
    __syncthreads();
    g_X2t[(size_t)(c0+ty)*MTOT + m0 + tx] = s[tx][ty];
}
__global__ void transpose_coef() {
    __shared__ float s[32][33];
    const int c0 = blockIdx.x * 32, m0 = blockIdx.y * 32;
    const int tx = threadIdx.x, ty = threadIdx.y;
    s[ty][tx] = g_COEF[(size_t)(m0+ty)*CH + c0 + tx];
    __syncthreads();
    g_COEFt[(size_t)(c0+ty)*LSEQ + m0 + tx] = s[tx][ty];
}

// ============================================================================
// Filter MLP part 1: h2[l][t] for t in [0,128)
// ============================================================================
__global__ void filter_h2(const float* __restrict__ fw1, const float* __restrict__ fb1,
                          const float* __restrict__ fw2, const float* __restrict__ fb2)
{
    __shared__ float h1[64];
    const int l = blockIdx.x;
    const int t = threadIdx.x;
    const float pos = (float)l / (float)(LSEQ - 1);
    if (t < 64) h1[t] = gelu_exact(pos * fw1[t] + fb1[t]);
    __syncthreads();
    float s = fb2[t];
    #pragma unroll 8
    for (int j = 0; j < 64; j++) s += h1[j] * fw2[j*128 + t];
    g_H2[(size_t)l*128 + t] = gelu_exact(s);
}

// ============================================================================
// GEMM coef (SIMT, small): COEF[l][c] = h2 @ fw3[:, 2c+1] + fb3[2c+1]
// ============================================================================
__global__ __launch_bounds__(256) void gemm_coef(
    const float* __restrict__ fw3, const float* __restrict__ fb3)
{
    __shared__ float As[8][128];
    __shared__ float Bs[8][128];
    const int tid = threadIdx.x;
    const int tx = tid & 15, ty = tid >> 4;
    const int m0 = blockIdx.y * 128;
    const int n0 = blockIdx.x * 128;

    float acc[8][8];
    #pragma unroll
    for (int i = 0; i < 8; i++)
        #pragma unroll
        for (int j = 0; j < 8; j++) acc[i][j] = 0.f;

    const int arow = tid >> 1, akq = (tid & 1) * 4;
    const int bn = tid & 127;
    const int jm = 2 * (n0 + bn) + 1;
    const int kk0 = (tid >> 7) * 4;

    for (int k0 = 0; k0 < 128; k0 += 8) {
        float4 av = *(const float4*)&g_H2[(size_t)(m0 + arow) * 128 + k0 + akq];
        As[akq+0][arow] = av.x; As[akq+1][arow] = av.y;
        As[akq+2][arow] = av.z; As[akq+3][arow] = av.w;
        #pragma unroll
        for (int r = 0; r < 4; r++)
            Bs[kk0 + r][bn] = fw3[(size_t)(k0 + kk0 + r) * 2048 + jm];
        __syncthreads();
        #pragma unroll
        for (int kk = 0; kk < 8; kk++) {
            float a[8], b[8];
            #pragma unroll
            for (int i = 0; i < 8; i++) a[i] = As[kk][ty*8 + i];
            #pragma unroll
            for (int j = 0; j < 8; j++) b[j] = Bs[kk][tx*8 + j];
            #pragma unroll
            for (int i = 0; i < 8; i++)
                #pragma unroll
                for (int j = 0; j < 8; j++) acc[i][j] += a[i] * b[j];
        }
        __syncthreads();
    }

    float bo[8];
    #pragma unroll
    for (int j = 0; j < 8; j++) bo[j] = fb3[2*(n0 + tx*8 + j) + 1];
    #pragma unroll
    for (int i = 0; i < 8; i++) {
        int m = m0 + ty*8 + i;
        float4 o0 = make_float4(acc[i][0]+bo[0], acc[i][1]+bo[1],
                                acc[i][2]+bo[2], acc[i][3]+bo[3]);
        float4 o1 = make_float4(acc[i][4]+bo[4], acc[i][5]+bo[5],
                                acc[i][6]+bo[6], acc[i][7]+bo[7]);
        *(float4*)&g_COEF[(size_t)m*CH + n0 + tx*8]     = o0;
        *(float4*)&g_COEF[(size_t)m*CH + n0 + tx*8 + 4] = o1;
    }
}

// ============================================================================
// FFT convolution per channel (unchanged, verified correct)
// ============================================================================
#define FFT_T   512
#define HS_OFF  16384
#define WT_OFF  (16384 + 8208)
#define FFT_SMEM ((16384 + 8208 + 4096) * 8)

__device__ __forceinline__ float2 twid(const float2* Wt, int k) {
    if (k < 4096) return Wt[k];
    float2 w = Wt[k - 4096];
    return make_float2(w.y, -w.x);      // multiply by -i
}

__device__ void fft_dit(float2* Z, const float2* Wt, int tid) {
    int loglen = 1;
    for (int len = 2; len <= NFFT; len <<= 1, loglen++) {
        const int half = len >> 1;
        for (int b = tid; b < NFFT/2; b += FFT_T) {
            const int p  = b & (half - 1);
            const int i0 = 2*b - p;
            const int i1 = i0 + half;
            float2 w = twid(Wt, p << (14 - loglen));
            float2 u = Z[i0];
            float2 t = cmulf(Z[i1], w);
            Z[i0] = make_float2(u.x + t.x, u.y + t.y);
            Z[i1] = make_float2(u.x - t.x, u.y - t.y);
        }
        __syncthreads();
    }
}

__device__ void ifft_dif(float2* Z, const float2* Wt, int tid) {
    int loglen = 14;
    for (int len = NFFT; len >= 2; len >>= 1, loglen--) {
        const int half = len >> 1;
        for (int b = tid; b < NFFT/2; b += FFT_T) {
            const int p  = b & (half - 1);
            const int i0 = 2*b - p;
            const int i1 = i0 + half;
            float2 u = Z[i0], v = Z[i1];
            Z[i0] = make_float2(u.x + v.x, u.y + v.y);
            float2 d = make_float2(u.x - v.x, u.y - v.y);
            float2 w = twid(Wt, p << (14 - loglen));
            Z[i1] = make_float2(d.x*w.x + d.y*w.y, d.y*w.x - d.x*w.y);
        }
        __syncthreads();
    }
}

__global__ __launch_bounds__(FFT_T, 1) void fft_conv_kernel() {
    extern __shared__ float2 sm[];
    float2* Z  = sm;
    float2* Hs = sm + HS_OFF;
    float2* Wt = sm + WT_OFF;
    const int c   = blockIdx.x;
    const int tid = threadIdx.x;

    for (int k = tid; k < 4096; k += FFT_T) {
        float ang = 3.834951969714103e-4f * (float)k;   // 2*pi/16384 * k
        float sv, cv;
        sincosf(ang, &sv, &cv);
        Wt[k] = make_float2(cv, -sv);
    }

    const float* hsrc = g_COEFt + (size_t)c * LSEQ;
    for (int i = tid; i < NFFT; i += FFT_T) {
        float re = (i < LSEQ) ? hsrc[i] : 0.f;
        Z[__brev((unsigned)i) >> 18] = make_float2(re, 0.f);
    }
    __syncthreads();
    fft_dit(Z, Wt, tid);

    for (int k = tid; k <= NFFT/2; k += FFT_T) Hs[k] = Z[k];
    __syncthreads();

    const float* v0 = g_Vt + (size_t)c * MTOT;
    const float* v1 = v0 + LSEQ;
    for (int i = tid; i < NFFT; i += FFT_T) {
        float re = (i < LSEQ) ? v0[i] : 0.f;
        float im = (i < LSEQ) ? v1[i] : 0.f;
        Z[__brev((unsigned)i) >> 18] = make_float2(re, im);
    }
    __syncthreads();
    fft_dit(Z, Wt, tid);

    for (int k = tid; k <= NFFT/2; k += FFT_T) {
        const int k2 = (NFFT - k) & (NFFT - 1);
        float2 Zk = Z[k], Zn = Z[k2];
        float2 V0 = make_float2(0.5f*(Zk.x + Zn.x), 0.5f*(Zk.y - Zn.y));
        float2 V1 = make_float2(0.5f*(Zk.y + Zn.y), 0.5f*(Zn.x - Zk.x));
        float2 H  = Hs[k];
        float2 C0 = cmulf(V0, H);
        float2 C1 = cmulf(V1, H);
        Z[k]  = make_float2(C0.x - C1.y, C0.y + C1.x);
        Z[k2] = make_float2(C0.x + C1.y, C1.x - C0.y);
    }
    __syncthreads();

    ifft_dif(Z, Wt, tid);

    const float* x2 = g_X2t + (size_t)c * MTOT;
    float* go = g_Gt + (size_t)c * MTOT;
    const float scale = 1.0f / (float)NFFT;
    for (int l = tid; l < LSEQ; l += FFT_T) {
        float2 d0 = Z[__brev((unsigned)l) >> 18];
        go[l]        = x2[l]        * (d0.x * scale);
        go[LSEQ + l] = x2[LSEQ + l] * (d0.y * scale);
    }
}

// ============================================================================
extern "C" void kernel_launch(void* const* d_in, const int* in_sizes, int n_in,
                              void* d_out, int out_size)
{
    const float* x   = (const float*)d_in[0];
    const float* ipw = (const float*)d_in[1];
    const float* ipb = (const float*)d_in[2];
    const float* sw  = (const float*)d_in[3];
    const float* sb  = (const float*)d_in[4];
    const float* fw1 = (const float*)d_in[5];
    const float* fb1 = (const float*)d_in[6];
    const float* fw2 = (const float*)d_in[7];
    const float* fb2 = (const float*)d_in[8];
    const float* fw3 = (const float*)d_in[9];
    const float* fb3 = (const float*)d_in[10];
    const float* ow  = (const float*)d_in[11];
    const float* ob  = (const float*)d_in[12];
    float* out = (float*)d_out;

    cudaFuncSetAttribute(fft_conv_kernel,
                         cudaFuncAttributeMaxDynamicSharedMemorySize, FFT_SMEM);
    cudaFuncSetAttribute(gemm_bf16_tc<0>,
                         cudaFuncAttributeMaxDynamicSharedMemorySize, GSM_BYTES);
    cudaFuncSetAttribute(gemm_bf16_tc<1>,
                         cudaFuncAttributeMaxDynamicSharedMemorySize, GSM_BYTES);

    // 1) split x and in_proj weights into bf16 hi/lo
    convert_x_split<<<MTOT*CH/4/256, 256>>>(x);
    convert_wip_split<<<2048, 128>>>(ipw);
    convert_wout_split<<<1024, 128>>>(ow);
    // 2) in_proj GEMM (bf16 mma.sync; v + x2 branches only; x1 is dead)
    gemm_bf16_tc<0><<<dim3(16, 128), 256, GSM_BYTES>>>(ipb, nullptr);
    // 3) depthwise short conv + transpose to channel-major
    shortconv_transpose<<<dim3(32, 512), dim3(32, 32)>>>(sw, sb);
    // 4) x2 transpose
    transpose_x2<<<dim3(32, 512), dim3(32, 32)>>>();
    // 5) filter MLP hidden
    filter_h2<<<LSEQ, 128>>>(fw1, fb1, fw2, fb2);
    // 6) filter coef GEMM (only order index 1 survives the reference loop)
    gemm_coef<<<dim3(8, 64), 256>>>(fw3, fb3);
    // 7) coef transpose
    transpose_coef<<<dim3(32, 256), dim3(32, 32)>>>();
    // 8) FFT long conv + gating (one CTA per channel)
    fft_conv_kernel<<<CH, FFT_T, FFT_SMEM>>>();
    // 9) split gated output, out GEMM
    convert_gt_split<<<dim3(32, 512), dim3(32, 32)>>>();
    gemm_bf16_tc<1><<<dim3(8, 128), 256, GSM_BYTES>>>(ob, out);
}

// round 6
// speedup vs baseline: 2.0651x; 1.2470x over previous
#include <cuda_runtime.h>
#include <cuda_bf16.h>
#include <math.h>
#include <stdint.h>

// Problem constants
#define LSEQ   8192
#define NFFT   16384
#define CH     1024
#define BATCH  2
#define MTOT   (BATCH*LSEQ)      // 16384 rows

// ---------------- scratch (device globals; no allocations allowed) ----------
__device__ float g_Vrow [MTOT*CH];     // short-conv input, row-major [m][c]
__device__ float g_X2row[MTOT*CH];     // x2 branch, row-major [m][c]
__device__ float g_Vt   [CH*MTOT];     // short-conv'd v, channel-major [c][b*L+l]
__device__ float g_X2t  [CH*MTOT];     // x2, channel-major
__device__ float g_H2   [LSEQ*128];    // filter MLP hidden (L x 128)
__device__ float g_COEF [LSEQ*CH];     // filter coefs order-1, row-major [l][c]
__device__ float g_COEFt[CH*LSEQ];     // channel-major [c][l]
__device__ float g_Gt   [CH*MTOT];     // gated conv output, [c][m]
__device__ float2 g_Hspec[(size_t)CH*NFFT];  // filter spectrum, digit-rev order

// bf16 split operands for the tensor-core GEMMs
__device__ __nv_bfloat16 g_Xh [MTOT*CH], g_Xl [MTOT*CH];     // x, [m][k]
__device__ __nv_bfloat16 g_Gh [MTOT*CH], g_Gl [MTOT*CH];     // gated, [m][k]
__device__ __nv_bfloat16 g_Wih[2048*CH], g_Wil[2048*CH];     // in_proj cols, [n][k]
__device__ __nv_bfloat16 g_Woh[CH*CH],   g_Wol[CH*CH];       // out_w^T, [n][k]

// ---------------- generic helpers -------------------------------------------
__device__ __forceinline__ float gelu_exact(float x) {
    return 0.5f * x * (1.0f + erff(x * 0.70710678118654752f));
}
__device__ __forceinline__ float2 cmulf(float2 a, float2 b) {
    return make_float2(a.x*b.x - a.y*b.y, a.x*b.y + a.y*b.x);
}
__device__ __forceinline__ float2 cmulconjf(float2 a, float2 w) {  // a * conj(w)
    return make_float2(a.x*w.x + a.y*w.y, a.y*w.x - a.x*w.y);
}
__device__ __forceinline__ float2 caddf(float2 a, float2 b) {
    return make_float2(a.x + b.x, a.y + b.y);
}
__device__ __forceinline__ float2 csubf(float2 a, float2 b) {
    return make_float2(a.x - b.x, a.y - b.y);
}
__device__ __forceinline__ void bf16_split(float v, __nv_bfloat16 &h, __nv_bfloat16 &l) {
    h = __float2bfloat16(v);
    l = __float2bfloat16(v - __bfloat162float(h));
}
__device__ __forceinline__ uint32_t smem_u32(const void* p) {
    uint32_t a;
    asm("{ .reg .u64 t; cvta.to.shared.u64 t, %1; cvt.u32.u64 %0, t; }"
        : "=r"(a) : "l"(p));
    return a;
}

#define CP_ASYNC16(sm, gp) \
    asm volatile("cp.async.cg.shared.global [%0], [%1], 16;" \
                 :: "r"(sm), "l"(__cvta_generic_to_global(gp)) : "memory")
#define CP_COMMIT() asm volatile("cp.async.commit_group;" ::: "memory")
#define CP_WAIT0()  asm volatile("cp.async.wait_group 0;" ::: "memory")
#define CP_WAIT1()  asm volatile("cp.async.wait_group 1;" ::: "memory")

#define LDSM4(r0, r1, r2, r3, ad) \
    asm volatile("ldmatrix.sync.aligned.m8n8.x4.shared.b16 {%0,%1,%2,%3}, [%4];" \
                 : "=r"(r0), "=r"(r1), "=r"(r2), "=r"(r3) : "r"(ad))

__device__ __forceinline__ void mma_bf16(float* c, const uint32_t* a, const uint32_t* b) {
    asm volatile("mma.sync.aligned.m16n8k16.row.col.f32.bf16.bf16.f32 "
        "{%0,%1,%2,%3}, {%4,%5,%6,%7}, {%8,%9}, {%0,%1,%2,%3};"
        : "+f"(c[0]), "+f"(c[1]), "+f"(c[2]), "+f"(c[3])
        : "r"(a[0]), "r"(a[1]), "r"(a[2]), "r"(a[3]), "r"(b[0]), "r"(b[1]));
}

// ============================================================================
// convert/split kernels
// ============================================================================
__global__ __launch_bounds__(256) void convert_x_split(const float* __restrict__ x) {
    size_t i = ((size_t)blockIdx.x * 256 + threadIdx.x) * 4;
    float4 v = *(const float4*)&x[i];
    __nv_bfloat16 h[4], l[4];
    bf16_split(v.x, h[0], l[0]); bf16_split(v.y, h[1], l[1]);
    bf16_split(v.z, h[2], l[2]); bf16_split(v.w, h[3], l[3]);
    *(__nv_bfloat162*)&g_Xh[i]   = __nv_bfloat162(h[0], h[1]);
    *(__nv_bfloat162*)&g_Xh[i+2] = __nv_bfloat162(h[2], h[3]);
    *(__nv_bfloat162*)&g_Xl[i]   = __nv_bfloat162(l[0], l[1]);
    *(__nv_bfloat162*)&g_Xl[i+2] = __nv_bfloat162(l[2], l[3]);
}

// in_proj weight: virtual row n -> gmem column jmap(n); output [n][k] bf16 hi/lo
__global__ __launch_bounds__(128) void convert_wip_split(const float* __restrict__ ipw) {
    const int n  = blockIdx.x;
    const int j  = (n < 1024) ? 3*n : 3*(n - 1024) + 2;
    const int k0 = threadIdx.x * 8;
    __nv_bfloat16 h[8], l[8];
    #pragma unroll
    for (int u = 0; u < 8; u++)
        bf16_split(ipw[(size_t)(k0 + u) * 3072 + j], h[u], l[u]);
    #pragma unroll
    for (int u = 0; u < 8; u += 2) {
        *(__nv_bfloat162*)&g_Wih[(size_t)n*1024 + k0 + u] = __nv_bfloat162(h[u], h[u+1]);
        *(__nv_bfloat162*)&g_Wil[(size_t)n*1024 + k0 + u] = __nv_bfloat162(l[u], l[u+1]);
    }
}

__global__ __launch_bounds__(128) void convert_wout_split(const float* __restrict__ ow) {
    const int n  = blockIdx.x;
    const int k0 = threadIdx.x * 8;
    __nv_bfloat16 h[8], l[8];
    #pragma unroll
    for (int u = 0; u < 8; u++)
        bf16_split(ow[(size_t)(k0 + u) * CH + n], h[u], l[u]);
    #pragma unroll
    for (int u = 0; u < 8; u += 2) {
        *(__nv_bfloat162*)&g_Woh[(size_t)n*1024 + k0 + u] = __nv_bfloat162(h[u], h[u+1]);
        *(__nv_bfloat162*)&g_Wol[(size_t)n*1024 + k0 + u] = __nv_bfloat162(l[u], l[u+1]);
    }
}

// g_Gt [c][m] f32 -> g_Gh/g_Gl [m][c] bf16 (tiled transpose + split)
__global__ void convert_gt_split() {
    __shared__ float s[32][33];
    const int c0 = blockIdx.x * 32, m0 = blockIdx.y * 32;
    const int tx = threadIdx.x, ty = threadIdx.y;
    s[ty][tx] = g_Gt[(size_t)(c0 + ty) * MTOT + m0 + tx];
    __syncthreads();
    __nv_bfloat16 h, l;
    bf16_split(s[tx][ty], h, l);
    g_Gh[(size_t)(m0 + ty) * CH + c0 + tx] = h;
    g_Gl[(size_t)(m0 + ty) * CH + c0 + tx] = l;
}

// ============================================================================
// bf16 mma.sync GEMM, 2-term split, ldmatrix + cp.async double-buffered.
// Block 128x128, 8 warps (4m x 2n), warp tile 32x64, K chunk 32.
// smem per buffer: A[128 rows][128B = h(64B)|l(64B)] 16KB + B same 16KB.
// Two buffers -> 64KB total, 2 CTAs/SM.
// MODE 0: in_proj  (A=g_Xh/l, B=g_Wih/l, epilogue -> g_Vrow / g_X2row + bias)
// MODE 1: out proj (A=g_Gh/l, B=g_Woh/l, epilogue -> out + bias)
// ============================================================================
#define GSM_BYTES 65536

template<int MODE>
__global__ __launch_bounds__(256, 2) void gemm_bf16_tc(
    const float* __restrict__ bias, float* __restrict__ out)
{
    extern __shared__ char dsm[];
    const uint32_t sb = smem_u32(dsm);

    const int tid  = threadIdx.x;
    const int lane = tid & 31;
    const int wid  = tid >> 5;
    const int wm   = wid >> 1;          // 0..3 -> 32 rows each
    const int wn   = wid & 1;           // 0..1 -> 64 cols each
    const int m0   = blockIdx.y * 128;
    const int bx   = blockIdx.x;
    const int n0   = bx * 128;

    const __nv_bfloat16* Ah = (MODE == 0) ? g_Xh : g_Gh;
    const __nv_bfloat16* Al = (MODE == 0) ? g_Xl : g_Gl;
    const __nv_bfloat16* Bh = (MODE == 0) ? g_Wih : g_Woh;
    const __nv_bfloat16* Bl = (MODE == 0) ? g_Wil : g_Wol;

    float acc[2][8][4];
    #pragma unroll
    for (int i = 0; i < 2; i++)
        #pragma unroll
        for (int j = 0; j < 8; j++)
            #pragma unroll
            for (int q = 0; q < 4; q++) acc[i][j][q] = 0.f;

    auto load_chunk = [&](int it, int buf) {
        const size_t kc0 = (size_t)it * 32;
        const uint32_t sA = sb + (uint32_t)buf * 32768u;
        const uint32_t sB = sA + 16384u;
        #pragma unroll
        for (int u = 0; u < 4; u++) {
            const int s = tid + u * 256;
            const int row = s >> 3, seg = s & 7;
            const uint32_t so = (uint32_t)(row * 128 + ((seg * 16) ^ ((row & 7) << 4)));
            const size_t ka = kc0 + (size_t)(seg & 3) * 8;
            const __nv_bfloat16* gA = (seg < 4 ? Ah : Al) + (size_t)(m0 + row) * 1024 + ka;
            const __nv_bfloat16* gB = (seg < 4 ? Bh : Bl) + (size_t)(n0 + row) * 1024 + ka;
            CP_ASYNC16(sA + so, gA);
            CP_ASYNC16(sB + so, gB);
        }
        CP_COMMIT();
    };

    auto compute_chunk = [&](int buf) {
        const uint32_t sA = sb + (uint32_t)buf * 32768u;
        const uint32_t sB = sA + 16384u;
        #pragma unroll
        for (int ks = 0; ks < 2; ks++) {
            uint32_t ah[2][4], al[2][4];
            #pragma unroll
            for (int mt = 0; mt < 2; mt++) {
                const int row = wm * 32 + mt * 16 + (lane & 15);
                const uint32_t r4 = (row & 7) << 4;
                const uint32_t cb = (uint32_t)(ks * 32 + ((lane >> 4) << 4));
                const uint32_t adh = sA + row * 128 + (cb ^ r4);
                const uint32_t adl = sA + row * 128 + ((cb + 64) ^ r4);
                LDSM4(ah[mt][0], ah[mt][1], ah[mt][2], ah[mt][3], adh);
                LDSM4(al[mt][0], al[mt][1], al[mt][2], al[mt][3], adl);
            }
            uint32_t bh[8][2], bl[8][2];
            #pragma unroll
            for (int nt2 = 0; nt2 < 4; nt2++) {
                const int n = wn * 64 + nt2 * 16 + (lane & 7) + ((lane >> 4) << 3);
                const uint32_t r4 = (n & 7) << 4;
                const uint32_t cb = (uint32_t)(ks * 32 + (((lane >> 3) & 1) << 4));
                const uint32_t adh = sB + n * 128 + (cb ^ r4);
                const uint32_t adl = sB + n * 128 + ((cb + 64) ^ r4);
                LDSM4(bh[2*nt2][0], bh[2*nt2][1], bh[2*nt2+1][0], bh[2*nt2+1][1], adh);
                LDSM4(bl[2*nt2][0], bl[2*nt2][1], bl[2*nt2+1][0], bl[2*nt2+1][1], adl);
            }
            #pragma unroll
            for (int mt = 0; mt < 2; mt++)
                #pragma unroll
                for (int nt = 0; nt < 8; nt++) {
                    mma_bf16(acc[mt][nt], ah[mt], bh[nt]);
                    mma_bf16(acc[mt][nt], ah[mt], bl[nt]);
                    mma_bf16(acc[mt][nt], al[mt], bh[nt]);
                }
        }
    };

    load_chunk(0, 0);
    for (int it = 0; it < 32; ++it) {
        if (it + 1 < 32) { load_chunk(it + 1, (it + 1) & 1); CP_WAIT1(); }
        else             { CP_WAIT0(); }
        __syncthreads();
        compute_chunk(it & 1);
        __syncthreads();
    }

    // epilogue: c frag rows = lane>>2 (+8), cols = 2*(lane&3) (+1)
    #pragma unroll
    for (int mt = 0; mt < 2; mt++) {
        const int r = m0 + wm * 32 + mt * 16 + (lane >> 2);
        #pragma unroll
        for (int nt = 0; nt < 8; nt++) {
            const int nl = wn * 64 + nt * 8 + ((lane & 3) << 1);
            if (MODE == 0) {
                const bool is_v = (bx < 8);
                const int c = (is_v ? bx : bx - 8) * 128 + nl;
                const float b0 = is_v ? bias[3*c]     : bias[3*c + 2];
                const float b1 = is_v ? bias[3*(c+1)] : bias[3*(c+1) + 2];
                float* dst = (is_v ? g_Vrow : g_X2row);
                *(float2*)&dst[(size_t)r * CH + c] =
                    make_float2(acc[mt][nt][0] + b0, acc[mt][nt][1] + b1);
                *(float2*)&dst[(size_t)(r + 8) * CH + c] =
                    make_float2(acc[mt][nt][2] + b0, acc[mt][nt][3] + b1);
            } else {
                const int c = n0 + nl;
                const float b0 = bias[c], b1 = bias[c + 1];
                *(float2*)&out[(size_t)r * CH + c] =
                    make_float2(acc[mt][nt][0] + b0, acc[mt][nt][1] + b1);
                *(float2*)&out[(size_t)(r + 8) * CH + c] =
                    make_float2(acc[mt][nt][2] + b0, acc[mt][nt][3] + b1);
            }
        }
    }
}

// ============================================================================
// Depthwise short conv (k=3, pad 1, per batch) fused with transpose to [c][m]
// ============================================================================
__global__ void shortconv_transpose(const float* __restrict__ sw,
                                    const float* __restrict__ sb)
{
    __shared__ float s[32][33];
    const int c0 = blockIdx.x * 32;
    const int m0 = blockIdx.y * 32;
    const int b  = m0 / LSEQ;
    const int l0 = m0 - b * LSEQ;
    const int tx = threadIdx.x, ty = threadIdx.y;
    const int c = c0 + tx;
    const int l = l0 + ty;

    size_t base = (size_t)(b*LSEQ + l) * CH + c;
    float vc = g_Vrow[base];
    float vm = (l > 0)       ? g_Vrow[base - CH] : 0.f;
    float vp = (l < LSEQ-1)  ? g_Vrow[base + CH] : 0.f;
    float w0 = sw[c*3], w1 = sw[c*3+1], w2 = sw[c*3+2];
    s[ty][tx] = w0*vm + w1*vc + w2*vp + sb[c];
    __syncthreads();
    g_Vt[(size_t)(c0 + ty) * MTOT + b*LSEQ + l0 + tx] = s[tx][ty];
}

__global__ void transpose_x2() {
    __shared__ float s[32][33];
    const int c0 = blockIdx.x * 32, m0 = blockIdx.y * 32;
    const int tx = threadIdx.x, ty = threadIdx.y;
    s[ty][tx] = g_X2row[(size_t)(m0+ty)*CH + c0 + tx];
    __syncthreads();
    g_X2t[(size_t)(c0+ty)*MTOT + m0 + tx] = s[tx][ty];
}
__global__ void transpose_coef() {
    __shared__ float s[32][33];
    const int c0 = blockIdx.x * 32, m0 = blockIdx.y * 32;
    const int tx = threadIdx.x, ty = threadIdx.y;
    s[ty][tx] = g_COEF[(size_t)(m0+ty)*CH + c0 + tx];
    __syncthreads();
    g_COEFt[(size_t)(c0+ty)*LSEQ + m0 + tx] = s[tx][ty];
}

// ============================================================================
// Filter MLP part 1: h2[l][t] for t in [0,128)
// ============================================================================
__global__ void filter_h2(const float* __restrict__ fw1, const float* __restrict__ fb1,
                          const float* __restrict__ fw2, const float* __restrict__ fb2)
{
    __shared__ float h1[64];
    const int l = blockIdx.x;
    const int t = threadIdx.x;
    const float pos = (float)l / (float)(LSEQ - 1);
    if (t < 64) h1[t] = gelu_exact(pos * fw1[t] + fb1[t]);
    __syncthreads();
    float s = fb2[t];
    #pragma unroll 8
    for (int j = 0; j < 64; j++) s += h1[j] * fw2[j*128 + t];
    g_H2[(size_t)l*128 + t] = gelu_exact(s);
}

// ============================================================================
// GEMM coef (SIMT, small): COEF[l][c] = h2 @ fw3[:, 2c+1] + fb3[2c+1]
// ============================================================================
__global__ __launch_bounds__(256) void gemm_coef(
    const float* __restrict__ fw3, const float* __restrict__ fb3)
{
    __shared__ float As[8][128];
    __shared__ float Bs[8][128];
    const int tid = threadIdx.x;
    const int tx = tid & 15, ty = tid >> 4;
    const int m0 = blockIdx.y * 128;
    const int n0 = blockIdx.x * 128;

    float acc[8][8];
    #pragma unroll
    for (int i = 0; i < 8; i++)
        #pragma unroll
        for (int j = 0; j < 8; j++) acc[i][j] = 0.f;

    const int arow = tid >> 1, akq = (tid & 1) * 4;
    const int bn = tid & 127;
    const int jm = 2 * (n0 + bn) + 1;
    const int kk0 = (tid >> 7) * 4;

    for (int k0 = 0; k0 < 128; k0 += 8) {
        float4 av = *(const float4*)&g_H2[(size_t)(m0 + arow) * 128 + k0 + akq];
        As[akq+0][arow] = av.x; As[akq+1][arow] = av.y;
        As[akq+2][arow] = av.z; As[akq+3][arow] = av.w;
        #pragma unroll
        for (int r = 0; r < 4; r++)
            Bs[kk0 + r][bn] = fw3[(size_t)(k0 + kk0 + r) * 2048 + jm];
        __syncthreads();
        #pragma unroll
        for (int kk = 0; kk < 8; kk++) {
            float a[8], b[8];
            #pragma unroll
            for (int i = 0; i < 8; i++) a[i] = As[kk][ty*8 + i];
            #pragma unroll
            for (int j = 0; j < 8; j++) b[j] = Bs[kk][tx*8 + j];
            #pragma unroll
            for (int i = 0; i < 8; i++)
                #pragma unroll
                for (int j = 0; j < 8; j++) acc[i][j] += a[i] * b[j];
        }
        __syncthreads();
    }

    float bo[8];
    #pragma unroll
    for (int j = 0; j < 8; j++) bo[j] = fb3[2*(n0 + tx*8 + j) + 1];
    #pragma unroll
    for (int i = 0; i < 8; i++) {
        int m = m0 + ty*8 + i;
        float4 o0 = make_float4(acc[i][0]+bo[0], acc[i][1]+bo[1],
                                acc[i][2]+bo[2], acc[i][3]+bo[3]);
        float4 o1 = make_float4(acc[i][4]+bo[4], acc[i][5]+bo[5],
                                acc[i][6]+bo[6], acc[i][7]+bo[7]);
        *(float4*)&g_COEF[(size_t)m*CH + n0 + tx*8]     = o0;
        *(float4*)&g_COEF[(size_t)m*CH + n0 + tx*8 + 4] = o1;
    }
}

// ============================================================================
// FFT convolution per channel — radix-4, no bit-reversal passes.
// Forward DIF (natural in -> digit-rev out); pointwise multiply in digit-rev
// order; inverse DIT with conj twiddles (digit-rev in -> natural out).
// Packing trick: z = v0 + i*v1; IFFT(FFT(z)*H) = conv0 + i*conv1 (both real),
// so NO spectral unpack is needed at all.
// smem: Z[16384] float2 (128KB) + Wt[4096] quarter twiddle table (32KB).
// ============================================================================
#define FFT_T    1024
#define FFT_SMEM ((16384 + 4096) * 8)

// W^k for k in [0, 12288): quarter table + quadrant rotation
__device__ __forceinline__ float2 tw3(const float2* Wt, int k) {
    float2 w = Wt[k & 4095];
    const int q = k >> 12;
    float2 r = w;
    if (q == 1) r = make_float2(w.y, -w.x);        // * -i
    if (q == 2) r = make_float2(-w.x, -w.y);       // * -1
    return r;
}

// Fused: zero-padded load + first forward-DIF stage (len=16384, c=d=0).
__device__ void fft_dif_first(float2* Z, const float2* Wt,
                              const float* __restrict__ re,
                              const float* __restrict__ im, int tid) {
    for (int p = tid; p < 4096; p += FFT_T) {
        float2 a = make_float2(re[p],        im ? im[p]        : 0.f);
        float2 b = make_float2(re[p + 4096], im ? im[p + 4096] : 0.f);
        Z[p]         = caddf(a, b);                                       // t0+t2
        Z[p + 4096]  = cmulf(make_float2(a.x + b.y, a.y - b.x), tw3(Wt, p));     // (t1+t3)*w1
        Z[p + 8192]  = cmulf(csubf(a, b),                       tw3(Wt, 2*p));   // (t0-t2)*w2
        Z[p + 12288] = cmulf(make_float2(a.x - b.y, a.y + b.x), tw3(Wt, 3*p));   // (t1-t3)*w3
    }
    __syncthreads();
}

// Forward DIF remaining stages: len = 4096 .. 4
__device__ void fft_dif_rest(float2* Z, const float2* Wt, int tid) {
    int tw = 2;
    for (int len = 4096; len >= 4; len >>= 2, tw += 2) {
        const int quarter = len >> 2;
        for (int b = tid; b < NFFT/4; b += FFT_T) {
            const int p  = b & (quarter - 1);
            const int i0 = 4*b - 3*p;
            const int i1 = i0 + quarter, i2 = i1 + quarter, i3 = i2 + quarter;
            float2 a = Z[i0], bb = Z[i1], cc = Z[i2], dd = Z[i3];
            float2 t0 = caddf(a, cc), t1 = csubf(a, cc);
            float2 t2 = caddf(bb, dd);
            float2 bd = csubf(bb, dd);
            float2 t3 = make_float2(bd.y, -bd.x);          // -i*(b-d)
            const int k1 = p << tw;
            Z[i0] = caddf(t0, t2);
            Z[i1] = cmulf(caddf(t1, t3), tw3(Wt, k1));
            Z[i2] = cmulf(csubf(t0, t2), tw3(Wt, 2*k1));
            Z[i3] = cmulf(csubf(t1, t3), tw3(Wt, 3*k1));
        }
        __syncthreads();
    }
}

// Inverse DIT (conj twiddles) stages: len = 4 .. 4096
__device__ void ifft_dit_rest(float2* Z, const float2* Wt, int tid) {
    int tw = 12;
    for (int len = 4; len <= 4096; len <<= 2, tw -= 2) {
        const int quarter = len >> 2;
        for (int b = tid; b < NFFT/4; b += FFT_T) {
            const int p  = b & (quarter - 1);
            const int i0 = 4*b - 3*p;
            const int i1 = i0 + quarter, i2 = i1 + quarter, i3 = i2 + quarter;
            const int k1 = p << tw;
            float2 a  = Z[i0];
            float2 bb = cmulconjf(Z[i1], tw3(Wt, k1));
            float2 cc = cmulconjf(Z[i2], tw3(Wt, 2*k1));
            float2 dd = cmulconjf(Z[i3], tw3(Wt, 3*k1));
            float2 t0 = caddf(a, cc), t1 = csubf(a, cc);
            float2 t2 = caddf(bb, dd);
            float2 bd = csubf(bb, dd);
            float2 t3 = make_float2(-bd.y, bd.x);          // +i*(b'-d')
            Z[i0] = caddf(t0, t2);
            Z[i1] = caddf(t1, t3);
            Z[i2] = csubf(t0, t2);
            Z[i3] = csubf(t1, t3);
        }
        __syncthreads();
    }
}

__global__ __launch_bounds__(FFT_T, 1) void fft_conv_kernel() {
    extern __shared__ float2 sm[];
    float2* Z  = sm;
    float2* Wt = sm + 16384;
    const int c   = blockIdx.x;
    const int tid = threadIdx.x;

    // quarter twiddle table: W[k] = (cos(2pik/N), -sin(2pik/N)), k < 4096
    for (int k = tid; k < 4096; k += FFT_T) {
        float ang = 3.834951969714103e-4f * (float)k;   // 2*pi/16384 * k
        float sv, cv;
        sincosf(ang, &sv, &cv);
        Wt[k] = make_float2(cv, -sv);
    }
    __syncthreads();

    // ---- filter FFT: coef (real, zero-padded) -> Hspec (digit-rev order) ----
    fft_dif_first(Z, Wt, g_COEFt + (size_t)c * LSEQ, nullptr, tid);
    fft_dif_rest(Z, Wt, tid);
    float2* Hs = g_Hspec + (size_t)c * NFFT;
    for (int j = tid; j < NFFT; j += FFT_T) Hs[j] = Z[j];
    __syncthreads();

    // ---- packed v FFT: z = v0 + i*v1 ----
    const float* v0 = g_Vt + (size_t)c * MTOT;
    fft_dif_first(Z, Wt, v0, v0 + LSEQ, tid);
    fft_dif_rest(Z, Wt, tid);

    // ---- pointwise multiply in digit-rev order (positions match) ----
    for (int j = tid; j < NFFT; j += FFT_T) Z[j] = cmulf(Z[j], Hs[j]);
    __syncthreads();

    // ---- inverse: DIT w/ conj twiddles; last stage fused with gate+store ----
    ifft_dit_rest(Z, Wt, tid);

    const float* x2 = g_X2t + (size_t)c * MTOT;
    float* go = g_Gt + (size_t)c * MTOT;
    const float scale = 1.0f / (float)NFFT;
    for (int p = tid; p < 4096; p += FFT_T) {
        float2 a  = Z[p];
        float2 bb = cmulconjf(Z[p + 4096],  tw3(Wt, p));
        float2 cc = cmulconjf(Z[p + 8192],  tw3(Wt, 2*p));
        float2 dd = cmulconjf(Z[p + 12288], tw3(Wt, 3*p));
        float2 t0 = caddf(a, cc), t1 = csubf(a, cc);
        float2 t2 = caddf(bb, dd);
        float2 bd = csubf(bb, dd);
        float2 t3 = make_float2(-bd.y, bd.x);
        float2 o0 = caddf(t0, t2);      // time index p      (re=batch0, im=batch1)
        float2 o1 = caddf(t1, t3);      // time index p+4096
        go[p]               = x2[p]               * (o0.x * scale);
        go[LSEQ + p]        = x2[LSEQ + p]        * (o0.y * scale);
        go[p + 4096]        = x2[p + 4096]        * (o1.x * scale);
        go[LSEQ + p + 4096] = x2[LSEQ + p + 4096] * (o1.y * scale);
    }
}

// ============================================================================
extern "C" void kernel_launch(void* const* d_in, const int* in_sizes, int n_in,
                              void* d_out, int out_size)
{
    const float* x   = (const float*)d_in[0];
    const float* ipw = (const float*)d_in[1];
    const float* ipb = (const float*)d_in[2];
    const float* sw  = (const float*)d_in[3];
    const float* sb  = (const float*)d_in[4];
    const float* fw1 = (const float*)d_in[5];
    const float* fb1 = (const float*)d_in[6];
    const float* fw2 = (const float*)d_in[7];
    const float* fb2 = (const float*)d_in[8];
    const float* fw3 = (const float*)d_in[9];
    const float* fb3 = (const float*)d_in[10];
    const float* ow  = (const float*)d_in[11];
    const float* ob  = (const float*)d_in[12];
    float* out = (float*)d_out;

    cudaFuncSetAttribute(fft_conv_kernel,
                         cudaFuncAttributeMaxDynamicSharedMemorySize, FFT_SMEM);
    cudaFuncSetAttribute(gemm_bf16_tc<0>,
                         cudaFuncAttributeMaxDynamicSharedMemorySize, GSM_BYTES);
    cudaFuncSetAttribute(gemm_bf16_tc<1>,
                         cudaFuncAttributeMaxDynamicSharedMemorySize, GSM_BYTES);

    // 1) split x and weights into bf16 hi/lo
    convert_x_split<<<MTOT*CH/4/256, 256>>>(x);
    convert_wip_split<<<2048, 128>>>(ipw);
    convert_wout_split<<<1024, 128>>>(ow);
    // 2) in_proj GEMM (bf16 mma.sync; v + x2 branches only; x1 is dead)
    gemm_bf16_tc<0><<<dim3(16, 128), 256, GSM_BYTES>>>(ipb, nullptr);
    // 3) depthwise short conv + transpose to channel-major
    shortconv_transpose<<<dim3(32, 512), dim3(32, 32)>>>(sw, sb);
    // 4) x2 transpose
    transpose_x2<<<dim3(32, 512), dim3(32, 32)>>>();
    // 5) filter MLP hidden
    filter_h2<<<LSEQ, 128>>>(fw1, fb1, fw2, fb2);
    // 6) filter coef GEMM (only order index 1 survives the reference loop)
    gemm_coef<<<dim3(8, 64), 256>>>(fw3, fb3);
    // 7) coef transpose
    transpose_coef<<<dim3(32, 256), dim3(32, 32)>>>();
    // 8) radix-4 FFT long conv + gating (one CTA per channel)
    fft_conv_kernel<<<CH, FFT_T, FFT_SMEM>>>();
    // 9) split gated output, out GEMM
    convert_gt_split<<<dim3(32, 512), dim3(32, 32)>>>();
    gemm_bf16_tc<1><<<dim3(8, 128), 256, GSM_BYTES>>>(ob, out);
}

// round 7
// speedup vs baseline: 2.1806x; 1.0560x over previous
#include <cuda_runtime.h>
#include <cuda_bf16.h>
#include <math.h>
#include <stdint.h>

// Problem constants
#define LSEQ   8192
#define NFFT   16384
#define CH     1024
#define BATCH  2
#define MTOT   (BATCH*LSEQ)      // 16384 rows

// ---------------- scratch (device globals; no allocations allowed) ----------
__device__ float g_Vcm  [CH*MTOT];     // in_proj v branch, channel-major [c][m]
__device__ float g_X2t  [CH*MTOT];     // x2 branch, channel-major [c][m]
__device__ float g_H2   [LSEQ*128];    // filter MLP hidden (L x 128)
__device__ float g_COEF [LSEQ*CH];     // filter coefs order-1, row-major [l][c]
__device__ float g_COEFt[CH*LSEQ];     // channel-major [c][l]
__device__ float g_Gt   [CH*MTOT];     // gated conv output, [c][m]
__device__ float2 g_Hspec[(size_t)CH*NFFT];  // filter spectrum, digit-rev order

// bf16 split operands for the tensor-core GEMMs
__device__ __nv_bfloat16 g_Xh [MTOT*CH], g_Xl [MTOT*CH];     // x, [m][k]
__device__ __nv_bfloat16 g_Gh [MTOT*CH], g_Gl [MTOT*CH];     // gated, [m][k]
__device__ __nv_bfloat16 g_Wih[2048*CH], g_Wil[2048*CH];     // in_proj cols, [n][k]
__device__ __nv_bfloat16 g_Woh[CH*CH],   g_Wol[CH*CH];       // out_w^T, [n][k]

// ---------------- generic helpers -------------------------------------------
__device__ __forceinline__ float gelu_exact(float x) {
    return 0.5f * x * (1.0f + erff(x * 0.70710678118654752f));
}
__device__ __forceinline__ float2 cmulf(float2 a, float2 b) {
    return make_float2(a.x*b.x - a.y*b.y, a.x*b.y + a.y*b.x);
}
__device__ __forceinline__ float2 cmulconjf(float2 a, float2 w) {  // a * conj(w)
    return make_float2(a.x*w.x + a.y*w.y, a.y*w.x - a.x*w.y);
}
__device__ __forceinline__ float2 caddf(float2 a, float2 b) {
    return make_float2(a.x + b.x, a.y + b.y);
}
__device__ __forceinline__ float2 csubf(float2 a, float2 b) {
    return make_float2(a.x - b.x, a.y - b.y);
}
__device__ __forceinline__ void bf16_split(float v, __nv_bfloat16 &h, __nv_bfloat16 &l) {
    h = __float2bfloat16(v);
    l = __float2bfloat16(v - __bfloat162float(h));
}
__device__ __forceinline__ uint32_t smem_u32(const void* p) {
    uint32_t a;
    asm("{ .reg .u64 t; cvta.to.shared.u64 t, %1; cvt.u32.u64 %0, t; }"
        : "=r"(a) : "l"(p));
    return a;
}

#define CP_ASYNC16(sm, gp) \
    asm volatile("cp.async.cg.shared.global [%0], [%1], 16;" \
                 :: "r"(sm), "l"(__cvta_generic_to_global(gp)) : "memory")
#define CP_COMMIT() asm volatile("cp.async.commit_group;" ::: "memory")
#define CP_WAIT0()  asm volatile("cp.async.wait_group 0;" ::: "memory")

#define LDSM4(r0, r1, r2, r3, ad) \
    asm volatile("ldmatrix.sync.aligned.m8n8.x4.shared.b16 {%0,%1,%2,%3}, [%4];" \
                 : "=r"(r0), "=r"(r1), "=r"(r2), "=r"(r3) : "r"(ad))

__device__ __forceinline__ void mma_bf16(float* c, const uint32_t* a, const uint32_t* b) {
    asm volatile("mma.sync.aligned.m16n8k16.row.col.f32.bf16.bf16.f32 "
        "{%0,%1,%2,%3}, {%4,%5,%6,%7}, {%8,%9}, {%0,%1,%2,%3};"
        : "+f"(c[0]), "+f"(c[1]), "+f"(c[2]), "+f"(c[3])
        : "r"(a[0]), "r"(a[1]), "r"(a[2]), "r"(a[3]), "r"(b[0]), "r"(b[1]));
}

// ============================================================================
// convert/split kernels
// ============================================================================
__global__ __launch_bounds__(256) void convert_x_split(const float* __restrict__ x) {
    size_t i = ((size_t)blockIdx.x * 256 + threadIdx.x) * 4;
    float4 v = *(const float4*)&x[i];
    __nv_bfloat16 h[4], l[4];
    bf16_split(v.x, h[0], l[0]); bf16_split(v.y, h[1], l[1]);
    bf16_split(v.z, h[2], l[2]); bf16_split(v.w, h[3], l[3]);
    *(__nv_bfloat162*)&g_Xh[i]   = __nv_bfloat162(h[0], h[1]);
    *(__nv_bfloat162*)&g_Xh[i+2] = __nv_bfloat162(h[2], h[3]);
    *(__nv_bfloat162*)&g_Xl[i]   = __nv_bfloat162(l[0], l[1]);
    *(__nv_bfloat162*)&g_Xl[i+2] = __nv_bfloat162(l[2], l[3]);
}

// in_proj weight: virtual row n -> gmem column jmap(n); output [n][k] bf16 hi/lo
__global__ __launch_bounds__(128) void convert_wip_split(const float* __restrict__ ipw) {
    const int n  = blockIdx.x;
    const int j  = (n < 1024) ? 3*n : 3*(n - 1024) + 2;
    const int k0 = threadIdx.x * 8;
    __nv_bfloat16 h[8], l[8];
    #pragma unroll
    for (int u = 0; u < 8; u++)
        bf16_split(ipw[(size_t)(k0 + u) * 3072 + j], h[u], l[u]);
    #pragma unroll
    for (int u = 0; u < 8; u += 2) {
        *(__nv_bfloat162*)&g_Wih[(size_t)n*1024 + k0 + u] = __nv_bfloat162(h[u], h[u+1]);
        *(__nv_bfloat162*)&g_Wil[(size_t)n*1024 + k0 + u] = __nv_bfloat162(l[u], l[u+1]);
    }
}

__global__ __launch_bounds__(128) void convert_wout_split(const float* __restrict__ ow) {
    const int n  = blockIdx.x;
    const int k0 = threadIdx.x * 8;
    __nv_bfloat16 h[8], l[8];
    #pragma unroll
    for (int u = 0; u < 8; u++)
        bf16_split(ow[(size_t)(k0 + u) * CH + n], h[u], l[u]);
    #pragma unroll
    for (int u = 0; u < 8; u += 2) {
        *(__nv_bfloat162*)&g_Woh[(size_t)n*1024 + k0 + u] = __nv_bfloat162(h[u], h[u+1]);
        *(__nv_bfloat162*)&g_Wol[(size_t)n*1024 + k0 + u] = __nv_bfloat162(l[u], l[u+1]);
    }
}

// g_Gt [c][m] f32 -> g_Gh/g_Gl [m][c] bf16 (tiled transpose + split)
__global__ void convert_gt_split() {
    __shared__ float s[32][33];
    const int c0 = blockIdx.x * 32, m0 = blockIdx.y * 32;
    const int tx = threadIdx.x, ty = threadIdx.y;
    s[ty][tx] = g_Gt[(size_t)(c0 + ty) * MTOT + m0 + tx];
    __syncthreads();
    __nv_bfloat16 h, l;
    bf16_split(s[tx][ty], h, l);
    g_Gh[(size_t)(m0 + ty) * CH + c0 + tx] = h;
    g_Gl[(size_t)(m0 + ty) * CH + c0 + tx] = l;
}

// ============================================================================
// bf16 mma.sync GEMM, 2-term split, ldmatrix + cp.async, ONE-sync pipeline.
// Block 128x128, 8 warps (4m x 2n), warp tile 32x64, K chunk 32, 2 buffers.
// MODE 0: in_proj. Epilogue TRANSPOSES tile -> g_Vcm / g_X2t [c][m] (+bias).
// MODE 1: out proj. Epilogue -> out [m][n] (+bias).
// ============================================================================
#define GSM_BYTES 65536

template<int MODE>
__global__ __launch_bounds__(256, 2) void gemm_bf16_tc(
    const float* __restrict__ bias, float* __restrict__ out)
{
    extern __shared__ char dsm[];
    const uint32_t sb = smem_u32(dsm);

    const int tid  = threadIdx.x;
    const int lane = tid & 31;
    const int wid  = tid >> 5;
    const int wm   = wid >> 1;          // 0..3 -> 32 rows each
    const int wn   = wid & 1;           // 0..1 -> 64 cols each
    const int m0   = blockIdx.y * 128;
    const int bx   = blockIdx.x;
    const int n0   = bx * 128;

    const __nv_bfloat16* Ah = (MODE == 0) ? g_Xh : g_Gh;
    const __nv_bfloat16* Al = (MODE == 0) ? g_Xl : g_Gl;
    const __nv_bfloat16* Bh = (MODE == 0) ? g_Wih : g_Woh;
    const __nv_bfloat16* Bl = (MODE == 0) ? g_Wil : g_Wol;

    float acc[2][8][4];
    #pragma unroll
    for (int i = 0; i < 2; i++)
        #pragma unroll
        for (int j = 0; j < 8; j++)
            #pragma unroll
            for (int q = 0; q < 4; q++) acc[i][j][q] = 0.f;

    auto load_chunk = [&](int it, int buf) {
        const size_t kc0 = (size_t)it * 32;
        const uint32_t sA = sb + (uint32_t)buf * 32768u;
        const uint32_t sB = sA + 16384u;
        #pragma unroll
        for (int u = 0; u < 4; u++) {
            const int s = tid + u * 256;
            const int row = s >> 3, seg = s & 7;
            const uint32_t so = (uint32_t)(row * 128 + ((seg * 16) ^ ((row & 7) << 4)));
            const size_t ka = kc0 + (size_t)(seg & 3) * 8;
            const __nv_bfloat16* gA = (seg < 4 ? Ah : Al) + (size_t)(m0 + row) * 1024 + ka;
            const __nv_bfloat16* gB = (seg < 4 ? Bh : Bl) + (size_t)(n0 + row) * 1024 + ka;
            CP_ASYNC16(sA + so, gA);
            CP_ASYNC16(sB + so, gB);
        }
        CP_COMMIT();
    };

    auto compute_chunk = [&](int buf) {
        const uint32_t sA = sb + (uint32_t)buf * 32768u;
        const uint32_t sB = sA + 16384u;
        #pragma unroll
        for (int ks = 0; ks < 2; ks++) {
            uint32_t ah[2][4], al[2][4];
            #pragma unroll
            for (int mt = 0; mt < 2; mt++) {
                const int row = wm * 32 + mt * 16 + (lane & 15);
                const uint32_t r4 = (row & 7) << 4;
                const uint32_t cb = (uint32_t)(ks * 32 + ((lane >> 4) << 4));
                const uint32_t adh = sA + row * 128 + (cb ^ r4);
                const uint32_t adl = sA + row * 128 + ((cb + 64) ^ r4);
                LDSM4(ah[mt][0], ah[mt][1], ah[mt][2], ah[mt][3], adh);
                LDSM4(al[mt][0], al[mt][1], al[mt][2], al[mt][3], adl);
            }
            uint32_t bh[8][2], bl[8][2];
            #pragma unroll
            for (int nt2 = 0; nt2 < 4; nt2++) {
                const int n = wn * 64 + nt2 * 16 + (lane & 7) + ((lane >> 4) << 3);
                const uint32_t r4 = (n & 7) << 4;
                const uint32_t cb = (uint32_t)(ks * 32 + (((lane >> 3) & 1) << 4));
                const uint32_t adh = sB + n * 128 + (cb ^ r4);
                const uint32_t adl = sB + n * 128 + ((cb + 64) ^ r4);
                LDSM4(bh[2*nt2][0], bh[2*nt2][1], bh[2*nt2+1][0], bh[2*nt2+1][1], adh);
                LDSM4(bl[2*nt2][0], bl[2*nt2][1], bl[2*nt2+1][0], bl[2*nt2+1][1], adl);
            }
            #pragma unroll
            for (int mt = 0; mt < 2; mt++)
                #pragma unroll
                for (int nt = 0; nt < 8; nt++) {
                    mma_bf16(acc[mt][nt], ah[mt], bh[nt]);
                    mma_bf16(acc[mt][nt], ah[mt], bl[nt]);
                    mma_bf16(acc[mt][nt], al[mt], bh[nt]);
                }
        }
    };

    // one-sync pipeline: wait load(it) -> sync -> prefetch load(it+1) -> compute(it)
    load_chunk(0, 0);
    for (int it = 0; it < 32; ++it) {
        CP_WAIT0();
        __syncthreads();
        if (it + 1 < 32) load_chunk(it + 1, (it + 1) & 1);
        compute_chunk(it & 1);
    }

    if (MODE == 0) {
        // Transposed epilogue: stage half-tile (128 m x 64 c) in smem,
        // write channel-major [c][m] with coalesced float4 stores.
        float* stage = (float*)dsm;          // [128][65] floats = 33 KB
        const bool is_v = (bx < 8);
        const int cbase = (is_v ? bx : bx - 8) * 128;
        #pragma unroll
        for (int h = 0; h < 2; h++) {
            __syncthreads();
            if (wn == h) {
                #pragma unroll
                for (int mt = 0; mt < 2; mt++) {
                    const int rl = wm * 32 + mt * 16 + (lane >> 2);
                    #pragma unroll
                    for (int nt = 0; nt < 8; nt++) {
                        const int cl = nt * 8 + ((lane & 3) << 1);
                        stage[rl * 65 + cl]           = acc[mt][nt][0];
                        stage[rl * 65 + cl + 1]       = acc[mt][nt][1];
                        stage[(rl + 8) * 65 + cl]     = acc[mt][nt][2];
                        stage[(rl + 8) * 65 + cl + 1] = acc[mt][nt][3];
                    }
                }
            }
            __syncthreads();
            const int cl  = tid >> 2;            // 0..63
            const int mch = (tid & 3) << 5;      // 0,32,64,96
            const int c   = cbase + h * 64 + cl;
            const float b = is_v ? bias[3*c] : bias[3*c + 2];
            float* dst = (is_v ? g_Vcm : g_X2t) + (size_t)c * MTOT + m0 + mch;
            #pragma unroll
            for (int j = 0; j < 32; j += 4) {
                float4 o = make_float4(stage[(mch+j)*65   + cl] + b,
                                       stage[(mch+j+1)*65 + cl] + b,
                                       stage[(mch+j+2)*65 + cl] + b,
                                       stage[(mch+j+3)*65 + cl] + b);
                *(float4*)&dst[j] = o;
            }
        }
    } else {
        #pragma unroll
        for (int mt = 0; mt < 2; mt++) {
            const int r = m0 + wm * 32 + mt * 16 + (lane >> 2);
            #pragma unroll
            for (int nt = 0; nt < 8; nt++) {
                const int c = n0 + wn * 64 + nt * 8 + ((lane & 3) << 1);
                const float b0 = bias[c], b1 = bias[c + 1];
                *(float2*)&out[(size_t)r * CH + c] =
                    make_float2(acc[mt][nt][0] + b0, acc[mt][nt][1] + b1);
                *(float2*)&out[(size_t)(r + 8) * CH + c] =
                    make_float2(acc[mt][nt][2] + b0, acc[mt][nt][3] + b1);
            }
        }
    }
}

// ============================================================================
// Filter MLP part 1: h2[l][t] for t in [0,128)
// ============================================================================
__global__ void filter_h2(const float* __restrict__ fw1, const float* __restrict__ fb1,
                          const float* __restrict__ fw2, const float* __restrict__ fb2)
{
    __shared__ float h1[64];
    const int l = blockIdx.x;
    const int t = threadIdx.x;
    const float pos = (float)l / (float)(LSEQ - 1);
    if (t < 64) h1[t] = gelu_exact(pos * fw1[t] + fb1[t]);
    __syncthreads();
    float s = fb2[t];
    #pragma unroll 8
    for (int j = 0; j < 64; j++) s += h1[j] * fw2[j*128 + t];
    g_H2[(size_t)l*128 + t] = gelu_exact(s);
}

// ============================================================================
// GEMM coef (SIMT, small): COEF[l][c] = h2 @ fw3[:, 2c+1] + fb3[2c+1]
// ============================================================================
__global__ __launch_bounds__(256) void gemm_coef(
    const float* __restrict__ fw3, const float* __restrict__ fb3)
{
    __shared__ float As[8][128];
    __shared__ float Bs[8][128];
    const int tid = threadIdx.x;
    const int tx = tid & 15, ty = tid >> 4;
    const int m0 = blockIdx.y * 128;
    const int n0 = blockIdx.x * 128;

    float acc[8][8];
    #pragma unroll
    for (int i = 0; i < 8; i++)
        #pragma unroll
        for (int j = 0; j < 8; j++) acc[i][j] = 0.f;

    const int arow = tid >> 1, akq = (tid & 1) * 4;
    const int bn = tid & 127;
    const int jm = 2 * (n0 + bn) + 1;
    const int kk0 = (tid >> 7) * 4;

    for (int k0 = 0; k0 < 128; k0 += 8) {
        float4 av = *(const float4*)&g_H2[(size_t)(m0 + arow) * 128 + k0 + akq];
        As[akq+0][arow] = av.x; As[akq+1][arow] = av.y;
        As[akq+2][arow] = av.z; As[akq+3][arow] = av.w;
        #pragma unroll
        for (int r = 0; r < 4; r++)
            Bs[kk0 + r][bn] = fw3[(size_t)(k0 + kk0 + r) * 2048 + jm];
        __syncthreads();
        #pragma unroll
        for (int kk = 0; kk < 8; kk++) {
            float a[8], b[8];
            #pragma unroll
            for (int i = 0; i < 8; i++) a[i] = As[kk][ty*8 + i];
            #pragma unroll
            for (int j = 0; j < 8; j++) b[j] = Bs[kk][tx*8 + j];
            #pragma unroll
            for (int i = 0; i < 8; i++)
                #pragma unroll
                for (int j = 0; j < 8; j++) acc[i][j] += a[i] * b[j];
        }
        __syncthreads();
    }

    float bo[8];
    #pragma unroll
    for (int j = 0; j < 8; j++) bo[j] = fb3[2*(n0 + tx*8 + j) + 1];
    #pragma unroll
    for (int i = 0; i < 8; i++) {
        int m = m0 + ty*8 + i;
        float4 o0 = make_float4(acc[i][0]+bo[0], acc[i][1]+bo[1],
                                acc[i][2]+bo[2], acc[i][3]+bo[3]);
        float4 o1 = make_float4(acc[i][4]+bo[4], acc[i][5]+bo[5],
                                acc[i][6]+bo[6], acc[i][7]+bo[7]);
        *(float4*)&g_COEF[(size_t)m*CH + n0 + tx*8]     = o0;
        *(float4*)&g_COEF[(size_t)m*CH + n0 + tx*8 + 4] = o1;
    }
}

__global__ void transpose_coef() {
    __shared__ float s[32][33];
    const int c0 = blockIdx.x * 32, m0 = blockIdx.y * 32;
    const int tx = threadIdx.x, ty = threadIdx.y;
    s[ty][tx] = g_COEF[(size_t)(m0+ty)*CH + c0 + tx];
    __syncthreads();
    g_COEFt[(size_t)(c0+ty)*LSEQ + m0 + tx] = s[tx][ty];
}

// ============================================================================
// FFT convolution per channel — radix-4, no bit-reversal passes.
// Fused: depthwise short-conv on load, spectral multiply in first inverse
// stage, gate + store in last inverse stage.
// ============================================================================
#define FFT_T    1024
#define FFT_SMEM ((16384 + 4096) * 8)

__device__ __forceinline__ float2 tw3(const float2* Wt, int k) {
    float2 w = Wt[k & 4095];
    const int q = k >> 12;
    float2 r = w;
    if (q == 1) r = make_float2(w.y, -w.x);        // * -i
    if (q == 2) r = make_float2(-w.x, -w.y);       // * -1
    return r;
}

__device__ __forceinline__ float conv3(const float* __restrict__ q, int l,
                                       float w0, float w1, float w2, float b) {
    float s = w1 * q[l] + b;
    if (l > 0)        s += w0 * q[l-1];
    if (l < LSEQ - 1) s += w2 * q[l+1];
    return s;
}

// Fused: zero-padded load + first forward-DIF stage (plain, for filter)
__device__ void fft_dif_first(float2* Z, const float2* Wt,
                              const float* __restrict__ re, int tid) {
    for (int p = tid; p < 4096; p += FFT_T) {
        float2 a = make_float2(re[p], 0.f);
        float2 b = make_float2(re[p + 4096], 0.f);
        Z[p]         = caddf(a, b);
        Z[p + 4096]  = cmulf(make_float2(a.x + b.y, a.y - b.x), tw3(Wt, p));
        Z[p + 8192]  = cmulf(csubf(a, b),                       tw3(Wt, 2*p));
        Z[p + 12288] = cmulf(make_float2(a.x - b.y, a.y + b.x), tw3(Wt, 3*p));
    }
    __syncthreads();
}

// Fused: short-conv + packed load (b0 in re, b1 in im) + first DIF stage
__device__ void fft_dif_first_conv(float2* Z, const float2* Wt,
                                   const float* __restrict__ v0,
                                   float w0, float w1, float w2, float cb, int tid) {
    const float* v1 = v0 + LSEQ;
    for (int p = tid; p < 4096; p += FFT_T) {
        float2 a = make_float2(conv3(v0, p, w0, w1, w2, cb),
                               conv3(v1, p, w0, w1, w2, cb));
        float2 b = make_float2(conv3(v0, p + 4096, w0, w1, w2, cb),
                               conv3(v1, p + 4096, w0, w1, w2, cb));
        Z[p]         = caddf(a, b);
        Z[p + 4096]  = cmulf(make_float2(a.x + b.y, a.y - b.x), tw3(Wt, p));
        Z[p + 8192]  = cmulf(csubf(a, b),                       tw3(Wt, 2*p));
        Z[p + 12288] = cmulf(make_float2(a.x - b.y, a.y + b.x), tw3(Wt, 3*p));
    }
    __syncthreads();
}

// Forward DIF remaining stages: len = 4096 .. 4
__device__ void fft_dif_rest(float2* Z, const float2* Wt, int tid) {
    int tw = 2;
    for (int len = 4096; len >= 4; len >>= 2, tw += 2) {
        const int quarter = len >> 2;
        for (int b = tid; b < NFFT/4; b += FFT_T) {
            const int p  = b & (quarter - 1);
            const int i0 = 4*b - 3*p;
            const int i1 = i0 + quarter, i2 = i1 + quarter, i3 = i2 + quarter;
            float2 a = Z[i0], bb = Z[i1], cc = Z[i2], dd = Z[i3];
            float2 t0 = caddf(a, cc), t1 = csubf(a, cc);
            float2 t2 = caddf(bb, dd);
            float2 bd = csubf(bb, dd);
            float2 t3 = make_float2(bd.y, -bd.x);          // -i*(b-d)
            const int k1 = p << tw;
            Z[i0] = caddf(t0, t2);
            Z[i1] = cmulf(caddf(t1, t3), tw3(Wt, k1));
            Z[i2] = cmulf(csubf(t0, t2), tw3(Wt, 2*k1));
            Z[i3] = cmulf(csubf(t1, t3), tw3(Wt, 3*k1));
        }
        __syncthreads();
    }
}

// First inverse stage (len=4, twiddles = 1) fused with spectral multiply
__device__ void ifft_first_mult(float2* Z, const float2* __restrict__ Hs, int tid) {
    for (int b = tid; b < NFFT/4; b += FFT_T) {
        const int i0 = 4*b;
        float2 a  = cmulf(Z[i0],     Hs[i0]);
        float2 bb = cmulf(Z[i0 + 1], Hs[i0 + 1]);
        float2 cc = cmulf(Z[i0 + 2], Hs[i0 + 2]);
        float2 dd = cmulf(Z[i0 + 3], Hs[i0 + 3]);
        float2 t0 = caddf(a, cc), t1 = csubf(a, cc);
        float2 t2 = caddf(bb, dd);
        float2 bd = csubf(bb, dd);
        float2 t3 = make_float2(-bd.y, bd.x);
        Z[i0]     = caddf(t0, t2);
        Z[i0 + 1] = caddf(t1, t3);
        Z[i0 + 2] = csubf(t0, t2);
        Z[i0 + 3] = csubf(t1, t3);
    }
    __syncthreads();
}

// Inverse DIT (conj twiddles) stages: len = 16 .. 4096
__device__ void ifft_dit_rest(float2* Z, const float2* Wt, int tid) {
    int tw = 10;
    for (int len = 16; len <= 4096; len <<= 2, tw -= 2) {
        const int quarter = len >> 2;
        for (int b = tid; b < NFFT/4; b += FFT_T) {
            const int p  = b & (quarter - 1);
            const int i0 = 4*b - 3*p;
            const int i1 = i0 + quarter, i2 = i1 + quarter, i3 = i2 + quarter;
            const int k1 = p << tw;
            float2 a  = Z[i0];
            float2 bb = cmulconjf(Z[i1], tw3(Wt, k1));
            float2 cc = cmulconjf(Z[i2], tw3(Wt, 2*k1));
            float2 dd = cmulconjf(Z[i3], tw3(Wt, 3*k1));
            float2 t0 = caddf(a, cc), t1 = csubf(a, cc);
            float2 t2 = caddf(bb, dd);
            float2 bd = csubf(bb, dd);
            float2 t3 = make_float2(-bd.y, bd.x);          // +i*(b'-d')
            Z[i0] = caddf(t0, t2);
            Z[i1] = caddf(t1, t3);
            Z[i2] = csubf(t0, t2);
            Z[i3] = csubf(t1, t3);
        }
        __syncthreads();
    }
}

__global__ __launch_bounds__(FFT_T, 1) void fft_conv_kernel(
    const float* __restrict__ sw, const float* __restrict__ sb)
{
    extern __shared__ float2 sm[];
    float2* Z  = sm;
    float2* Wt = sm + 16384;
    const int c   = blockIdx.x;
    const int tid = threadIdx.x;

    for (int k = tid; k < 4096; k += FFT_T) {
        float ang = 3.834951969714103e-4f * (float)k;   // 2*pi/16384 * k
        float sv, cv;
        sincosf(ang, &sv, &cv);
        Wt[k] = make_float2(cv, -sv);
    }
    __syncthreads();

    // ---- filter FFT: coef (real, zero-padded) -> Hspec (digit-rev order) ----
    fft_dif_first(Z, Wt, g_COEFt + (size_t)c * LSEQ, tid);
    fft_dif_rest(Z, Wt, tid);
    float2* Hs = g_Hspec + (size_t)c * NFFT;
    for (int j = tid; j < NFFT; j += FFT_T) Hs[j] = Z[j];
    __syncthreads();

    // ---- v FFT with fused depthwise short-conv: z = conv(v0) + i*conv(v1) ----
    const float w0 = sw[c*3], w1 = sw[c*3+1], w2 = sw[c*3+2], cb = sb[c];
    fft_dif_first_conv(Z, Wt, g_Vcm + (size_t)c * MTOT, w0, w1, w2, cb, tid);
    fft_dif_rest(Z, Wt, tid);

    // ---- inverse: multiply fused into first stage; remaining DIT stages ----
    ifft_first_mult(Z, Hs, tid);
    ifft_dit_rest(Z, Wt, tid);

    // ---- last inverse stage fused with gate + store ----
    const float* x2 = g_X2t + (size_t)c * MTOT;
    float* go = g_Gt + (size_t)c * MTOT;
    const float scale = 1.0f / (float)NFFT;
    for (int p = tid; p < 4096; p += FFT_T) {
        float2 a  = Z[p];
        float2 bb = cmulconjf(Z[p + 4096],  tw3(Wt, p));
        float2 cc = cmulconjf(Z[p + 8192],  tw3(Wt, 2*p));
        float2 dd = cmulconjf(Z[p + 12288], tw3(Wt, 3*p));
        float2 t0 = caddf(a, cc), t1 = csubf(a, cc);
        float2 t2 = caddf(bb, dd);
        float2 bd = csubf(bb, dd);
        float2 t3 = make_float2(-bd.y, bd.x);
        float2 o0 = caddf(t0, t2);      // time index p      (re=batch0, im=batch1)
        float2 o1 = caddf(t1, t3);      // time index p+4096
        go[p]               = x2[p]               * (o0.x * scale);
        go[LSEQ + p]        = x2[LSEQ + p]        * (o0.y * scale);
        go[p + 4096]        = x2[p + 4096]        * (o1.x * scale);
        go[LSEQ + p + 4096] = x2[LSEQ + p + 4096] * (o1.y * scale);
    }
}

// ============================================================================
extern "C" void kernel_launch(void* const* d_in, const int* in_sizes, int n_in,
                              void* d_out, int out_size)
{
    const float* x   = (const float*)d_in[0];
    const float* ipw = (const float*)d_in[1];
    const float* ipb = (const float*)d_in[2];
    const float* sw  = (const float*)d_in[3];
    const float* sb  = (const float*)d_in[4];
    const float* fw1 = (const float*)d_in[5];
    const float* fb1 = (const float*)d_in[6];
    const float* fw2 = (const float*)d_in[7];
    const float* fb2 = (const float*)d_in[8];
    const float* fw3 = (const float*)d_in[9];
    const float* fb3 = (const float*)d_in[10];
    const float* ow  = (const float*)d_in[11];
    const float* ob  = (const float*)d_in[12];
    float* out = (float*)d_out;

    cudaFuncSetAttribute(fft_conv_kernel,
                         cudaFuncAttributeMaxDynamicSharedMemorySize, FFT_SMEM);
    cudaFuncSetAttribute(gemm_bf16_tc<0>,
                         cudaFuncAttributeMaxDynamicSharedMemorySize, GSM_BYTES);
    cudaFuncSetAttribute(gemm_bf16_tc<1>,
                         cudaFuncAttributeMaxDynamicSharedMemorySize, GSM_BYTES);

    // 1) split x and weights into bf16 hi/lo
    convert_x_split<<<MTOT*CH/4/256, 256>>>(x);
    convert_wip_split<<<2048, 128>>>(ipw);
    convert_wout_split<<<1024, 128>>>(ow);
    // 2) in_proj GEMM; epilogue writes v/x2 directly in channel-major
    gemm_bf16_tc<0><<<dim3(16, 128), 256, GSM_BYTES>>>(ipb, nullptr);
    // 3) filter MLP hidden + coef GEMM + transpose
    filter_h2<<<LSEQ, 128>>>(fw1, fb1, fw2, fb2);
    gemm_coef<<<dim3(8, 64), 256>>>(fw3, fb3);
    transpose_coef<<<dim3(32, 256), dim3(32, 32)>>>();
    // 4) radix-4 FFT long conv (fused short-conv, multiply, gate)
    fft_conv_kernel<<<CH, FFT_T, FFT_SMEM>>>(sw, sb);
    // 5) split gated output, out GEMM
    convert_gt_split<<<dim3(32, 512), dim3(32, 32)>>>();
    gemm_bf16_tc<1><<<dim3(8, 128), 256, GSM_BYTES>>>(ob, out);
}

// round 8
// speedup vs baseline: 2.5555x; 1.1719x over previous
#include <cuda_runtime.h>
#include <cuda_bf16.h>
#include <math.h>
#include <stdint.h>

// Problem constants
#define LSEQ   8192
#define NFFT   16384
#define CH     1024
#define BATCH  2
#define MTOT   (BATCH*LSEQ)      // 16384 rows

// ---------------- scratch (device globals; no allocations allowed) ----------
__device__ float g_Vcm  [CH*MTOT];     // in_proj v branch, channel-major [c][m]
__device__ float g_X2t  [CH*MTOT];     // x2 branch, channel-major [c][m]
__device__ float g_H2   [LSEQ*128];    // filter MLP hidden (L x 128)
__device__ float g_COEF [LSEQ*CH];     // filter coefs order-1, row-major [l][c]
__device__ float g_COEFt[CH*LSEQ];     // channel-major [c][l]
__device__ float g_Gt   [CH*MTOT];     // gated conv output, [c][m]
__device__ float2 g_Hspec[(size_t)CH*NFFT];  // filter spectrum, digit-rev order

// bf16 split operands for the tensor-core GEMMs
__device__ __nv_bfloat16 g_Xh [MTOT*CH], g_Xl [MTOT*CH];     // x, [m][k]
__device__ __nv_bfloat16 g_Gh [MTOT*CH], g_Gl [MTOT*CH];     // gated, [m][k]
__device__ __nv_bfloat16 g_Wih[2048*CH], g_Wil[2048*CH];     // in_proj cols, [n][k]
__device__ __nv_bfloat16 g_Woh[CH*CH],   g_Wol[CH*CH];       // out_w^T, [n][k]

// ---------------- generic helpers -------------------------------------------
__device__ __forceinline__ float gelu_exact(float x) {
    return 0.5f * x * (1.0f + erff(x * 0.70710678118654752f));
}
__device__ __forceinline__ float2 cmulf(float2 a, float2 b) {
    return make_float2(a.x*b.x - a.y*b.y, a.x*b.y + a.y*b.x);
}
__device__ __forceinline__ float2 cmulconjf(float2 a, float2 w) {  // a * conj(w)
    return make_float2(a.x*w.x + a.y*w.y, a.y*w.x - a.x*w.y);
}
__device__ __forceinline__ float2 caddf(float2 a, float2 b) {
    return make_float2(a.x + b.x, a.y + b.y);
}
__device__ __forceinline__ float2 csubf(float2 a, float2 b) {
    return make_float2(a.x - b.x, a.y - b.y);
}
__device__ __forceinline__ void bf16_split(float v, __nv_bfloat16 &h, __nv_bfloat16 &l) {
    h = __float2bfloat16(v);
    l = __float2bfloat16(v - __bfloat162float(h));
}
__device__ __forceinline__ uint32_t smem_u32(const void* p) {
    uint32_t a;
    asm("{ .reg .u64 t; cvta.to.shared.u64 t, %1; cvt.u32.u64 %0, t; }"
        : "=r"(a) : "l"(p));
    return a;
}

#define CP_ASYNC16(sm, gp) \
    asm volatile("cp.async.cg.shared.global [%0], [%1], 16;" \
                 :: "r"(sm), "l"(__cvta_generic_to_global(gp)) : "memory")
#define CP_COMMIT() asm volatile("cp.async.commit_group;" ::: "memory")
#define CP_WAIT0()  asm volatile("cp.async.wait_group 0;" ::: "memory")

#define LDSM4(r0, r1, r2, r3, ad) \
    asm volatile("ldmatrix.sync.aligned.m8n8.x4.shared.b16 {%0,%1,%2,%3}, [%4];" \
                 : "=r"(r0), "=r"(r1), "=r"(r2), "=r"(r3) : "r"(ad))

__device__ __forceinline__ void mma_bf16(float* c, const uint32_t* a, const uint32_t* b) {
    asm volatile("mma.sync.aligned.m16n8k16.row.col.f32.bf16.bf16.f32 "
        "{%0,%1,%2,%3}, {%4,%5,%6,%7}, {%8,%9}, {%0,%1,%2,%3};"
        : "+f"(c[0]), "+f"(c[1]), "+f"(c[2]), "+f"(c[3])
        : "r"(a[0]), "r"(a[1]), "r"(a[2]), "r"(a[3]), "r"(b[0]), "r"(b[1]));
}

// ============================================================================
// convert/split kernels
// ============================================================================
__global__ __launch_bounds__(256) void convert_x_split(const float* __restrict__ x) {
    size_t i = ((size_t)blockIdx.x * 256 + threadIdx.x) * 4;
    float4 v = *(const float4*)&x[i];
    __nv_bfloat16 h[4], l[4];
    bf16_split(v.x, h[0], l[0]); bf16_split(v.y, h[1], l[1]);
    bf16_split(v.z, h[2], l[2]); bf16_split(v.w, h[3], l[3]);
    *(__nv_bfloat162*)&g_Xh[i]   = __nv_bfloat162(h[0], h[1]);
    *(__nv_bfloat162*)&g_Xh[i+2] = __nv_bfloat162(h[2], h[3]);
    *(__nv_bfloat162*)&g_Xl[i]   = __nv_bfloat162(l[0], l[1]);
    *(__nv_bfloat162*)&g_Xl[i+2] = __nv_bfloat162(l[2], l[3]);
}

// in_proj weight gather, COALESCED: tile [32 k][96 j] through smem.
// v rows n=c use col 3c; x2 rows n=1024+c use col 3c+2.
__global__ __launch_bounds__(256) void convert_wip_split(const float* __restrict__ ipw) {
    __shared__ float s[32][97];
    const int c0 = blockIdx.x * 32;
    const int k0 = blockIdx.y * 32;
    const int tid = threadIdx.x;
    for (int idx = tid; idx < 32*96; idx += 256) {
        const int r = idx / 96, cc = idx % 96;
        s[r][cc] = ipw[(size_t)(k0 + r) * 3072 + 3*c0 + cc];
    }
    __syncthreads();
    const int dc = tid >> 3;            // 0..31 channel within tile
    const int kq = (tid & 7) * 4;       // 4 consecutive k per thread
    const int c  = c0 + dc;
    __nv_bfloat16 vh[4], vl[4], xh[4], xl[4];
    #pragma unroll
    for (int u = 0; u < 4; u++) {
        bf16_split(s[kq+u][3*dc],     vh[u], vl[u]);
        bf16_split(s[kq+u][3*dc + 2], xh[u], xl[u]);
    }
    const size_t ov = (size_t)c * 1024 + k0 + kq;
    const size_t ox = (size_t)(1024 + c) * 1024 + k0 + kq;
    *(__nv_bfloat162*)&g_Wih[ov]   = __nv_bfloat162(vh[0], vh[1]);
    *(__nv_bfloat162*)&g_Wih[ov+2] = __nv_bfloat162(vh[2], vh[3]);
    *(__nv_bfloat162*)&g_Wil[ov]   = __nv_bfloat162(vl[0], vl[1]);
    *(__nv_bfloat162*)&g_Wil[ov+2] = __nv_bfloat162(vl[2], vl[3]);
    *(__nv_bfloat162*)&g_Wih[ox]   = __nv_bfloat162(xh[0], xh[1]);
    *(__nv_bfloat162*)&g_Wih[ox+2] = __nv_bfloat162(xh[2], xh[3]);
    *(__nv_bfloat162*)&g_Wil[ox]   = __nv_bfloat162(xl[0], xl[1]);
    *(__nv_bfloat162*)&g_Wil[ox+2] = __nv_bfloat162(xl[2], xl[3]);
}

// out_w [k][n] -> g_Woh/g_Wol [n][k], coalesced tiled transpose + split
__global__ void convert_wout_split(const float* __restrict__ ow) {
    __shared__ float s[32][33];
    const int c0 = blockIdx.x * 32, k0 = blockIdx.y * 32;
    const int tx = threadIdx.x, ty = threadIdx.y;
    s[ty][tx] = ow[(size_t)(k0 + ty) * CH + c0 + tx];
    __syncthreads();
    __nv_bfloat16 h, l;
    bf16_split(s[tx][ty], h, l);
    g_Woh[(size_t)(c0 + ty) * 1024 + k0 + tx] = h;
    g_Wol[(size_t)(c0 + ty) * 1024 + k0 + tx] = l;
}

// g_Gt [c][m] f32 -> g_Gh/g_Gl [m][c] bf16 (tiled transpose + split)
__global__ void convert_gt_split() {
    __shared__ float s[32][33];
    const int c0 = blockIdx.x * 32, m0 = blockIdx.y * 32;
    const int tx = threadIdx.x, ty = threadIdx.y;
    s[ty][tx] = g_Gt[(size_t)(c0 + ty) * MTOT + m0 + tx];
    __syncthreads();
    __nv_bfloat16 h, l;
    bf16_split(s[tx][ty], h, l);
    g_Gh[(size_t)(m0 + ty) * CH + c0 + tx] = h;
    g_Gl[(size_t)(m0 + ty) * CH + c0 + tx] = l;
}

// ============================================================================
// bf16 mma.sync GEMM (Round-4 schedule: single 64KB buffer, KC=64, 2 syncs).
// Block 128x128, 8 warps (4m x 2n), warp tile 32x64.
// MODE 0: in_proj. Epilogue TRANSPOSES tile -> g_Vcm / g_X2t [c][m] (+bias).
// MODE 1: out proj. Epilogue -> out [m][n] (+bias).
// ============================================================================
#define GSM_BYTES 65536

template<int MODE>
__global__ __launch_bounds__(256, 2) void gemm_bf16_tc(
    const float* __restrict__ bias, float* __restrict__ out)
{
    extern __shared__ char dsm[];
    const uint32_t sb  = smem_u32(dsm);
    const uint32_t sAh = sb, sAl = sb + 16384, sBh = sb + 32768, sBl = sb + 49152;

    const int tid  = threadIdx.x;
    const int lane = tid & 31;
    const int wid  = tid >> 5;
    const int wm   = wid >> 1;
    const int wn   = wid & 1;
    const int m0   = blockIdx.y * 128;
    const int bx   = blockIdx.x;
    const int n0   = bx * 128;

    const __nv_bfloat16* Ah = (MODE == 0) ? g_Xh : g_Gh;
    const __nv_bfloat16* Al = (MODE == 0) ? g_Xl : g_Gl;
    const __nv_bfloat16* Bh = (MODE == 0) ? g_Wih : g_Woh;
    const __nv_bfloat16* Bl = (MODE == 0) ? g_Wil : g_Wol;

    float acc[2][8][4];
    #pragma unroll
    for (int i = 0; i < 2; i++)
        #pragma unroll
        for (int j = 0; j < 8; j++)
            #pragma unroll
            for (int q = 0; q < 4; q++) acc[i][j][q] = 0.f;

    const int lrow = tid >> 3;
    const int lseg = tid & 7;

    for (int it = 0; it < 16; ++it) {
        const size_t kc0 = (size_t)it * 64;
        #pragma unroll
        for (int u = 0; u < 4; u++) {
            const int row = lrow + u * 32;
            const uint32_t so = (uint32_t)(row * 128 + ((lseg * 16) ^ ((row & 7) << 4)));
            const size_t ga = (size_t)(m0 + row) * 1024 + kc0 + lseg * 8;
            const size_t gb = (size_t)(n0 + row) * 1024 + kc0 + lseg * 8;
            CP_ASYNC16(sAh + so, Ah + ga);
            CP_ASYNC16(sAl + so, Al + ga);
            CP_ASYNC16(sBh + so, Bh + gb);
            CP_ASYNC16(sBl + so, Bl + gb);
        }
        CP_COMMIT();
        CP_WAIT0();
        __syncthreads();

        #pragma unroll
        for (int ks = 0; ks < 4; ks++) {
            uint32_t ah[2][4], al[2][4];
            #pragma unroll
            for (int mt = 0; mt < 2; mt++) {
                const int row = wm * 32 + mt * 16 + (lane & 15);
                const uint32_t r4 = (row & 7) << 4;
                const uint32_t cb = (uint32_t)(ks * 32 + ((lane >> 4) << 4));
                const uint32_t ad = sAh + row * 128 + (cb ^ r4);
                LDSM4(ah[mt][0], ah[mt][1], ah[mt][2], ah[mt][3], ad);
                LDSM4(al[mt][0], al[mt][1], al[mt][2], al[mt][3], ad + 16384);
            }
            uint32_t bh[8][2], bl[8][2];
            #pragma unroll
            for (int nt2 = 0; nt2 < 4; nt2++) {
                const int n = wn * 64 + nt2 * 16 + (lane & 7) + ((lane >> 4) << 3);
                const uint32_t r4 = (n & 7) << 4;
                const uint32_t cb = (uint32_t)(ks * 32 + (((lane >> 3) & 1) << 4));
                const uint32_t ad = sBh + n * 128 + (cb ^ r4);
                LDSM4(bh[2*nt2][0], bh[2*nt2][1], bh[2*nt2+1][0], bh[2*nt2+1][1], ad);
                LDSM4(bl[2*nt2][0], bl[2*nt2][1], bl[2*nt2+1][0], bl[2*nt2+1][1], ad + 16384);
            }
            #pragma unroll
            for (int mt = 0; mt < 2; mt++)
                #pragma unroll
                for (int nt = 0; nt < 8; nt++) {
                    mma_bf16(acc[mt][nt], ah[mt], bh[nt]);
                    mma_bf16(acc[mt][nt], ah[mt], bl[nt]);
                    mma_bf16(acc[mt][nt], al[mt], bh[nt]);
                }
        }
        __syncthreads();
    }

    if (MODE == 0) {
        float* stage = (float*)dsm;          // [128][65] floats = 33 KB
        const bool is_v = (bx < 8);
        const int cbase = (is_v ? bx : bx - 8) * 128;
        #pragma unroll
        for (int h = 0; h < 2; h++) {
            __syncthreads();
            if (wn == h) {
                #pragma unroll
                for (int mt = 0; mt < 2; mt++) {
                    const int rl = wm * 32 + mt * 16 + (lane >> 2);
                    #pragma unroll
                    for (int nt = 0; nt < 8; nt++) {
                        const int cl = nt * 8 + ((lane & 3) << 1);
                        stage[rl * 65 + cl]           = acc[mt][nt][0];
                        stage[rl * 65 + cl + 1]       = acc[mt][nt][1];
                        stage[(rl + 8) * 65 + cl]     = acc[mt][nt][2];
                        stage[(rl + 8) * 65 + cl + 1] = acc[mt][nt][3];
                    }
                }
            }
            __syncthreads();
            const int cl  = tid >> 2;
            const int mch = (tid & 3) << 5;
            const int c   = cbase + h * 64 + cl;
            const float b = is_v ? bias[3*c] : bias[3*c + 2];
            float* dst = (is_v ? g_Vcm : g_X2t) + (size_t)c * MTOT + m0 + mch;
            #pragma unroll
            for (int j = 0; j < 32; j += 4) {
                float4 o = make_float4(stage[(mch+j)*65   + cl] + b,
                                       stage[(mch+j+1)*65 + cl] + b,
                                       stage[(mch+j+2)*65 + cl] + b,
                                       stage[(mch+j+3)*65 + cl] + b);
                *(float4*)&dst[j] = o;
            }
        }
    } else {
        #pragma unroll
        for (int mt = 0; mt < 2; mt++) {
            const int r = m0 + wm * 32 + mt * 16 + (lane >> 2);
            #pragma unroll
            for (int nt = 0; nt < 8; nt++) {
                const int c = n0 + wn * 64 + nt * 8 + ((lane & 3) << 1);
                const float b0 = bias[c], b1 = bias[c + 1];
                *(float2*)&out[(size_t)r * CH + c] =
                    make_float2(acc[mt][nt][0] + b0, acc[mt][nt][1] + b1);
                *(float2*)&out[(size_t)(r + 8) * CH + c] =
                    make_float2(acc[mt][nt][2] + b0, acc[mt][nt][3] + b1);
            }
        }
    }
}

// ============================================================================
// Filter MLP part 1 + coef GEMM + transpose (small, unchanged)
// ============================================================================
__global__ void filter_h2(const float* __restrict__ fw1, const float* __restrict__ fb1,
                          const float* __restrict__ fw2, const float* __restrict__ fb2)
{
    __shared__ float h1[64];
    const int l = blockIdx.x;
    const int t = threadIdx.x;
    const float pos = (float)l / (float)(LSEQ - 1);
    if (t < 64) h1[t] = gelu_exact(pos * fw1[t] + fb1[t]);
    __syncthreads();
    float s = fb2[t];
    #pragma unroll 8
    for (int j = 0; j < 64; j++) s += h1[j] * fw2[j*128 + t];
    g_H2[(size_t)l*128 + t] = gelu_exact(s);
}

__global__ __launch_bounds__(256) void gemm_coef(
    const float* __restrict__ fw3, const float* __restrict__ fb3)
{
    __shared__ float As[8][128];
    __shared__ float Bs[8][128];
    const int tid = threadIdx.x;
    const int tx = tid & 15, ty = tid >> 4;
    const int m0 = blockIdx.y * 128;
    const int n0 = blockIdx.x * 128;

    float acc[8][8];
    #pragma unroll
    for (int i = 0; i < 8; i++)
        #pragma unroll
        for (int j = 0; j < 8; j++) acc[i][j] = 0.f;

    const int arow = tid >> 1, akq = (tid & 1) * 4;
    const int bn = tid & 127;
    const int jm = 2 * (n0 + bn) + 1;
    const int kk0 = (tid >> 7) * 4;

    for (int k0 = 0; k0 < 128; k0 += 8) {
        float4 av = *(const float4*)&g_H2[(size_t)(m0 + arow) * 128 + k0 + akq];
        As[akq+0][arow] = av.x; As[akq+1][arow] = av.y;
        As[akq+2][arow] = av.z; As[akq+3][arow] = av.w;
        #pragma unroll
        for (int r = 0; r < 4; r++)
            Bs[kk0 + r][bn] = fw3[(size_t)(k0 + kk0 + r) * 2048 + jm];
        __syncthreads();
        #pragma unroll
        for (int kk = 0; kk < 8; kk++) {
            float a[8], b[8];
            #pragma unroll
            for (int i = 0; i < 8; i++) a[i] = As[kk][ty*8 + i];
            #pragma unroll
            for (int j = 0; j < 8; j++) b[j] = Bs[kk][tx*8 + j];
            #pragma unroll
            for (int i = 0; i < 8; i++)
                #pragma unroll
                for (int j = 0; j < 8; j++) acc[i][j] += a[i] * b[j];
        }
        __syncthreads();
    }

    float bo[8];
    #pragma unroll
    for (int j = 0; j < 8; j++) bo[j] = fb3[2*(n0 + tx*8 + j) + 1];
    #pragma unroll
    for (int i = 0; i < 8; i++) {
        int m = m0 + ty*8 + i;
        float4 o0 = make_float4(acc[i][0]+bo[0], acc[i][1]+bo[1],
                                acc[i][2]+bo[2], acc[i][3]+bo[3]);
        float4 o1 = make_float4(acc[i][4]+bo[4], acc[i][5]+bo[5],
                                acc[i][6]+bo[6], acc[i][7]+bo[7]);
        *(float4*)&g_COEF[(size_t)m*CH + n0 + tx*8]     = o0;
        *(float4*)&g_COEF[(size_t)m*CH + n0 + tx*8 + 4] = o1;
    }
}

__global__ void transpose_coef() {
    __shared__ float s[32][33];
    const int c0 = blockIdx.x * 32, m0 = blockIdx.y * 32;
    const int tx = threadIdx.x, ty = threadIdx.y;
    s[ty][tx] = g_COEF[(size_t)(m0+ty)*CH + c0 + tx];
    __syncthreads();
    g_COEFt[(size_t)(c0+ty)*LSEQ + m0 + tx] = s[tx][ty];
}

// ============================================================================
// FFT convolution per channel — radix-4 first/mult stages + radix-16 paired
// passes. Forward DIF (natural -> digit-rev), pointwise in digit-rev order,
// inverse DIT w/ conj twiddles (digit-rev -> natural).
// ============================================================================
#define FFT_T    512
#define FFT_SMEM ((16384 + 4096) * 8)

__device__ __forceinline__ float2 tw3(const float2* Wt, int k) {
    float2 w = Wt[k & 4095];
    const int q = k >> 12;
    float2 r = w;
    if (q == 1) r = make_float2(w.y, -w.x);        // * -i
    if (q == 2) r = make_float2(-w.x, -w.y);       // * -1
    return r;
}

__device__ __forceinline__ float conv3(const float* __restrict__ q, int l,
                                       float w0, float w1, float w2, float b) {
    float s = w1 * q[l] + b;
    if (l > 0)        s += w0 * q[l-1];
    if (l < LSEQ - 1) s += w2 * q[l+1];
    return s;
}

// Fused: zero-padded load + first forward-DIF stage (len 16384, radix-4)
__device__ void fft_dif_first(float2* Z, const float2* Wt,
                              const float* __restrict__ re, int tid) {
    for (int p = tid; p < 4096; p += FFT_T) {
        float2 a = make_float2(re[p], 0.f);
        float2 b = make_float2(re[p + 4096], 0.f);
        Z[p]         = caddf(a, b);
        Z[p + 4096]  = cmulf(make_float2(a.x + b.y, a.y - b.x), tw3(Wt, p));
        Z[p + 8192]  = cmulf(csubf(a, b),                       tw3(Wt, 2*p));
        Z[p + 12288] = cmulf(make_float2(a.x - b.y, a.y + b.x), tw3(Wt, 3*p));
    }
    __syncthreads();
}

// Fused: short-conv + packed load (b0 in re, b1 in im) + first DIF stage
__device__ void fft_dif_first_conv(float2* Z, const float2* Wt,
                                   const float* __restrict__ v0,
                                   float w0, float w1, float w2, float cb, int tid) {
    const float* v1 = v0 + LSEQ;
    for (int p = tid; p < 4096; p += FFT_T) {
        float2 a = make_float2(conv3(v0, p, w0, w1, w2, cb),
                               conv3(v1, p, w0, w1, w2, cb));
        float2 b = make_float2(conv3(v0, p + 4096, w0, w1, w2, cb),
                               conv3(v1, p + 4096, w0, w1, w2, cb));
        Z[p]         = caddf(a, b);
        Z[p + 4096]  = cmulf(make_float2(a.x + b.y, a.y - b.x), tw3(Wt, p));
        Z[p + 8192]  = cmulf(csubf(a, b),                       tw3(Wt, 2*p));
        Z[p + 12288] = cmulf(make_float2(a.x - b.y, a.y + b.x), tw3(Wt, 3*p));
    }
    __syncthreads();
}

// Forward DIF paired radix-16 pass: stage (len=LA) then stage (len=LA/4).
// TWA: 1<<TWA = NFFT/LA.
template<int LA, int TWA>
__device__ void fft_dif_pass16(float2* Z, const float2* Wt, int tid) {
    constexpr int qA = LA / 4, qB = LA / 16;
    constexpr int TWB = TWA + 2;
    for (int g = tid; g < NFFT/16; g += FFT_T) {
        const int base = (g / qB) * LA + (g % qB);
        const int p2   = g % qB;
        float2 x[4][4];                        // x[b][a] at base + a*qB + b*qA
        #pragma unroll
        for (int b = 0; b < 4; b++)
            #pragma unroll
            for (int a = 0; a < 4; a++)
                x[b][a] = Z[base + a*qB + b*qA];
        #pragma unroll
        for (int a = 0; a < 4; a++) {          // stage A: butterfly over b
            const int k = (p2 + a*qB) << TWA;
            float2 t0 = caddf(x[0][a], x[2][a]);
            float2 t1 = csubf(x[0][a], x[2][a]);
            float2 t2 = caddf(x[1][a], x[3][a]);
            float2 bd = csubf(x[1][a], x[3][a]);
            float2 t3 = make_float2(bd.y, -bd.x);
            x[0][a] = caddf(t0, t2);
            x[1][a] = cmulf(caddf(t1, t3), tw3(Wt, k));
            x[2][a] = cmulf(csubf(t0, t2), tw3(Wt, 2*k));
            x[3][a] = cmulf(csubf(t1, t3), tw3(Wt, 3*k));
        }
        const int k2 = p2 << TWB;
        const float2 w1 = tw3(Wt, k2), w2 = tw3(Wt, 2*k2), w3 = tw3(Wt, 3*k2);
        #pragma unroll
        for (int b = 0; b < 4; b++) {          // stage B: butterfly over a
            float2 t0 = caddf(x[b][0], x[b][2]);
            float2 t1 = csubf(x[b][0], x[b][2]);
            float2 t2 = caddf(x[b][1], x[b][3]);
            float2 bd = csubf(x[b][1], x[b][3]);
            float2 t3 = make_float2(bd.y, -bd.x);
            Z[base + 0*qB + b*qA] = caddf(t0, t2);
            Z[base + 1*qB + b*qA] = cmulf(caddf(t1, t3), w1);
            Z[base + 2*qB + b*qA] = cmulf(csubf(t0, t2), w2);
            Z[base + 3*qB + b*qA] = cmulf(csubf(t1, t3), w3);
        }
    }
    __syncthreads();
}

// First inverse stage (len=4, unit twiddles) fused with spectral multiply
__device__ void ifft_first_mult(float2* Z, const float2* __restrict__ Hs, int tid) {
    for (int b = tid; b < NFFT/4; b += FFT_T) {
        const int i0 = 4*b;
        float2 a  = cmulf(Z[i0],     Hs[i0]);
        float2 bb = cmulf(Z[i0 + 1], Hs[i0 + 1]);
        float2 cc = cmulf(Z[i0 + 2], Hs[i0 + 2]);
        float2 dd = cmulf(Z[i0 + 3], Hs[i0 + 3]);
        float2 t0 = caddf(a, cc), t1 = csubf(a, cc);
        float2 t2 = caddf(bb, dd);
        float2 bd = csubf(bb, dd);
        float2 t3 = make_float2(-bd.y, bd.x);
        Z[i0]     = caddf(t0, t2);
        Z[i0 + 1] = caddf(t1, t3);
        Z[i0 + 2] = csubf(t0, t2);
        Z[i0 + 3] = csubf(t1, t3);
    }
    __syncthreads();
}

// Inverse DIT paired radix-16 pass: stage (len=L1) then stage (len=4*L1).
// TW1: 1<<TW1 = NFFT/L1.
template<int L1, int TW1>
__device__ void ifft_dit_pass16(float2* Z, const float2* Wt, int tid) {
    constexpr int q1 = L1 / 4, L2 = 4 * L1;
    constexpr int TW2 = TW1 - 2;
    for (int g = tid; g < NFFT/16; g += FFT_T) {
        const int base = (g / q1) * L2 + (g % q1);
        const int p    = g % q1;
        float2 x[4][4];                        // x[b][a] at base + a*q1 + b*L1
        #pragma unroll
        for (int b = 0; b < 4; b++)
            #pragma unroll
            for (int a = 0; a < 4; a++)
                x[b][a] = Z[base + a*q1 + b*L1];
        const int k1 = p << TW1;
        const float2 u1 = tw3(Wt, k1), u2 = tw3(Wt, 2*k1), u3 = tw3(Wt, 3*k1);
        #pragma unroll
        for (int b = 0; b < 4; b++) {          // stage 1: butterfly over a
            float2 a0 = x[b][0];
            float2 a1 = cmulconjf(x[b][1], u1);
            float2 a2 = cmulconjf(x[b][2], u2);
            float2 a3 = cmulconjf(x[b][3], u3);
            float2 t0 = caddf(a0, a2), t1 = csubf(a0, a2);
            float2 t2 = caddf(a1, a3);
            float2 bd = csubf(a1, a3);
            float2 t3 = make_float2(-bd.y, bd.x);
            x[b][0] = caddf(t0, t2);
            x[b][1] = caddf(t1, t3);
            x[b][2] = csubf(t0, t2);
            x[b][3] = csubf(t1, t3);
        }
        #pragma unroll
        for (int a = 0; a < 4; a++) {          // stage 2: butterfly over b
            const int k2 = (p + a*q1) << TW2;
            float2 b0 = x[0][a];
            float2 b1 = cmulconjf(x[1][a], tw3(Wt, k2));
            float2 b2 = cmulconjf(x[2][a], tw3(Wt, 2*k2));
            float2 b3 = cmulconjf(x[3][a], tw3(Wt, 3*k2));
            float2 t0 = caddf(b0, b2), t1 = csubf(b0, b2);
            float2 t2 = caddf(b1, b3);
            float2 bd = csubf(b1, b3);
            float2 t3 = make_float2(-bd.y, bd.x);
            Z[base + a*q1 + 0*L1] = caddf(t0, t2);
            Z[base + a*q1 + 1*L1] = caddf(t1, t3);
            Z[base + a*q1 + 2*L1] = csubf(t0, t2);
            Z[base + a*q1 + 3*L1] = csubf(t1, t3);
        }
    }
    __syncthreads();
}

__global__ __launch_bounds__(FFT_T, 1) void fft_conv_kernel(
    const float* __restrict__ sw, const float* __restrict__ sb)
{
    extern __shared__ float2 sm[];
    float2* Z  = sm;
    float2* Wt = sm + 16384;
    const int c   = blockIdx.x;
    const int tid = threadIdx.x;

    for (int k = tid; k < 4096; k += FFT_T) {
        float ang = 3.834951969714103e-4f * (float)k;   // 2*pi/16384 * k
        float sv, cv;
        sincosf(ang, &sv, &cv);
        Wt[k] = make_float2(cv, -sv);
    }
    __syncthreads();

    // ---- filter FFT -> Hspec (digit-rev order) ----
    fft_dif_first(Z, Wt, g_COEFt + (size_t)c * LSEQ, tid);
    fft_dif_pass16<4096, 2>(Z, Wt, tid);
    fft_dif_pass16<256, 6>(Z, Wt, tid);
    fft_dif_pass16<16, 10>(Z, Wt, tid);
    float2* Hs = g_Hspec + (size_t)c * NFFT;
    for (int j = tid; j < NFFT; j += FFT_T) Hs[j] = Z[j];
    __syncthreads();

    // ---- v FFT with fused depthwise short-conv ----
    const float w0 = sw[c*3], w1 = sw[c*3+1], w2 = sw[c*3+2], cb = sb[c];
    fft_dif_first_conv(Z, Wt, g_Vcm + (size_t)c * MTOT, w0, w1, w2, cb, tid);
    fft_dif_pass16<4096, 2>(Z, Wt, tid);
    fft_dif_pass16<256, 6>(Z, Wt, tid);
    fft_dif_pass16<16, 10>(Z, Wt, tid);

    // ---- inverse: multiply fused into len-4 stage; two paired passes ----
    ifft_first_mult(Z, Hs, tid);
    ifft_dit_pass16<16, 10>(Z, Wt, tid);
    ifft_dit_pass16<256, 6>(Z, Wt, tid);

    // ---- final paired pass (len 4096 + len 16384) fused with gate+store ----
    const float* x2 = g_X2t + (size_t)c * MTOT;
    float* go = g_Gt + (size_t)c * MTOT;
    const float scale = 1.0f / (float)NFFT;
    for (int p = tid; p < 1024; p += FFT_T) {
        float2 x[4][4];                        // x[b][a] at p + a*1024 + b*4096
        #pragma unroll
        for (int b = 0; b < 4; b++)
            #pragma unroll
            for (int a = 0; a < 4; a++)
                x[b][a] = Z[p + a*1024 + b*4096];
        const int k1 = p << 2;
        const float2 u1 = tw3(Wt, k1), u2 = tw3(Wt, 2*k1), u3 = tw3(Wt, 3*k1);
        #pragma unroll
        for (int b = 0; b < 4; b++) {          // stage len-4096: butterfly over a
            float2 a0 = x[b][0];
            float2 a1 = cmulconjf(x[b][1], u1);
            float2 a2 = cmulconjf(x[b][2], u2);
            float2 a3 = cmulconjf(x[b][3], u3);
            float2 t0 = caddf(a0, a2), t1 = csubf(a0, a2);
            float2 t2 = caddf(a1, a3);
            float2 bd = csubf(a1, a3);
            float2 t3 = make_float2(-bd.y, bd.x);
            x[b][0] = caddf(t0, t2);
            x[b][1] = caddf(t1, t3);
            x[b][2] = csubf(t0, t2);
            x[b][3] = csubf(t1, t3);
        }
        #pragma unroll
        for (int a = 0; a < 4; a++) {          // stage len-16384 over b; keep b=0,1
            const int k2 = p + a*1024;
            float2 b0 = x[0][a];
            float2 b1 = cmulconjf(x[1][a], tw3(Wt, k2));
            float2 b2 = cmulconjf(x[2][a], tw3(Wt, 2*k2));
            float2 b3 = cmulconjf(x[3][a], tw3(Wt, 3*k2));
            float2 t0 = caddf(b0, b2), t1 = csubf(b0, b2);
            float2 t2 = caddf(b1, b3);
            float2 bd = csubf(b1, b3);
            float2 t3 = make_float2(-bd.y, bd.x);
            float2 o0 = caddf(t0, t2);         // time t
            float2 o1 = caddf(t1, t3);         // time t + 4096
            const int t = p + a*1024;
            go[t]               = x2[t]               * (o0.x * scale);
            go[LSEQ + t]        = x2[LSEQ + t]        * (o0.y * scale);
            go[t + 4096]        = x2[t + 4096]        * (o1.x * scale);
            go[LSEQ + t + 4096] = x2[LSEQ + t + 4096] * (o1.y * scale);
        }
    }
}

// ============================================================================
extern "C" void kernel_launch(void* const* d_in, const int* in_sizes, int n_in,
                              void* d_out, int out_size)
{
    const float* x   = (const float*)d_in[0];
    const float* ipw = (const float*)d_in[1];
    const float* ipb = (const float*)d_in[2];
    const float* sw  = (const float*)d_in[3];
    const float* sb  = (const float*)d_in[4];
    const float* fw1 = (const float*)d_in[5];
    const float* fb1 = (const float*)d_in[6];
    const float* fw2 = (const float*)d_in[7];
    const float* fb2 = (const float*)d_in[8];
    const float* fw3 = (const float*)d_in[9];
    const float* fb3 = (const float*)d_in[10];
    const float* ow  = (const float*)d_in[11];
    const float* ob  = (const float*)d_in[12];
    float* out = (float*)d_out;

    cudaFuncSetAttribute(fft_conv_kernel,
                         cudaFuncAttributeMaxDynamicSharedMemorySize, FFT_SMEM);
    cudaFuncSetAttribute(gemm_bf16_tc<0>,
                         cudaFuncAttributeMaxDynamicSharedMemorySize, GSM_BYTES);
    cudaFuncSetAttribute(gemm_bf16_tc<1>,
                         cudaFuncAttributeMaxDynamicSharedMemorySize, GSM_BYTES);

    // 1) split x and weights into bf16 hi/lo (coalesced gathers)
    convert_x_split<<<MTOT*CH/4/256, 256>>>(x);
    convert_wip_split<<<dim3(32, 32), 256>>>(ipw);
    convert_wout_split<<<dim3(32, 32), dim3(32, 32)>>>(ow);
    // 2) in_proj GEMM; epilogue writes v/x2 directly in channel-major
    gemm_bf16_tc<0><<<dim3(16, 128), 256, GSM_BYTES>>>(ipb, nullptr);
    // 3) filter MLP hidden + coef GEMM + transpose
    filter_h2<<<LSEQ, 128>>>(fw1, fb1, fw2, fb2);
    gemm_coef<<<dim3(8, 64), 256>>>(fw3, fb3);
    transpose_coef<<<dim3(32, 256), dim3(32, 32)>>>();
    // 4) radix-16-pass FFT long conv (fused short-conv, multiply, gate)
    fft_conv_kernel<<<CH, FFT_T, FFT_SMEM>>>(sw, sb);
    // 5) split gated output, out GEMM
    convert_gt_split<<<dim3(32, 512), dim3(32, 32)>>>();
    gemm_bf16_tc<1><<<dim3(8, 128), 256, GSM_BYTES>>>(ob, out);
}

// round 9
// speedup vs baseline: 3.0293x; 1.1854x over previous
#include <cuda_runtime.h>
#include <cuda_bf16.h>
#include <math.h>
#include <stdint.h>

// Problem constants
#define LSEQ   8192
#define NFFT   16384
#define CH     1024
#define BATCH  2
#define MTOT   (BATCH*LSEQ)      // 16384 rows

// ---------------- scratch (device globals; no allocations allowed) ----------
__device__ float g_Vcm  [CH*MTOT];     // in_proj v branch, channel-major [c][m]
__device__ float g_X2t  [CH*MTOT];     // x2 branch, channel-major [c][m]
__device__ float g_H2   [LSEQ*128];    // filter MLP hidden (L x 128)
__device__ float g_COEF [LSEQ*CH];     // filter coefs order-1, row-major [l][c]
__device__ float g_COEFt[CH*LSEQ];     // channel-major [c][l]
__device__ float g_Gt   [CH*MTOT];     // gated conv output, [c][m]
__device__ float2 g_Hspec[(size_t)CH*NFFT];  // filter spectrum, digit-rev order

// bf16 split operands for the tensor-core GEMMs
__device__ __nv_bfloat16 g_Xh [MTOT*CH], g_Xl [MTOT*CH];     // x, [m][k]
__device__ __nv_bfloat16 g_Gh [MTOT*CH], g_Gl [MTOT*CH];     // gated, [m][k]
__device__ __nv_bfloat16 g_Wih[2048*CH], g_Wil[2048*CH];     // in_proj cols, [n][k]
__device__ __nv_bfloat16 g_Woh[CH*CH],   g_Wol[CH*CH];       // out_w^T, [n][k]

// ---------------- generic helpers -------------------------------------------
__device__ __forceinline__ float gelu_exact(float x) {
    return 0.5f * x * (1.0f + erff(x * 0.70710678118654752f));
}
__device__ __forceinline__ float2 cmulf(float2 a, float2 b) {
    return make_float2(a.x*b.x - a.y*b.y, a.x*b.y + a.y*b.x);
}
__device__ __forceinline__ float2 cmulconjf(float2 a, float2 w) {  // a * conj(w)
    return make_float2(a.x*w.x + a.y*w.y, a.y*w.x - a.x*w.y);
}
__device__ __forceinline__ float2 caddf(float2 a, float2 b) {
    return make_float2(a.x + b.x, a.y + b.y);
}
__device__ __forceinline__ float2 csubf(float2 a, float2 b) {
    return make_float2(a.x - b.x, a.y - b.y);
}
__device__ __forceinline__ void bf16_split(float v, __nv_bfloat16 &h, __nv_bfloat16 &l) {
    h = __float2bfloat16(v);
    l = __float2bfloat16(v - __bfloat162float(h));
}
__device__ __forceinline__ uint32_t smem_u32(const void* p) {
    uint32_t a;
    asm("{ .reg .u64 t; cvta.to.shared.u64 t, %1; cvt.u32.u64 %0, t; }"
        : "=r"(a) : "l"(p));
    return a;
}

#define CP_ASYNC16(sm, gp) \
    asm volatile("cp.async.cg.shared.global [%0], [%1], 16;" \
                 :: "r"(sm), "l"(__cvta_generic_to_global(gp)) : "memory")
#define CP_COMMIT() asm volatile("cp.async.commit_group;" ::: "memory")
#define CP_WAIT0()  asm volatile("cp.async.wait_group 0;" ::: "memory")

#define LDSM4(r0, r1, r2, r3, ad) \
    asm volatile("ldmatrix.sync.aligned.m8n8.x4.shared.b16 {%0,%1,%2,%3}, [%4];" \
                 : "=r"(r0), "=r"(r1), "=r"(r2), "=r"(r3) : "r"(ad))

__device__ __forceinline__ void mma_bf16(float* c, const uint32_t* a, const uint32_t* b) {
    asm volatile("mma.sync.aligned.m16n8k16.row.col.f32.bf16.bf16.f32 "
        "{%0,%1,%2,%3}, {%4,%5,%6,%7}, {%8,%9}, {%0,%1,%2,%3};"
        : "+f"(c[0]), "+f"(c[1]), "+f"(c[2]), "+f"(c[3])
        : "r"(a[0]), "r"(a[1]), "r"(a[2]), "r"(a[3]), "r"(b[0]), "r"(b[1]));
}

// ============================================================================
// convert/split kernels
// ============================================================================
__global__ __launch_bounds__(256) void convert_x_split(const float* __restrict__ x) {
    size_t i = ((size_t)blockIdx.x * 256 + threadIdx.x) * 4;
    float4 v = *(const float4*)&x[i];
    __nv_bfloat16 h[4], l[4];
    bf16_split(v.x, h[0], l[0]); bf16_split(v.y, h[1], l[1]);
    bf16_split(v.z, h[2], l[2]); bf16_split(v.w, h[3], l[3]);
    *(__nv_bfloat162*)&g_Xh[i]   = __nv_bfloat162(h[0], h[1]);
    *(__nv_bfloat162*)&g_Xh[i+2] = __nv_bfloat162(h[2], h[3]);
    *(__nv_bfloat162*)&g_Xl[i]   = __nv_bfloat162(l[0], l[1]);
    *(__nv_bfloat162*)&g_Xl[i+2] = __nv_bfloat162(l[2], l[3]);
}

// in_proj weight gather, COALESCED: tile [32 k][96 j] through smem.
__global__ __launch_bounds__(256) void convert_wip_split(const float* __restrict__ ipw) {
    __shared__ float s[32][97];
    const int c0 = blockIdx.x * 32;
    const int k0 = blockIdx.y * 32;
    const int tid = threadIdx.x;
    for (int idx = tid; idx < 32*96; idx += 256) {
        const int r = idx / 96, cc = idx % 96;
        s[r][cc] = ipw[(size_t)(k0 + r) * 3072 + 3*c0 + cc];
    }
    __syncthreads();
    const int dc = tid >> 3;            // 0..31 channel within tile
    const int kq = (tid & 7) * 4;       // 4 consecutive k per thread
    const int c  = c0 + dc;
    __nv_bfloat16 vh[4], vl[4], xh[4], xl[4];
    #pragma unroll
    for (int u = 0; u < 4; u++) {
        bf16_split(s[kq+u][3*dc],     vh[u], vl[u]);
        bf16_split(s[kq+u][3*dc + 2], xh[u], xl[u]);
    }
    const size_t ov = (size_t)c * 1024 + k0 + kq;
    const size_t ox = (size_t)(1024 + c) * 1024 + k0 + kq;
    *(__nv_bfloat162*)&g_Wih[ov]   = __nv_bfloat162(vh[0], vh[1]);
    *(__nv_bfloat162*)&g_Wih[ov+2] = __nv_bfloat162(vh[2], vh[3]);
    *(__nv_bfloat162*)&g_Wil[ov]   = __nv_bfloat162(vl[0], vl[1]);
    *(__nv_bfloat162*)&g_Wil[ov+2] = __nv_bfloat162(vl[2], vl[3]);
    *(__nv_bfloat162*)&g_Wih[ox]   = __nv_bfloat162(xh[0], xh[1]);
    *(__nv_bfloat162*)&g_Wih[ox+2] = __nv_bfloat162(xh[2], xh[3]);
    *(__nv_bfloat162*)&g_Wil[ox]   = __nv_bfloat162(xl[0], xl[1]);
    *(__nv_bfloat162*)&g_Wil[ox+2] = __nv_bfloat162(xl[2], xl[3]);
}

// out_w [k][n] -> g_Woh/g_Wol [n][k], coalesced tiled transpose + split
__global__ void convert_wout_split(const float* __restrict__ ow) {
    __shared__ float s[32][33];
    const int c0 = blockIdx.x * 32, k0 = blockIdx.y * 32;
    const int tx = threadIdx.x, ty = threadIdx.y;
    s[ty][tx] = ow[(size_t)(k0 + ty) * CH + c0 + tx];
    __syncthreads();
    __nv_bfloat16 h, l;
    bf16_split(s[tx][ty], h, l);
    g_Woh[(size_t)(c0 + ty) * 1024 + k0 + tx] = h;
    g_Wol[(size_t)(c0 + ty) * 1024 + k0 + tx] = l;
}

// g_Gt [c][m] f32 -> g_Gh/g_Gl [m][c] bf16 (tiled transpose + split)
__global__ void convert_gt_split() {
    __shared__ float s[32][33];
    const int c0 = blockIdx.x * 32, m0 = blockIdx.y * 32;
    const int tx = threadIdx.x, ty = threadIdx.y;
    s[ty][tx] = g_Gt[(size_t)(c0 + ty) * MTOT + m0 + tx];
    __syncthreads();
    __nv_bfloat16 h, l;
    bf16_split(s[tx][ty], h, l);
    g_Gh[(size_t)(m0 + ty) * CH + c0 + tx] = h;
    g_Gl[(size_t)(m0 + ty) * CH + c0 + tx] = l;
}

// ============================================================================
// bf16 mma.sync GEMM (single 64KB buffer, KC=64, 2 syncs) — unchanged
// ============================================================================
#define GSM_BYTES 65536

template<int MODE>
__global__ __launch_bounds__(256, 2) void gemm_bf16_tc(
    const float* __restrict__ bias, float* __restrict__ out)
{
    extern __shared__ char dsm[];
    const uint32_t sb  = smem_u32(dsm);
    const uint32_t sAh = sb, sBh = sb + 32768;

    const int tid  = threadIdx.x;
    const int lane = tid & 31;
    const int wid  = tid >> 5;
    const int wm   = wid >> 1;
    const int wn   = wid & 1;
    const int m0   = blockIdx.y * 128;
    const int bx   = blockIdx.x;
    const int n0   = bx * 128;

    const __nv_bfloat16* Ah = (MODE == 0) ? g_Xh : g_Gh;
    const __nv_bfloat16* Al = (MODE == 0) ? g_Xl : g_Gl;
    const __nv_bfloat16* Bh = (MODE == 0) ? g_Wih : g_Woh;
    const __nv_bfloat16* Bl = (MODE == 0) ? g_Wil : g_Wol;

    float acc[2][8][4];
    #pragma unroll
    for (int i = 0; i < 2; i++)
        #pragma unroll
        for (int j = 0; j < 8; j++)
            #pragma unroll
            for (int q = 0; q < 4; q++) acc[i][j][q] = 0.f;

    const int lrow = tid >> 3;
    const int lseg = tid & 7;

    for (int it = 0; it < 16; ++it) {
        const size_t kc0 = (size_t)it * 64;
        #pragma unroll
        for (int u = 0; u < 4; u++) {
            const int row = lrow + u * 32;
            const uint32_t so = (uint32_t)(row * 128 + ((lseg * 16) ^ ((row & 7) << 4)));
            const size_t ga = (size_t)(m0 + row) * 1024 + kc0 + lseg * 8;
            const size_t gb = (size_t)(n0 + row) * 1024 + kc0 + lseg * 8;
            CP_ASYNC16(sAh + so, Ah + ga);
            CP_ASYNC16(sAh + 16384 + so, Al + ga);
            CP_ASYNC16(sBh + so, Bh + gb);
            CP_ASYNC16(sBh + 16384 + so, Bl + gb);
        }
        CP_COMMIT();
        CP_WAIT0();
        __syncthreads();

        #pragma unroll
        for (int ks = 0; ks < 4; ks++) {
            uint32_t ah[2][4], al[2][4];
            #pragma unroll
            for (int mt = 0; mt < 2; mt++) {
                const int row = wm * 32 + mt * 16 + (lane & 15);
                const uint32_t r4 = (row & 7) << 4;
                const uint32_t cb = (uint32_t)(ks * 32 + ((lane >> 4) << 4));
                const uint32_t ad = sAh + row * 128 + (cb ^ r4);
                LDSM4(ah[mt][0], ah[mt][1], ah[mt][2], ah[mt][3], ad);
                LDSM4(al[mt][0], al[mt][1], al[mt][2], al[mt][3], ad + 16384);
            }
            uint32_t bh[8][2], bl[8][2];
            #pragma unroll
            for (int nt2 = 0; nt2 < 4; nt2++) {
                const int n = wn * 64 + nt2 * 16 + (lane & 7) + ((lane >> 4) << 3);
                const uint32_t r4 = (n & 7) << 4;
                const uint32_t cb = (uint32_t)(ks * 32 + (((lane >> 3) & 1) << 4));
                const uint32_t ad = sBh + n * 128 + (cb ^ r4);
                LDSM4(bh[2*nt2][0], bh[2*nt2][1], bh[2*nt2+1][0], bh[2*nt2+1][1], ad);
                LDSM4(bl[2*nt2][0], bl[2*nt2][1], bl[2*nt2+1][0], bl[2*nt2+1][1], ad + 16384);
            }
            #pragma unroll
            for (int mt = 0; mt < 2; mt++)
                #pragma unroll
                for (int nt = 0; nt < 8; nt++) {
                    mma_bf16(acc[mt][nt], ah[mt], bh[nt]);
                    mma_bf16(acc[mt][nt], ah[mt], bl[nt]);
                    mma_bf16(acc[mt][nt], al[mt], bh[nt]);
                }
        }
        __syncthreads();
    }

    if (MODE == 0) {
        float* stage = (float*)dsm;          // [128][65] floats = 33 KB
        const bool is_v = (bx < 8);
        const int cbase = (is_v ? bx : bx - 8) * 128;
        #pragma unroll
        for (int h = 0; h < 2; h++) {
            __syncthreads();
            if (wn == h) {
                #pragma unroll
                for (int mt = 0; mt < 2; mt++) {
                    const int rl = wm * 32 + mt * 16 + (lane >> 2);
                    #pragma unroll
                    for (int nt = 0; nt < 8; nt++) {
                        const int cl = nt * 8 + ((lane & 3) << 1);
                        stage[rl * 65 + cl]           = acc[mt][nt][0];
                        stage[rl * 65 + cl + 1]       = acc[mt][nt][1];
                        stage[(rl + 8) * 65 + cl]     = acc[mt][nt][2];
                        stage[(rl + 8) * 65 + cl + 1] = acc[mt][nt][3];
                    }
                }
            }
            __syncthreads();
            const int cl  = tid >> 2;
            const int mch = (tid & 3) << 5;
            const int c   = cbase + h * 64 + cl;
            const float b = is_v ? bias[3*c] : bias[3*c + 2];
            float* dst = (is_v ? g_Vcm : g_X2t) + (size_t)c * MTOT + m0 + mch;
            #pragma unroll
            for (int j = 0; j < 32; j += 4) {
                float4 o = make_float4(stage[(mch+j)*65   + cl] + b,
                                       stage[(mch+j+1)*65 + cl] + b,
                                       stage[(mch+j+2)*65 + cl] + b,
                                       stage[(mch+j+3)*65 + cl] + b);
                *(float4*)&dst[j] = o;
            }
        }
    } else {
        #pragma unroll
        for (int mt = 0; mt < 2; mt++) {
            const int r = m0 + wm * 32 + mt * 16 + (lane >> 2);
            #pragma unroll
            for (int nt = 0; nt < 8; nt++) {
                const int c = n0 + wn * 64 + nt * 8 + ((lane & 3) << 1);
                const float b0 = bias[c], b1 = bias[c + 1];
                *(float2*)&out[(size_t)r * CH + c] =
                    make_float2(acc[mt][nt][0] + b0, acc[mt][nt][1] + b1);
                *(float2*)&out[(size_t)(r + 8) * CH + c] =
                    make_float2(acc[mt][nt][2] + b0, acc[mt][nt][3] + b1);
            }
        }
    }
}

// ============================================================================
// Filter MLP + coef GEMM + transpose (small, unchanged)
// ============================================================================
__global__ void filter_h2(const float* __restrict__ fw1, const float* __restrict__ fb1,
                          const float* __restrict__ fw2, const float* __restrict__ fb2)
{
    __shared__ float h1[64];
    const int l = blockIdx.x;
    const int t = threadIdx.x;
    const float pos = (float)l / (float)(LSEQ - 1);
    if (t < 64) h1[t] = gelu_exact(pos * fw1[t] + fb1[t]);
    __syncthreads();
    float s = fb2[t];
    #pragma unroll 8
    for (int j = 0; j < 64; j++) s += h1[j] * fw2[j*128 + t];
    g_H2[(size_t)l*128 + t] = gelu_exact(s);
}

__global__ __launch_bounds__(256) void gemm_coef(
    const float* __restrict__ fw3, const float* __restrict__ fb3)
{
    __shared__ float As[8][128];
    __shared__ float Bs[8][128];
    const int tid = threadIdx.x;
    const int tx = tid & 15, ty = tid >> 4;
    const int m0 = blockIdx.y * 128;
    const int n0 = blockIdx.x * 128;

    float acc[8][8];
    #pragma unroll
    for (int i = 0; i < 8; i++)
        #pragma unroll
        for (int j = 0; j < 8; j++) acc[i][j] = 0.f;

    const int arow = tid >> 1, akq = (tid & 1) * 4;
    const int bn = tid & 127;
    const int jm = 2 * (n0 + bn) + 1;
    const int kk0 = (tid >> 7) * 4;

    for (int k0 = 0; k0 < 128; k0 += 8) {
        float4 av = *(const float4*)&g_H2[(size_t)(m0 + arow) * 128 + k0 + akq];
        As[akq+0][arow] = av.x; As[akq+1][arow] = av.y;
        As[akq+2][arow] = av.z; As[akq+3][arow] = av.w;
        #pragma unroll
        for (int r = 0; r < 4; r++)
            Bs[kk0 + r][bn] = fw3[(size_t)(k0 + kk0 + r) * 2048 + jm];
        __syncthreads();
        #pragma unroll
        for (int kk = 0; kk < 8; kk++) {
            float a[8], b[8];
            #pragma unroll
            for (int i = 0; i < 8; i++) a[i] = As[kk][ty*8 + i];
            #pragma unroll
            for (int j = 0; j < 8; j++) b[j] = Bs[kk][tx*8 + j];
            #pragma unroll
            for (int i = 0; i < 8; i++)
                #pragma unroll
                for (int j = 0; j < 8; j++) acc[i][j] += a[i] * b[j];
        }
        __syncthreads();
    }

    float bo[8];
    #pragma unroll
    for (int j = 0; j < 8; j++) bo[j] = fb3[2*(n0 + tx*8 + j) + 1];
    #pragma unroll
    for (int i = 0; i < 8; i++) {
        int m = m0 + ty*8 + i;
        float4 o0 = make_float4(acc[i][0]+bo[0], acc[i][1]+bo[1],
                                acc[i][2]+bo[2], acc[i][3]+bo[3]);
        float4 o1 = make_float4(acc[i][4]+bo[4], acc[i][5]+bo[5],
                                acc[i][6]+bo[6], acc[i][7]+bo[7]);
        *(float4*)&g_COEF[(size_t)m*CH + n0 + tx*8]     = o0;
        *(float4*)&g_COEF[(size_t)m*CH + n0 + tx*8 + 4] = o1;
    }
}

__global__ void transpose_coef() {
    __shared__ float s[32][33];
    const int c0 = blockIdx.x * 32, m0 = blockIdx.y * 32;
    const int tx = threadIdx.x, ty = threadIdx.y;
    s[ty][tx] = g_COEF[(size_t)(m0+ty)*CH + c0 + tx];
    __syncthreads();
    g_COEFt[(size_t)(c0+ty)*LSEQ + m0 + tx] = s[tx][ty];
}

// ============================================================================
// FFT convolution — radix-16 passes, conflict-free padded smem + hoisted
// twiddles (w2=w1^2, w3=w1^3 computed arithmetically).
// ============================================================================
#define FFT_T    512
// padded Z index: one float2 pad per 16 -> conflict-free for all strides used
#define ZI(i) ((i) + ((i) >> 4))
#define Z_PAD_SZ 17408
#define FFT_SMEM ((Z_PAD_SZ + 4096) * 8)

__device__ __forceinline__ float2 tw3(const float2* Wt, int k) {
    float2 w = Wt[k & 4095];
    const int q = k >> 12;
    float2 r = w;
    if (q == 1) r = make_float2(w.y, -w.x);        // * -i
    if (q == 2) r = make_float2(-w.x, -w.y);       // * -1
    return r;
}

__device__ __forceinline__ float conv3(const float* __restrict__ q, int l,
                                       float w0, float w1, float w2, float b) {
    float s = w1 * q[l] + b;
    if (l > 0)        s += w0 * q[l-1];
    if (l < LSEQ - 1) s += w2 * q[l+1];
    return s;
}

// Fused: zero-padded load + first forward-DIF stage (len 16384, radix-4)
__device__ void fft_dif_first(float2* Z, const float2* Wt,
                              const float* __restrict__ re, int tid) {
    for (int p = tid; p < 4096; p += FFT_T) {
        float2 a = make_float2(re[p], 0.f);
        float2 b = make_float2(re[p + 4096], 0.f);
        float2 w1 = tw3(Wt, p);
        float2 w2 = cmulf(w1, w1);
        float2 w3 = cmulf(w2, w1);
        Z[ZI(p)]         = caddf(a, b);
        Z[ZI(p + 4096)]  = cmulf(make_float2(a.x + b.y, a.y - b.x), w1);
        Z[ZI(p + 8192)]  = cmulf(csubf(a, b),                       w2);
        Z[ZI(p + 12288)] = cmulf(make_float2(a.x - b.y, a.y + b.x), w3);
    }
    __syncthreads();
}

// Fused: short-conv + packed load (b0 in re, b1 in im) + first DIF stage
__device__ void fft_dif_first_conv(float2* Z, const float2* Wt,
                                   const float* __restrict__ v0,
                                   float w0, float w1, float w2, float cb, int tid) {
    const float* v1 = v0 + LSEQ;
    for (int p = tid; p < 4096; p += FFT_T) {
        float2 a = make_float2(conv3(v0, p, w0, w1, w2, cb),
                               conv3(v1, p, w0, w1, w2, cb));
        float2 b = make_float2(conv3(v0, p + 4096, w0, w1, w2, cb),
                               conv3(v1, p + 4096, w0, w1, w2, cb));
        float2 t1 = tw3(Wt, p);
        float2 t2 = cmulf(t1, t1);
        float2 t3 = cmulf(t2, t1);
        Z[ZI(p)]         = caddf(a, b);
        Z[ZI(p + 4096)]  = cmulf(make_float2(a.x + b.y, a.y - b.x), t1);
        Z[ZI(p + 8192)]  = cmulf(csubf(a, b),                       t2);
        Z[ZI(p + 12288)] = cmulf(make_float2(a.x - b.y, a.y + b.x), t3);
    }
    __syncthreads();
}

// Forward DIF paired radix-16 pass: stage (len=LA) then (len=LA/4).
// Twiddles depend only on tid%qB -> hoisted; powers computed arithmetically.
template<int LA, int TWA>
__device__ void fft_dif_pass16(float2* Z, const float2* Wt, int tid) {
    constexpr int qA = LA / 4, qB = LA / 16;
    constexpr int TWB = TWA + 2;
    const int p2 = tid & (qB - 1);          // 512 % qB == 0 for qB in {256,16,1}
    float2 wA1[4], wA2[4], wA3[4];
    #pragma unroll
    for (int a = 0; a < 4; a++) {
        const int k = (p2 + a*qB) << TWA;
        wA1[a] = tw3(Wt, k);
        wA2[a] = cmulf(wA1[a], wA1[a]);
        wA3[a] = cmulf(wA2[a], wA1[a]);
    }
    const int k2 = p2 << TWB;
    const float2 wB1 = tw3(Wt, k2);
    const float2 wB2 = cmulf(wB1, wB1);
    const float2 wB3 = cmulf(wB2, wB1);
    #pragma unroll
    for (int half = 0; half < 2; half++) {
        const int g = tid + half * FFT_T;
        const int base = (g / qB) * LA + p2;
        float2 x[4][4];                        // x[b][a] at base + a*qB + b*qA
        #pragma unroll
        for (int b = 0; b < 4; b++)
            #pragma unroll
            for (int a = 0; a < 4; a++)
                x[b][a] = Z[ZI(base + a*qB + b*qA)];
        #pragma unroll
        for (int a = 0; a < 4; a++) {          // stage A: butterfly over b
            float2 t0 = caddf(x[0][a], x[2][a]);
            float2 t1 = csubf(x[0][a], x[2][a]);
            float2 t2 = caddf(x[1][a], x[3][a]);
            float2 bd = csubf(x[1][a], x[3][a]);
            float2 t3 = make_float2(bd.y, -bd.x);
            x[0][a] = caddf(t0, t2);
            x[1][a] = cmulf(caddf(t1, t3), wA1[a]);
            x[2][a] = cmulf(csubf(t0, t2), wA2[a]);
            x[3][a] = cmulf(csubf(t1, t3), wA3[a]);
        }
        #pragma unroll
        for (int b = 0; b < 4; b++) {          // stage B: butterfly over a
            float2 t0 = caddf(x[b][0], x[b][2]);
            float2 t1 = csubf(x[b][0], x[b][2]);
            float2 t2 = caddf(x[b][1], x[b][3]);
            float2 bd = csubf(x[b][1], x[b][3]);
            float2 t3 = make_float2(bd.y, -bd.x);
            Z[ZI(base + 0*qB + b*qA)] = caddf(t0, t2);
            Z[ZI(base + 1*qB + b*qA)] = cmulf(caddf(t1, t3), wB1);
            Z[ZI(base + 2*qB + b*qA)] = cmulf(csubf(t0, t2), wB2);
            Z[ZI(base + 3*qB + b*qA)] = cmulf(csubf(t1, t3), wB3);
        }
    }
    __syncthreads();
}

// First inverse stage (len=4, unit twiddles) fused with spectral multiply
__device__ void ifft_first_mult(float2* Z, const float2* __restrict__ Hs, int tid) {
    for (int b = tid; b < NFFT/4; b += FFT_T) {
        const int i0 = 4*b;
        float2 a  = cmulf(Z[ZI(i0)],     Hs[i0]);
        float2 bb = cmulf(Z[ZI(i0 + 1)], Hs[i0 + 1]);
        float2 cc = cmulf(Z[ZI(i0 + 2)], Hs[i0 + 2]);
        float2 dd = cmulf(Z[ZI(i0 + 3)], Hs[i0 + 3]);
        float2 t0 = caddf(a, cc), t1 = csubf(a, cc);
        float2 t2 = caddf(bb, dd);
        float2 bd = csubf(bb, dd);
        float2 t3 = make_float2(-bd.y, bd.x);
        Z[ZI(i0)]     = caddf(t0, t2);
        Z[ZI(i0 + 1)] = caddf(t1, t3);
        Z[ZI(i0 + 2)] = csubf(t0, t2);
        Z[ZI(i0 + 3)] = csubf(t1, t3);
    }
    __syncthreads();
}

// Inverse DIT paired radix-16 pass: stage (len=L1) then (len=4*L1).
template<int L1, int TW1>
__device__ void ifft_dit_pass16(float2* Z, const float2* Wt, int tid) {
    constexpr int q1 = L1 / 4, L2 = 4 * L1;
    constexpr int TW2 = TW1 - 2;
    const int p = tid & (q1 - 1);           // 512 % q1 == 0 for q1 in {4,64}
    const int k1 = p << TW1;
    const float2 u1 = tw3(Wt, k1);
    const float2 u2 = cmulf(u1, u1);
    const float2 u3 = cmulf(u2, u1);
    float2 v1[4], v2[4], v3[4];
    #pragma unroll
    for (int a = 0; a < 4; a++) {
        const int kk = (p + a*q1) << TW2;
        v1[a] = tw3(Wt, kk);
        v2[a] = cmulf(v1[a], v1[a]);
        v3[a] = cmulf(v2[a], v1[a]);
    }
    #pragma unroll
    for (int half = 0; half < 2; half++) {
        const int g = tid + half * FFT_T;
        const int base = (g / q1) * L2 + p;
        float2 x[4][4];                        // x[b][a] at base + a*q1 + b*L1
        #pragma unroll
        for (int b = 0; b < 4; b++)
            #pragma unroll
            for (int a = 0; a < 4; a++)
                x[b][a] = Z[ZI(base + a*q1 + b*L1)];
        #pragma unroll
        for (int b = 0; b < 4; b++) {          // stage 1: butterfly over a
            float2 a0 = x[b][0];
            float2 a1 = cmulconjf(x[b][1], u1);
            float2 a2 = cmulconjf(x[b][2], u2);
            float2 a3 = cmulconjf(x[b][3], u3);
            float2 t0 = caddf(a0, a2), t1 = csubf(a0, a2);
            float2 t2 = caddf(a1, a3);
            float2 bd = csubf(a1, a3);
            float2 t3 = make_float2(-bd.y, bd.x);
            x[b][0] = caddf(t0, t2);
            x[b][1] = caddf(t1, t3);
            x[b][2] = csubf(t0, t2);
            x[b][3] = csubf(t1, t3);
        }
        #pragma unroll
        for (int a = 0; a < 4; a++) {          // stage 2: butterfly over b
            float2 b0 = x[0][a];
            float2 b1 = cmulconjf(x[1][a], v1[a]);
            float2 b2 = cmulconjf(x[2][a], v2[a]);
            float2 b3 = cmulconjf(x[3][a], v3[a]);
            float2 t0 = caddf(b0, b2), t1 = csubf(b0, b2);
            float2 t2 = caddf(b1, b3);
            float2 bd = csubf(b1, b3);
            float2 t3 = make_float2(-bd.y, bd.x);
            Z[ZI(base + a*q1 + 0*L1)] = caddf(t0, t2);
            Z[ZI(base + a*q1 + 1*L1)] = caddf(t1, t3);
            Z[ZI(base + a*q1 + 2*L1)] = csubf(t0, t2);
            Z[ZI(base + a*q1 + 3*L1)] = csubf(t1, t3);
        }
    }
    __syncthreads();
}

__global__ __launch_bounds__(FFT_T, 1) void fft_conv_kernel(
    const float* __restrict__ sw, const float* __restrict__ sb)
{
    extern __shared__ float2 sm[];
    float2* Z  = sm;
    float2* Wt = sm + Z_PAD_SZ;
    const int c   = blockIdx.x;
    const int tid = threadIdx.x;

    for (int k = tid; k < 4096; k += FFT_T) {
        float ang = 3.834951969714103e-4f * (float)k;   // 2*pi/16384 * k
        float sv, cv;
        sincosf(ang, &sv, &cv);
        Wt[k] = make_float2(cv, -sv);
    }
    __syncthreads();

    // ---- filter FFT -> Hspec (digit-rev order) ----
    fft_dif_first(Z, Wt, g_COEFt + (size_t)c * LSEQ, tid);
    fft_dif_pass16<4096, 2>(Z, Wt, tid);
    fft_dif_pass16<256, 6>(Z, Wt, tid);
    fft_dif_pass16<16, 10>(Z, Wt, tid);
    float2* Hs = g_Hspec + (size_t)c * NFFT;
    for (int j = tid; j < NFFT; j += FFT_T) Hs[j] = Z[ZI(j)];
    __syncthreads();

    // ---- v FFT with fused depthwise short-conv ----
    const float w0 = sw[c*3], w1 = sw[c*3+1], w2 = sw[c*3+2], cb = sb[c];
    fft_dif_first_conv(Z, Wt, g_Vcm + (size_t)c * MTOT, w0, w1, w2, cb, tid);
    fft_dif_pass16<4096, 2>(Z, Wt, tid);
    fft_dif_pass16<256, 6>(Z, Wt, tid);
    fft_dif_pass16<16, 10>(Z, Wt, tid);

    // ---- inverse: multiply fused into len-4 stage; two paired passes ----
    ifft_first_mult(Z, Hs, tid);
    ifft_dit_pass16<16, 10>(Z, Wt, tid);
    ifft_dit_pass16<256, 6>(Z, Wt, tid);

    // ---- final paired pass (len 4096 + len 16384) fused with gate+store ----
    const float* x2 = g_X2t + (size_t)c * MTOT;
    float* go = g_Gt + (size_t)c * MTOT;
    const float scale = 1.0f / (float)NFFT;
    for (int p = tid; p < 1024; p += FFT_T) {
        float2 x[4][4];                        // x[b][a] at p + a*1024 + b*4096
        #pragma unroll
        for (int b = 0; b < 4; b++)
            #pragma unroll
            for (int a = 0; a < 4; a++)
                x[b][a] = Z[ZI(p + a*1024 + b*4096)];
        const float2 u1 = tw3(Wt, p << 2);
        const float2 u2 = cmulf(u1, u1);
        const float2 u3 = cmulf(u2, u1);
        #pragma unroll
        for (int b = 0; b < 4; b++) {          // stage len-4096: butterfly over a
            float2 a0 = x[b][0];
            float2 a1 = cmulconjf(x[b][1], u1);
            float2 a2 = cmulconjf(x[b][2], u2);
            float2 a3 = cmulconjf(x[b][3], u3);
            float2 t0 = caddf(a0, a2), t1 = csubf(a0, a2);
            float2 t2 = caddf(a1, a3);
            float2 bd = csubf(a1, a3);
            float2 t3 = make_float2(-bd.y, bd.x);
            x[b][0] = caddf(t0, t2);
            x[b][1] = caddf(t1, t3);
            x[b][2] = csubf(t0, t2);
            x[b][3] = csubf(t1, t3);
        }
        #pragma unroll
        for (int a = 0; a < 4; a++) {          // stage len-16384 over b; keep b=0,1
            const int k2 = p + a*1024;
            const float2 q1 = tw3(Wt, k2);
            const float2 q2 = cmulf(q1, q1);
            const float2 q3 = cmulf(q2, q1);
            float2 b0 = x[0][a];
            float2 b1 = cmulconjf(x[1][a], q1);
            float2 b2 = cmulconjf(x[2][a], q2);
            float2 b3 = cmulconjf(x[3][a], q3);
            float2 t0 = caddf(b0, b2), t1 = csubf(b0, b2);
            float2 t2 = caddf(b1, b3);
            float2 bd = csubf(b1, b3);
            float2 t3 = make_float2(-bd.y, bd.x);
            float2 o0 = caddf(t0, t2);         // time t
            float2 o1 = caddf(t1, t3);         // time t + 4096
            const int t = p + a*1024;
            go[t]               = x2[t]               * (o0.x * scale);
            go[LSEQ + t]        = x2[LSEQ + t]        * (o0.y * scale);
            go[t + 4096]        = x2[t + 4096]        * (o1.x * scale);
            go[LSEQ + t + 4096] = x2[LSEQ + t + 4096] * (o1.y * scale);
        }
    }
}

// ============================================================================
extern "C" void kernel_launch(void* const* d_in, const int* in_sizes, int n_in,
                              void* d_out, int out_size)
{
    const float* x   = (const float*)d_in[0];
    const float* ipw = (const float*)d_in[1];
    const float* ipb = (const float*)d_in[2];
    const float* sw  = (const float*)d_in[3];
    const float* sb  = (const float*)d_in[4];
    const float* fw1 = (const float*)d_in[5];
    const float* fb1 = (const float*)d_in[6];
    const float* fw2 = (const float*)d_in[7];
    const float* fb2 = (const float*)d_in[8];
    const float* fw3 = (const float*)d_in[9];
    const float* fb3 = (const float*)d_in[10];
    const float* ow  = (const float*)d_in[11];
    const float* ob  = (const float*)d_in[12];
    float* out = (float*)d_out;

    cudaFuncSetAttribute(fft_conv_kernel,
                         cudaFuncAttributeMaxDynamicSharedMemorySize, FFT_SMEM);
    cudaFuncSetAttribute(gemm_bf16_tc<0>,
                         cudaFuncAttributeMaxDynamicSharedMemorySize, GSM_BYTES);
    cudaFuncSetAttribute(gemm_bf16_tc<1>,
                         cudaFuncAttributeMaxDynamicSharedMemorySize, GSM_BYTES);

    // 1) split x and weights into bf16 hi/lo (coalesced gathers)
    convert_x_split<<<MTOT*CH/4/256, 256>>>(x);
    convert_wip_split<<<dim3(32, 32), 256>>>(ipw);
    convert_wout_split<<<dim3(32, 32), dim3(32, 32)>>>(ow);
    // 2) in_proj GEMM; epilogue writes v/x2 directly in channel-major
    gemm_bf16_tc<0><<<dim3(16, 128), 256, GSM_BYTES>>>(ipb, nullptr);
    // 3) filter MLP hidden + coef GEMM + transpose
    filter_h2<<<LSEQ, 128>>>(fw1, fb1, fw2, fb2);
    gemm_coef<<<dim3(8, 64), 256>>>(fw3, fb3);
    transpose_coef<<<dim3(32, 256), dim3(32, 32)>>>();
    // 4) conflict-free radix-16 FFT long conv (fused short-conv, mult, gate)
    fft_conv_kernel<<<CH, FFT_T, FFT_SMEM>>>(sw, sb);
    // 5) split gated output, out GEMM
    convert_gt_split<<<dim3(32, 512), dim3(32, 32)>>>();
    gemm_bf16_tc<1><<<dim3(8, 128), 256, GSM_BYTES>>>(ob, out);
}

// round 10
// speedup vs baseline: 3.3128x; 1.0936x over previous
#include <cuda_runtime.h>
#include <cuda_bf16.h>
#include <math.h>
#include <stdint.h>

// Problem constants
#define LSEQ   8192
#define NFFT   16384
#define CH     1024
#define BATCH  2
#define MTOT   (BATCH*LSEQ)      // 16384 rows

// ---------------- scratch (device globals; no allocations allowed) ----------
__device__ float g_Vcm  [CH*MTOT];     // in_proj v branch, channel-major [c][m]
__device__ float g_X2t  [CH*MTOT];     // x2 branch, channel-major [c][m]
__device__ float g_H2   [LSEQ*128];    // filter MLP hidden (L x 128)
__device__ float g_COEF [LSEQ*CH];     // filter coefs order-1, row-major [l][c]
__device__ float g_COEFt[CH*LSEQ];     // channel-major [c][l]

// bf16 split operands for the tensor-core GEMMs
__device__ __nv_bfloat16 g_Xh [MTOT*CH], g_Xl [MTOT*CH];     // x, [m][k]
__device__ __nv_bfloat16 g_Gh [CH*MTOT], g_Gl [CH*MTOT];     // gated, [c][m] (k-major!)
__device__ __nv_bfloat16 g_Wih[2048*CH], g_Wil[2048*CH];     // in_proj cols, [n][k]
__device__ __nv_bfloat16 g_Woh[CH*CH],   g_Wol[CH*CH];       // out_w^T, [n][k]

// ---------------- generic helpers -------------------------------------------
__device__ __forceinline__ float gelu_exact(float x) {
    return 0.5f * x * (1.0f + erff(x * 0.70710678118654752f));
}
__device__ __forceinline__ float2 cmulf(float2 a, float2 b) {
    return make_float2(a.x*b.x - a.y*b.y, a.x*b.y + a.y*b.x);
}
__device__ __forceinline__ float2 cmulconjf(float2 a, float2 w) {  // a * conj(w)
    return make_float2(a.x*w.x + a.y*w.y, a.y*w.x - a.x*w.y);
}
__device__ __forceinline__ float2 caddf(float2 a, float2 b) {
    return make_float2(a.x + b.x, a.y + b.y);
}
__device__ __forceinline__ float2 csubf(float2 a, float2 b) {
    return make_float2(a.x - b.x, a.y - b.y);
}
__device__ __forceinline__ void bf16_split(float v, __nv_bfloat16 &h, __nv_bfloat16 &l) {
    h = __float2bfloat16(v);
    l = __float2bfloat16(v - __bfloat162float(h));
}
__device__ __forceinline__ uint32_t smem_u32(const void* p) {
    uint32_t a;
    asm("{ .reg .u64 t; cvta.to.shared.u64 t, %1; cvt.u32.u64 %0, t; }"
        : "=r"(a) : "l"(p));
    return a;
}

#define CP_ASYNC16(sm, gp) \
    asm volatile("cp.async.cg.shared.global [%0], [%1], 16;" \
                 :: "r"(sm), "l"(__cvta_generic_to_global(gp)) : "memory")
#define CP_COMMIT() asm volatile("cp.async.commit_group;" ::: "memory")
#define CP_WAIT0()  asm volatile("cp.async.wait_group 0;" ::: "memory")

#define LDSM4(r0, r1, r2, r3, ad) \
    asm volatile("ldmatrix.sync.aligned.m8n8.x4.shared.b16 {%0,%1,%2,%3}, [%4];" \
                 : "=r"(r0), "=r"(r1), "=r"(r2), "=r"(r3) : "r"(ad))
#define LDSM4T(r0, r1, r2, r3, ad) \
    asm volatile("ldmatrix.sync.aligned.m8n8.x4.trans.shared.b16 {%0,%1,%2,%3}, [%4];" \
                 : "=r"(r0), "=r"(r1), "=r"(r2), "=r"(r3) : "r"(ad))

__device__ __forceinline__ void mma_bf16(float* c, const uint32_t* a, const uint32_t* b) {
    asm volatile("mma.sync.aligned.m16n8k16.row.col.f32.bf16.bf16.f32 "
        "{%0,%1,%2,%3}, {%4,%5,%6,%7}, {%8,%9}, {%0,%1,%2,%3};"
        : "+f"(c[0]), "+f"(c[1]), "+f"(c[2]), "+f"(c[3])
        : "r"(a[0]), "r"(a[1]), "r"(a[2]), "r"(a[3]), "r"(b[0]), "r"(b[1]));
}

// ============================================================================
// convert/split kernels
// ============================================================================
__global__ __launch_bounds__(256) void convert_x_split(const float* __restrict__ x) {
    size_t i = ((size_t)blockIdx.x * 256 + threadIdx.x) * 4;
    float4 v = *(const float4*)&x[i];
    __nv_bfloat16 h[4], l[4];
    bf16_split(v.x, h[0], l[0]); bf16_split(v.y, h[1], l[1]);
    bf16_split(v.z, h[2], l[2]); bf16_split(v.w, h[3], l[3]);
    *(__nv_bfloat162*)&g_Xh[i]   = __nv_bfloat162(h[0], h[1]);
    *(__nv_bfloat162*)&g_Xh[i+2] = __nv_bfloat162(h[2], h[3]);
    *(__nv_bfloat162*)&g_Xl[i]   = __nv_bfloat162(l[0], l[1]);
    *(__nv_bfloat162*)&g_Xl[i+2] = __nv_bfloat162(l[2], l[3]);
}

// in_proj weight gather, COALESCED: tile [32 k][96 j] through smem.
__global__ __launch_bounds__(256) void convert_wip_split(const float* __restrict__ ipw) {
    __shared__ float s[32][97];
    const int c0 = blockIdx.x * 32;
    const int k0 = blockIdx.y * 32;
    const int tid = threadIdx.x;
    for (int idx = tid; idx < 32*96; idx += 256) {
        const int r = idx / 96, cc = idx % 96;
        s[r][cc] = ipw[(size_t)(k0 + r) * 3072 + 3*c0 + cc];
    }
    __syncthreads();
    const int dc = tid >> 3;
    const int kq = (tid & 7) * 4;
    const int c  = c0 + dc;
    __nv_bfloat16 vh[4], vl[4], xh[4], xl[4];
    #pragma unroll
    for (int u = 0; u < 4; u++) {
        bf16_split(s[kq+u][3*dc],     vh[u], vl[u]);
        bf16_split(s[kq+u][3*dc + 2], xh[u], xl[u]);
    }
    const size_t ov = (size_t)c * 1024 + k0 + kq;
    const size_t ox = (size_t)(1024 + c) * 1024 + k0 + kq;
    *(__nv_bfloat162*)&g_Wih[ov]   = __nv_bfloat162(vh[0], vh[1]);
    *(__nv_bfloat162*)&g_Wih[ov+2] = __nv_bfloat162(vh[2], vh[3]);
    *(__nv_bfloat162*)&g_Wil[ov]   = __nv_bfloat162(vl[0], vl[1]);
    *(__nv_bfloat162*)&g_Wil[ov+2] = __nv_bfloat162(vl[2], vl[3]);
    *(__nv_bfloat162*)&g_Wih[ox]   = __nv_bfloat162(xh[0], xh[1]);
    *(__nv_bfloat162*)&g_Wih[ox+2] = __nv_bfloat162(xh[2], xh[3]);
    *(__nv_bfloat162*)&g_Wil[ox]   = __nv_bfloat162(xl[0], xl[1]);
    *(__nv_bfloat162*)&g_Wil[ox+2] = __nv_bfloat162(xl[2], xl[3]);
}

// out_w [k][n] -> g_Woh/g_Wol [n][k], coalesced tiled transpose + split
__global__ void convert_wout_split(const float* __restrict__ ow) {
    __shared__ float s[32][33];
    const int c0 = blockIdx.x * 32, k0 = blockIdx.y * 32;
    const int tx = threadIdx.x, ty = threadIdx.y;
    s[ty][tx] = ow[(size_t)(k0 + ty) * CH + c0 + tx];
    __syncthreads();
    __nv_bfloat16 h, l;
    bf16_split(s[tx][ty], h, l);
    g_Woh[(size_t)(c0 + ty) * 1024 + k0 + tx] = h;
    g_Wol[(size_t)(c0 + ty) * 1024 + k0 + tx] = l;
}

// ============================================================================
// bf16 mma.sync GEMM (single 64KB buffer, KC=64, 2 syncs).
// MODE 0: in_proj. A = g_Xh/l [m][k], 128B rows. Epilogue transposes ->
//         g_Vcm / g_X2t [c][m] (+bias).
// MODE 1: out proj. A = g_Gh/l [k][m] (k=channel), 256B rows, loaded with
//         ldmatrix.trans. Epilogue -> out [m][n] (+bias).
// ============================================================================
#define GSM_BYTES 65536

template<int MODE>
__global__ __launch_bounds__(256, 2) void gemm_bf16_tc(
    const float* __restrict__ bias, float* __restrict__ out)
{
    extern __shared__ char dsm[];
    const uint32_t sb  = smem_u32(dsm);
    const uint32_t sAh = sb, sBh = sb + 32768;

    const int tid  = threadIdx.x;
    const int lane = tid & 31;
    const int wid  = tid >> 5;
    const int wm   = wid >> 1;
    const int wn   = wid & 1;
    const int m0   = blockIdx.y * 128;
    const int bx   = blockIdx.x;
    const int n0   = bx * 128;

    const __nv_bfloat16* Ah = (MODE == 0) ? g_Xh : g_Gh;
    const __nv_bfloat16* Al = (MODE == 0) ? g_Xl : g_Gl;
    const __nv_bfloat16* Bh = (MODE == 0) ? g_Wih : g_Woh;
    const __nv_bfloat16* Bl = (MODE == 0) ? g_Wil : g_Wol;

    float acc[2][8][4];
    #pragma unroll
    for (int i = 0; i < 2; i++)
        #pragma unroll
        for (int j = 0; j < 8; j++)
            #pragma unroll
            for (int q = 0; q < 4; q++) acc[i][j][q] = 0.f;

    for (int it = 0; it < 16; ++it) {
        const size_t kc0 = (size_t)it * 64;
        if (MODE == 0) {
            #pragma unroll
            for (int u = 0; u < 4; u++) {
                const int s = tid + u * 256;
                const int row = s >> 3, seg = s & 7;
                const uint32_t so = (uint32_t)(row * 128 + ((seg * 16) ^ ((row & 7) << 4)));
                const size_t ga = (size_t)(m0 + row) * 1024 + kc0 + seg * 8;
                const size_t gb = (size_t)(n0 + row) * 1024 + kc0 + seg * 8;
                CP_ASYNC16(sAh + so, Ah + ga);
                CP_ASYNC16(sAh + 16384 + so, Al + ga);
                CP_ASYNC16(sBh + so, Bh + gb);
                CP_ASYNC16(sBh + 16384 + so, Bl + gb);
            }
        } else {
            // A: 64 k-rows x 256B ([k][m], contiguous along m)
            #pragma unroll
            for (int u = 0; u < 4; u++) {
                const int s = tid + u * 256;          // 0..1023
                const int row = s >> 4, seg = s & 15;
                const uint32_t so = (uint32_t)(row * 256 + ((seg * 16) ^ ((row & 7) << 4)));
                const size_t ga = (size_t)(kc0 + row) * MTOT + m0 + seg * 8;
                CP_ASYNC16(sAh + so, Ah + ga);
                CP_ASYNC16(sAh + 16384 + so, Al + ga);
            }
            // B: 128 n-rows x 128B (as MODE 0)
            #pragma unroll
            for (int u = 0; u < 4; u++) {
                const int s = tid + u * 256;
                const int row = s >> 3, seg = s & 7;
                const uint32_t so = (uint32_t)(row * 128 + ((seg * 16) ^ ((row & 7) << 4)));
                const size_t gb = (size_t)(n0 + row) * 1024 + kc0 + seg * 8;
                CP_ASYNC16(sBh + so, Bh + gb);
                CP_ASYNC16(sBh + 16384 + so, Bl + gb);
            }
        }
        CP_COMMIT();
        CP_WAIT0();
        __syncthreads();

        #pragma unroll
        for (int ks = 0; ks < 4; ks++) {
            uint32_t ah[2][4], al[2][4];
            #pragma unroll
            for (int mt = 0; mt < 2; mt++) {
                if (MODE == 0) {
                    const int row = wm * 32 + mt * 16 + (lane & 15);
                    const uint32_t r4 = (row & 7) << 4;
                    const uint32_t cb = (uint32_t)(ks * 32 + ((lane >> 4) << 4));
                    const uint32_t ad = sAh + row * 128 + (cb ^ r4);
                    LDSM4(ah[mt][0], ah[mt][1], ah[mt][2], ah[mt][3], ad);
                    LDSM4(al[mt][0], al[mt][1], al[mt][2], al[mt][3], ad + 16384);
                } else {
                    const int rowk = ks * 16 + (lane & 7) + ((lane >> 4) << 3);
                    const int mcol = wm * 32 + mt * 16 + (((lane >> 3) & 1) << 3);
                    const uint32_t ad = sAh + rowk * 256 +
                        (((uint32_t)(2 * mcol)) ^ ((uint32_t)(rowk & 7) << 4));
                    LDSM4T(ah[mt][0], ah[mt][1], ah[mt][2], ah[mt][3], ad);
                    LDSM4T(al[mt][0], al[mt][1], al[mt][2], al[mt][3], ad + 16384);
                }
            }
            uint32_t bh[8][2], bl[8][2];
            #pragma unroll
            for (int nt2 = 0; nt2 < 4; nt2++) {
                const int n = wn * 64 + nt2 * 16 + (lane & 7) + ((lane >> 4) << 3);
                const uint32_t r4 = (n & 7) << 4;
                const uint32_t cb = (uint32_t)(ks * 32 + (((lane >> 3) & 1) << 4));
                const uint32_t ad = sBh + n * 128 + (cb ^ r4);
                LDSM4(bh[2*nt2][0], bh[2*nt2][1], bh[2*nt2+1][0], bh[2*nt2+1][1], ad);
                LDSM4(bl[2*nt2][0], bl[2*nt2][1], bl[2*nt2+1][0], bl[2*nt2+1][1], ad + 16384);
            }
            #pragma unroll
            for (int mt = 0; mt < 2; mt++)
                #pragma unroll
                for (int nt = 0; nt < 8; nt++) {
                    mma_bf16(acc[mt][nt], ah[mt], bh[nt]);
                    mma_bf16(acc[mt][nt], ah[mt], bl[nt]);
                    mma_bf16(acc[mt][nt], al[mt], bh[nt]);
                }
        }
        __syncthreads();
    }

    if (MODE == 0) {
        float* stage = (float*)dsm;          // [128][65] floats = 33 KB
        const bool is_v = (bx < 8);
        const int cbase = (is_v ? bx : bx - 8) * 128;
        #pragma unroll
        for (int h = 0; h < 2; h++) {
            __syncthreads();
            if (wn == h) {
                #pragma unroll
                for (int mt = 0; mt < 2; mt++) {
                    const int rl = wm * 32 + mt * 16 + (lane >> 2);
                    #pragma unroll
                    for (int nt = 0; nt < 8; nt++) {
                        const int cl = nt * 8 + ((lane & 3) << 1);
                        stage[rl * 65 + cl]           = acc[mt][nt][0];
                        stage[rl * 65 + cl + 1]       = acc[mt][nt][1];
                        stage[(rl + 8) * 65 + cl]     = acc[mt][nt][2];
                        stage[(rl + 8) * 65 + cl + 1] = acc[mt][nt][3];
                    }
                }
            }
            __syncthreads();
            const int cl  = tid >> 2;
            const int mch = (tid & 3) << 5;
            const int c   = cbase + h * 64 + cl;
            const float b = is_v ? bias[3*c] : bias[3*c + 2];
            float* dst = (is_v ? g_Vcm : g_X2t) + (size_t)c * MTOT + m0 + mch;
            #pragma unroll
            for (int j = 0; j < 32; j += 4) {
                float4 o = make_float4(stage[(mch+j)*65   + cl] + b,
                                       stage[(mch+j+1)*65 + cl] + b,
                                       stage[(mch+j+2)*65 + cl] + b,
                                       stage[(mch+j+3)*65 + cl] + b);
                *(float4*)&dst[j] = o;
            }
        }
    } else {
        #pragma unroll
        for (int mt = 0; mt < 2; mt++) {
            const int r = m0 + wm * 32 + mt * 16 + (lane >> 2);
            #pragma unroll
            for (int nt = 0; nt < 8; nt++) {
                const int c = n0 + wn * 64 + nt * 8 + ((lane & 3) << 1);
                const float b0 = bias[c], b1 = bias[c + 1];
                *(float2*)&out[(size_t)r * CH + c] =
                    make_float2(acc[mt][nt][0] + b0, acc[mt][nt][1] + b1);
                *(float2*)&out[(size_t)(r + 8) * CH + c] =
                    make_float2(acc[mt][nt][2] + b0, acc[mt][nt][3] + b1);
            }
        }
    }
}

// ============================================================================
// Filter MLP + coef GEMM + transpose (small, unchanged)
// ============================================================================
__global__ void filter_h2(const float* __restrict__ fw1, const float* __restrict__ fb1,
                          const float* __restrict__ fw2, const float* __restrict__ fb2)
{
    __shared__ float h1[64];
    const int l = blockIdx.x;
    const int t = threadIdx.x;
    const float pos = (float)l / (float)(LSEQ - 1);
    if (t < 64) h1[t] = gelu_exact(pos * fw1[t] + fb1[t]);
    __syncthreads();
    float s = fb2[t];
    #pragma unroll 8
    for (int j = 0; j < 64; j++) s += h1[j] * fw2[j*128 + t];
    g_H2[(size_t)l*128 + t] = gelu_exact(s);
}

__global__ __launch_bounds__(256) void gemm_coef(
    const float* __restrict__ fw3, const float* __restrict__ fb3)
{
    __shared__ float As[8][128];
    __shared__ float Bs[8][128];
    const int tid = threadIdx.x;
    const int tx = tid & 15, ty = tid >> 4;
    const int m0 = blockIdx.y * 128;
    const int n0 = blockIdx.x * 128;

    float acc[8][8];
    #pragma unroll
    for (int i = 0; i < 8; i++)
        #pragma unroll
        for (int j = 0; j < 8; j++) acc[i][j] = 0.f;

    const int arow = tid >> 1, akq = (tid & 1) * 4;
    const int bn = tid & 127;
    const int jm = 2 * (n0 + bn) + 1;
    const int kk0 = (tid >> 7) * 4;

    for (int k0 = 0; k0 < 128; k0 += 8) {
        float4 av = *(const float4*)&g_H2[(size_t)(m0 + arow) * 128 + k0 + akq];
        As[akq+0][arow] = av.x; As[akq+1][arow] = av.y;
        As[akq+2][arow] = av.z; As[akq+3][arow] = av.w;
        #pragma unroll
        for (int r = 0; r < 4; r++)
            Bs[kk0 + r][bn] = fw3[(size_t)(k0 + kk0 + r) * 2048 + jm];
        __syncthreads();
        #pragma unroll
        for (int kk = 0; kk < 8; kk++) {
            float a[8], b[8];
            #pragma unroll
            for (int i = 0; i < 8; i++) a[i] = As[kk][ty*8 + i];
            #pragma unroll
            for (int j = 0; j < 8; j++) b[j] = Bs[kk][tx*8 + j];
            #pragma unroll
            for (int i = 0; i < 8; i++)
                #pragma unroll
                for (int j = 0; j < 8; j++) acc[i][j] += a[i] * b[j];
        }
        __syncthreads();
    }

    float bo[8];
    #pragma unroll
    for (int j = 0; j < 8; j++) bo[j] = fb3[2*(n0 + tx*8 + j) + 1];
    #pragma unroll
    for (int i = 0; i < 8; i++) {
        int m = m0 + ty*8 + i;
        float4 o0 = make_float4(acc[i][0]+bo[0], acc[i][1]+bo[1],
                                acc[i][2]+bo[2], acc[i][3]+bo[3]);
        float4 o1 = make_float4(acc[i][4]+bo[4], acc[i][5]+bo[5],
                                acc[i][6]+bo[6], acc[i][7]+bo[7]);
        *(float4*)&g_COEF[(size_t)m*CH + n0 + tx*8]     = o0;
        *(float4*)&g_COEF[(size_t)m*CH + n0 + tx*8 + 4] = o1;
    }
}

__global__ void transpose_coef() {
    __shared__ float s[32][33];
    const int c0 = blockIdx.x * 32, m0 = blockIdx.y * 32;
    const int tx = threadIdx.x, ty = threadIdx.y;
    s[ty][tx] = g_COEF[(size_t)(m0+ty)*CH + c0 + tx];
    __syncthreads();
    g_COEFt[(size_t)(c0+ty)*LSEQ + m0 + tx] = s[tx][ty];
}

// ============================================================================
// FFT convolution — radix-16 passes, conflict-free padded smem, filter
// spectrum held IN SHARED MEMORY as a Hermitian half-spectrum (natural order).
// ============================================================================
#define FFT_T    512
#define ZI(i) ((i) + ((i) >> 4))
#define Z_PAD_SZ  17408                 // float2
#define HS_PAD_SZ 8232                  // float2 (needs 8224 with HsI pad)
#define COS_SZ    4104                  // floats (needs 4097)
#define HsI(k) ((k) + ((k) >> 8))
#define FFT_SMEM ((Z_PAD_SZ + HS_PAD_SZ) * 8 + COS_SZ * 4)

// base-4 digit reversal of a 14-bit index (7 digits)
__device__ __forceinline__ int digrev4_14(int j) {
    unsigned r = __brev((unsigned)j) >> 18;
    return (int)(((r & 0x2AAAu) >> 1) | ((r & 0x1555u) << 1));
}

// W(k) = e^{-2pi i k/N} for k in [0,4096): cos-only quarter table
__device__ __forceinline__ float2 twc(const float* __restrict__ C, int k) {
    return make_float2(C[k], -C[4096 - k]);
}

__device__ __forceinline__ float conv3(const float* __restrict__ q, int l,
                                       float w0, float w1, float w2, float b) {
    float s = w1 * q[l] + b;
    if (l > 0)        s += w0 * q[l-1];
    if (l < LSEQ - 1) s += w2 * q[l+1];
    return s;
}

// Fused: zero-padded load + first forward-DIF stage (len 16384, radix-4)
__device__ void fft_dif_first(float2* Z, const float* C,
                              const float* __restrict__ re, int tid) {
    for (int p = tid; p < 4096; p += FFT_T) {
        float2 a = make_float2(re[p], 0.f);
        float2 b = make_float2(re[p + 4096], 0.f);
        float2 w1 = twc(C, p);
        float2 w2 = cmulf(w1, w1);
        float2 w3 = cmulf(w2, w1);
        Z[ZI(p)]         = caddf(a, b);
        Z[ZI(p + 4096)]  = cmulf(make_float2(a.x + b.y, a.y - b.x), w1);
        Z[ZI(p + 8192)]  = cmulf(csubf(a, b),                       w2);
        Z[ZI(p + 12288)] = cmulf(make_float2(a.x - b.y, a.y + b.x), w3);
    }
    __syncthreads();
}

// Fused: short-conv + packed load (b0 in re, b1 in im) + first DIF stage
__device__ void fft_dif_first_conv(float2* Z, const float* C,
                                   const float* __restrict__ v0,
                                   float w0, float w1, float w2, float cb, int tid) {
    const float* v1 = v0 + LSEQ;
    for (int p = tid; p < 4096; p += FFT_T) {
        float2 a = make_float2(conv3(v0, p, w0, w1, w2, cb),
                               conv3(v1, p, w0, w1, w2, cb));
        float2 b = make_float2(conv3(v0, p + 4096, w0, w1, w2, cb),
                               conv3(v1, p + 4096, w0, w1, w2, cb));
        float2 t1 = twc(C, p);
        float2 t2 = cmulf(t1, t1);
        float2 t3 = cmulf(t2, t1);
        Z[ZI(p)]         = caddf(a, b);
        Z[ZI(p + 4096)]  = cmulf(make_float2(a.x + b.y, a.y - b.x), t1);
        Z[ZI(p + 8192)]  = cmulf(csubf(a, b),                       t2);
        Z[ZI(p + 12288)] = cmulf(make_float2(a.x - b.y, a.y + b.x), t3);
    }
    __syncthreads();
}

// Forward DIF paired radix-16 pass: stage (len=LA) then (len=LA/4).
template<int LA, int TWA>
__device__ void fft_dif_pass16(float2* Z, const float* C, int tid) {
    constexpr int qA = LA / 4, qB = LA / 16;
    constexpr int TWB = TWA + 2;
    const int p2 = tid & (qB - 1);
    float2 wA1[4], wA2[4], wA3[4];
    #pragma unroll
    for (int a = 0; a < 4; a++) {
        const int k = (p2 + a*qB) << TWA;
        wA1[a] = twc(C, k);
        wA2[a] = cmulf(wA1[a], wA1[a]);
        wA3[a] = cmulf(wA2[a], wA1[a]);
    }
    const int k2 = p2 << TWB;
    const float2 wB1 = twc(C, k2);
    const float2 wB2 = cmulf(wB1, wB1);
    const float2 wB3 = cmulf(wB2, wB1);
    #pragma unroll
    for (int half = 0; half < 2; half++) {
        const int g = tid + half * FFT_T;
        const int base = (g / qB) * LA + p2;
        float2 x[4][4];
        #pragma unroll
        for (int b = 0; b < 4; b++)
            #pragma unroll
            for (int a = 0; a < 4; a++)
                x[b][a] = Z[ZI(base + a*qB + b*qA)];
        #pragma unroll
        for (int a = 0; a < 4; a++) {
            float2 t0 = caddf(x[0][a], x[2][a]);
            float2 t1 = csubf(x[0][a], x[2][a]);
            float2 t2 = caddf(x[1][a], x[3][a]);
            float2 bd = csubf(x[1][a], x[3][a]);
            float2 t3 = make_float2(bd.y, -bd.x);
            x[0][a] = caddf(t0, t2);
            x[1][a] = cmulf(caddf(t1, t3), wA1[a]);
            x[2][a] = cmulf(csubf(t0, t2), wA2[a]);
            x[3][a] = cmulf(csubf(t1, t3), wA3[a]);
        }
        #pragma unroll
        for (int b = 0; b < 4; b++) {
            float2 t0 = caddf(x[b][0], x[b][2]);
            float2 t1 = csubf(x[b][0], x[b][2]);
            float2 t2 = caddf(x[b][1], x[b][3]);
            float2 bd = csubf(x[b][1], x[b][3]);
            float2 t3 = make_float2(bd.y, -bd.x);
            Z[ZI(base + 0*qB + b*qA)] = caddf(t0, t2);
            Z[ZI(base + 1*qB + b*qA)] = cmulf(caddf(t1, t3), wB1);
            Z[ZI(base + 2*qB + b*qA)] = cmulf(csubf(t0, t2), wB2);
            Z[ZI(base + 3*qB + b*qA)] = cmulf(csubf(t1, t3), wB3);
        }
    }
    __syncthreads();
}

// First inverse stage (len=4, unit twiddles) fused with spectral multiply.
// H fetched from Hermitian half-spectrum in smem (natural-order index).
__device__ void ifft_first_mult(float2* Z, const float2* __restrict__ Hs, int tid) {
    for (int b = tid; b < NFFT/4; b += FFT_T) {
        const int i0 = 4*b;
        const int kb = digrev4_14(i0);          // digrev(i0+s) = kb + s*4096
        float2 zz[4];
        #pragma unroll
        for (int s2 = 0; s2 < 4; s2++) {
            const int k = kb + s2 * 4096;
            float2 H;
            if (k <= 8192) H = Hs[HsI(k)];
            else { const int kc = 16384 - k; H = Hs[HsI(kc)]; H.y = -H.y; }
            zz[s2] = cmulf(Z[ZI(i0 + s2)], H);
        }
        float2 t0 = caddf(zz[0], zz[2]), t1 = csubf(zz[0], zz[2]);
        float2 t2 = caddf(zz[1], zz[3]);
        float2 bd = csubf(zz[1], zz[3]);
        float2 t3 = make_float2(-bd.y, bd.x);
        Z[ZI(i0)]     = caddf(t0, t2);
        Z[ZI(i0 + 1)] = caddf(t1, t3);
        Z[ZI(i0 + 2)] = csubf(t0, t2);
        Z[ZI(i0 + 3)] = csubf(t1, t3);
    }
    __syncthreads();
}

// Inverse DIT paired radix-16 pass: stage (len=L1) then (len=4*L1).
template<int L1, int TW1>
__device__ void ifft_dit_pass16(float2* Z, const float* C, int tid) {
    constexpr int q1 = L1 / 4, L2 = 4 * L1;
    constexpr int TW2 = TW1 - 2;
    const int p = tid & (q1 - 1);
    const int k1 = p << TW1;
    const float2 u1 = twc(C, k1);
    const float2 u2 = cmulf(u1, u1);
    const float2 u3 = cmulf(u2, u1);
    float2 v1[4], v2[4], v3[4];
    #pragma unroll
    for (int a = 0; a < 4; a++) {
        const int kk = (p + a*q1) << TW2;
        v1[a] = twc(C, kk);
        v2[a] = cmulf(v1[a], v1[a]);
        v3[a] = cmulf(v2[a], v1[a]);
    }
    #pragma unroll
    for (int half = 0; half < 2; half++) {
        const int g = tid + half * FFT_T;
        const int base = (g / q1) * L2 + p;
        float2 x[4][4];
        #pragma unroll
        for (int b = 0; b < 4; b++)
            #pragma unroll
            for (int a = 0; a < 4; a++)
                x[b][a] = Z[ZI(base + a*q1 + b*L1)];
        #pragma unroll
        for (int b = 0; b < 4; b++) {
            float2 a0 = x[b][0];
            float2 a1 = cmulconjf(x[b][1], u1);
            float2 a2 = cmulconjf(x[b][2], u2);
            float2 a3 = cmulconjf(x[b][3], u3);
            float2 t0 = caddf(a0, a2), t1 = csubf(a0, a2);
            float2 t2 = caddf(a1, a3);
            float2 bd = csubf(a1, a3);
            float2 t3 = make_float2(-bd.y, bd.x);
            x[b][0] = caddf(t0, t2);
            x[b][1] = caddf(t1, t3);
            x[b][2] = csubf(t0, t2);
            x[b][3] = csubf(t1, t3);
        }
        #pragma unroll
        for (int a = 0; a < 4; a++) {
            float2 b0 = x[0][a];
            float2 b1 = cmulconjf(x[1][a], v1[a]);
            float2 b2 = cmulconjf(x[2][a], v2[a]);
            float2 b3 = cmulconjf(x[3][a], v3[a]);
            float2 t0 = caddf(b0, b2), t1 = csubf(b0, b2);
            float2 t2 = caddf(b1, b3);
            float2 bd = csubf(b1, b3);
            float2 t3 = make_float2(-bd.y, bd.x);
            Z[ZI(base + a*q1 + 0*L1)] = caddf(t0, t2);
            Z[ZI(base + a*q1 + 1*L1)] = caddf(t1, t3);
            Z[ZI(base + a*q1 + 2*L1)] = csubf(t0, t2);
            Z[ZI(base + a*q1 + 3*L1)] = csubf(t1, t3);
        }
    }
    __syncthreads();
}

__global__ __launch_bounds__(FFT_T, 1) void fft_conv_kernel(
    const float* __restrict__ sw, const float* __restrict__ sb)
{
    extern __shared__ float2 sm[];
    float2* Z  = sm;
    float2* Hs = sm + Z_PAD_SZ;
    float*  C  = (float*)(sm + Z_PAD_SZ + HS_PAD_SZ);
    const int c   = blockIdx.x;
    const int tid = threadIdx.x;

    for (int k = tid; k <= 4096; k += FFT_T)
        C[k] = cosf(3.834951969714103e-4f * (float)k);   // cos(2*pi*k/16384)
    __syncthreads();

    // ---- filter FFT; stash Hermitian half-spectrum (natural order) in smem --
    fft_dif_first(Z, C, g_COEFt + (size_t)c * LSEQ, tid);
    fft_dif_pass16<4096, 2>(Z, C, tid);
    fft_dif_pass16<256, 6>(Z, C, tid);
    fft_dif_pass16<16, 10>(Z, C, tid);
    for (int j = tid; j < NFFT; j += FFT_T) {
        const int k = digrev4_14(j);
        if (k <= 8192) Hs[HsI(k)] = Z[ZI(j)];
    }
    __syncthreads();

    // ---- v FFT with fused depthwise short-conv ----
    const float w0 = sw[c*3], w1 = sw[c*3+1], w2 = sw[c*3+2], cb = sb[c];
    fft_dif_first_conv(Z, C, g_Vcm + (size_t)c * MTOT, w0, w1, w2, cb, tid);
    fft_dif_pass16<4096, 2>(Z, C, tid);
    fft_dif_pass16<256, 6>(Z, C, tid);
    fft_dif_pass16<16, 10>(Z, C, tid);

    // ---- inverse: multiply (from smem half-spectrum) fused into len-4 stage
    ifft_first_mult(Z, Hs, tid);
    ifft_dit_pass16<16, 10>(Z, C, tid);
    ifft_dit_pass16<256, 6>(Z, C, tid);

    // ---- final paired pass fused with gate + bf16 hi/lo store ([c][m]) ----
    const float* x2 = g_X2t + (size_t)c * MTOT;
    __nv_bfloat16* goh = g_Gh + (size_t)c * MTOT;
    __nv_bfloat16* gol = g_Gl + (size_t)c * MTOT;
    const float scale = 1.0f / (float)NFFT;
    for (int p = tid; p < 1024; p += FFT_T) {
        float2 x[4][4];
        #pragma unroll
        for (int b = 0; b < 4; b++)
            #pragma unroll
            for (int a = 0; a < 4; a++)
                x[b][a] = Z[ZI(p + a*1024 + b*4096)];
        const float2 u1 = twc(C, p << 2);
        const float2 u2 = cmulf(u1, u1);
        const float2 u3 = cmulf(u2, u1);
        #pragma unroll
        for (int b = 0; b < 4; b++) {
            float2 a0 = x[b][0];
            float2 a1 = cmulconjf(x[b][1], u1);
            float2 a2 = cmulconjf(x[b][2], u2);
            float2 a3 = cmulconjf(x[b][3], u3);
            float2 t0 = caddf(a0, a2), t1 = csubf(a0, a2);
            float2 t2 = caddf(a1, a3);
            float2 bd = csubf(a1, a3);
            float2 t3 = make_float2(-bd.y, bd.x);
            x[b][0] = caddf(t0, t2);
            x[b][1] = caddf(t1, t3);
            x[b][2] = csubf(t0, t2);
            x[b][3] = csubf(t1, t3);
        }
        #pragma unroll
        for (int a = 0; a < 4; a++) {
            const int k2 = p + a*1024;
            const float2 q1 = twc(C, k2);
            const float2 q2 = cmulf(q1, q1);
            const float2 q3 = cmulf(q2, q1);
            float2 b0 = x[0][a];
            float2 b1 = cmulconjf(x[1][a], q1);
            float2 b2 = cmulconjf(x[2][a], q2);
            float2 b3 = cmulconjf(x[3][a], q3);
            float2 t0 = caddf(b0, b2), t1 = csubf(b0, b2);
            float2 t2 = caddf(b1, b3);
            float2 bd = csubf(b1, b3);
            float2 t3 = make_float2(-bd.y, bd.x);
            float2 o0 = caddf(t0, t2);         // time t      (re=b0, im=b1)
            float2 o1 = caddf(t1, t3);         // time t+4096
            const int t = p + a*1024;
            float gv;
            __nv_bfloat16 hh, ll;
            gv = x2[t]               * (o0.x * scale); bf16_split(gv, hh, ll);
            goh[t] = hh;               gol[t] = ll;
            gv = x2[LSEQ + t]        * (o0.y * scale); bf16_split(gv, hh, ll);
            goh[LSEQ + t] = hh;        gol[LSEQ + t] = ll;
            gv = x2[t + 4096]        * (o1.x * scale); bf16_split(gv, hh, ll);
            goh[t + 4096] = hh;        gol[t + 4096] = ll;
            gv = x2[LSEQ + t + 4096] * (o1.y * scale); bf16_split(gv, hh, ll);
            goh[LSEQ + t + 4096] = hh; gol[LSEQ + t + 4096] = ll;
        }
    }
}

// ============================================================================
extern "C" void kernel_launch(void* const* d_in, const int* in_sizes, int n_in,
                              void* d_out, int out_size)
{
    const float* x   = (const float*)d_in[0];
    const float* ipw = (const float*)d_in[1];
    const float* ipb = (const float*)d_in[2];
    const float* sw  = (const float*)d_in[3];
    const float* sb  = (const float*)d_in[4];
    const float* fw1 = (const float*)d_in[5];
    const float* fb1 = (const float*)d_in[6];
    const float* fw2 = (const float*)d_in[7];
    const float* fb2 = (const float*)d_in[8];
    const float* fw3 = (const float*)d_in[9];
    const float* fb3 = (const float*)d_in[10];
    const float* ow  = (const float*)d_in[11];
    const float* ob  = (const float*)d_in[12];
    float* out = (float*)d_out;

    cudaFuncSetAttribute(fft_conv_kernel,
                         cudaFuncAttributeMaxDynamicSharedMemorySize, FFT_SMEM);
    cudaFuncSetAttribute(gemm_bf16_tc<0>,
                         cudaFuncAttributeMaxDynamicSharedMemorySize, GSM_BYTES);
    cudaFuncSetAttribute(gemm_bf16_tc<1>,
                         cudaFuncAttributeMaxDynamicSharedMemorySize, GSM_BYTES);

    // 1) split x and weights into bf16 hi/lo (coalesced gathers)
    convert_x_split<<<MTOT*CH/4/256, 256>>>(x);
    convert_wip_split<<<dim3(32, 32), 256>>>(ipw);
    convert_wout_split<<<dim3(32, 32), dim3(32, 32)>>>(ow);
    // 2) in_proj GEMM; epilogue writes v/x2 directly in channel-major
    gemm_bf16_tc<0><<<dim3(16, 128), 256, GSM_BYTES>>>(ipb, nullptr);
    // 3) filter MLP hidden + coef GEMM + transpose
    filter_h2<<<LSEQ, 128>>>(fw1, fb1, fw2, fb2);
    gemm_coef<<<dim3(8, 64), 256>>>(fw3, fb3);
    transpose_coef<<<dim3(32, 256), dim3(32, 32)>>>();
    // 4) FFT long conv (smem half-spectrum; fused short-conv, mult, gate,
    //    bf16 split output in [c][m])
    fft_conv_kernel<<<CH, FFT_T, FFT_SMEM>>>(sw, sb);
    // 5) out GEMM reads gated activations k-major via ldmatrix.trans
    gemm_bf16_tc<1><<<dim3(8, 128), 256, GSM_BYTES>>>(ob, out);
}

// round 11
// speedup vs baseline: 3.3771x; 1.0194x over previous
#include <cuda_runtime.h>
#include <cuda_bf16.h>
#include <math.h>
#include <stdint.h>

// Problem constants
#define LSEQ   8192
#define NFFT   16384
#define CH     1024
#define BATCH  2
#define MTOT   (BATCH*LSEQ)      // 16384 rows

// ---------------- scratch (device globals; no allocations allowed) ----------
__device__ float g_Vcm  [CH*MTOT];     // in_proj v branch, channel-major [c][m]
__device__ float g_X2t  [CH*MTOT];     // x2 branch, channel-major [c][m]
__device__ float g_H2   [LSEQ*128];    // filter MLP hidden (L x 128)
__device__ float g_COEFt[CH*LSEQ];     // filter coefs order-1, channel-major [c][l]

// bf16 split operands for the tensor-core GEMMs
__device__ __nv_bfloat16 g_Xh [MTOT*CH], g_Xl [MTOT*CH];     // x, [m][k]
__device__ __nv_bfloat16 g_Gh [CH*MTOT], g_Gl [CH*MTOT];     // gated, [c][m] (k-major)
__device__ __nv_bfloat16 g_Wih[2048*CH], g_Wil[2048*CH];     // in_proj cols, [n][k]
__device__ __nv_bfloat16 g_Woh[CH*CH],   g_Wol[CH*CH];       // out_w^T, [n][k]

// ---------------- generic helpers -------------------------------------------
__device__ __forceinline__ float gelu_exact(float x) {
    return 0.5f * x * (1.0f + erff(x * 0.70710678118654752f));
}
__device__ __forceinline__ float2 cmulf(float2 a, float2 b) {
    return make_float2(a.x*b.x - a.y*b.y, a.x*b.y + a.y*b.x);
}
__device__ __forceinline__ float2 cmulconjf(float2 a, float2 w) {  // a * conj(w)
    return make_float2(a.x*w.x + a.y*w.y, a.y*w.x - a.x*w.y);
}
__device__ __forceinline__ float2 caddf(float2 a, float2 b) {
    return make_float2(a.x + b.x, a.y + b.y);
}
__device__ __forceinline__ float2 csubf(float2 a, float2 b) {
    return make_float2(a.x - b.x, a.y - b.y);
}
__device__ __forceinline__ void bf16_split(float v, __nv_bfloat16 &h, __nv_bfloat16 &l) {
    h = __float2bfloat16(v);
    l = __float2bfloat16(v - __bfloat162float(h));
}
__device__ __forceinline__ uint32_t smem_u32(const void* p) {
    uint32_t a;
    asm("{ .reg .u64 t; cvta.to.shared.u64 t, %1; cvt.u32.u64 %0, t; }"
        : "=r"(a) : "l"(p));
    return a;
}

#define CP_ASYNC16(sm, gp) \
    asm volatile("cp.async.cg.shared.global [%0], [%1], 16;" \
                 :: "r"(sm), "l"(__cvta_generic_to_global(gp)) : "memory")
#define CP_COMMIT() asm volatile("cp.async.commit_group;" ::: "memory")
#define CP_WAIT0()  asm volatile("cp.async.wait_group 0;" ::: "memory")

#define LDSM4(r0, r1, r2, r3, ad) \
    asm volatile("ldmatrix.sync.aligned.m8n8.x4.shared.b16 {%0,%1,%2,%3}, [%4];" \
                 : "=r"(r0), "=r"(r1), "=r"(r2), "=r"(r3) : "r"(ad))
#define LDSM4T(r0, r1, r2, r3, ad) \
    asm volatile("ldmatrix.sync.aligned.m8n8.x4.trans.shared.b16 {%0,%1,%2,%3}, [%4];" \
                 : "=r"(r0), "=r"(r1), "=r"(r2), "=r"(r3) : "r"(ad))

__device__ __forceinline__ void mma_bf16(float* c, const uint32_t* a, const uint32_t* b) {
    asm volatile("mma.sync.aligned.m16n8k16.row.col.f32.bf16.bf16.f32 "
        "{%0,%1,%2,%3}, {%4,%5,%6,%7}, {%8,%9}, {%0,%1,%2,%3};"
        : "+f"(c[0]), "+f"(c[1]), "+f"(c[2]), "+f"(c[3])
        : "r"(a[0]), "r"(a[1]), "r"(a[2]), "r"(a[3]), "r"(b[0]), "r"(b[1]));
}

// ============================================================================
// convert/split kernels
// ============================================================================
__global__ __launch_bounds__(256) void convert_x_split(const float* __restrict__ x) {
    size_t i = ((size_t)blockIdx.x * 256 + threadIdx.x) * 4;
    float4 v = *(const float4*)&x[i];
    __nv_bfloat16 h[4], l[4];
    bf16_split(v.x, h[0], l[0]); bf16_split(v.y, h[1], l[1]);
    bf16_split(v.z, h[2], l[2]); bf16_split(v.w, h[3], l[3]);
    *(__nv_bfloat162*)&g_Xh[i]   = __nv_bfloat162(h[0], h[1]);
    *(__nv_bfloat162*)&g_Xh[i+2] = __nv_bfloat162(h[2], h[3]);
    *(__nv_bfloat162*)&g_Xl[i]   = __nv_bfloat162(l[0], l[1]);
    *(__nv_bfloat162*)&g_Xl[i+2] = __nv_bfloat162(l[2], l[3]);
}

// in_proj weight gather, COALESCED: tile [32 k][96 j] through smem.
__global__ __launch_bounds__(256) void convert_wip_split(const float* __restrict__ ipw) {
    __shared__ float s[32][97];
    const int c0 = blockIdx.x * 32;
    const int k0 = blockIdx.y * 32;
    const int tid = threadIdx.x;
    for (int idx = tid; idx < 32*96; idx += 256) {
        const int r = idx / 96, cc = idx % 96;
        s[r][cc] = ipw[(size_t)(k0 + r) * 3072 + 3*c0 + cc];
    }
    __syncthreads();
    const int dc = tid >> 3;
    const int kq = (tid & 7) * 4;
    const int c  = c0 + dc;
    __nv_bfloat16 vh[4], vl[4], xh[4], xl[4];
    #pragma unroll
    for (int u = 0; u < 4; u++) {
        bf16_split(s[kq+u][3*dc],     vh[u], vl[u]);
        bf16_split(s[kq+u][3*dc + 2], xh[u], xl[u]);
    }
    const size_t ov = (size_t)c * 1024 + k0 + kq;
    const size_t ox = (size_t)(1024 + c) * 1024 + k0 + kq;
    *(__nv_bfloat162*)&g_Wih[ov]   = __nv_bfloat162(vh[0], vh[1]);
    *(__nv_bfloat162*)&g_Wih[ov+2] = __nv_bfloat162(vh[2], vh[3]);
    *(__nv_bfloat162*)&g_Wil[ov]   = __nv_bfloat162(vl[0], vl[1]);
    *(__nv_bfloat162*)&g_Wil[ov+2] = __nv_bfloat162(vl[2], vl[3]);
    *(__nv_bfloat162*)&g_Wih[ox]   = __nv_bfloat162(xh[0], xh[1]);
    *(__nv_bfloat162*)&g_Wih[ox+2] = __nv_bfloat162(xh[2], xh[3]);
    *(__nv_bfloat162*)&g_Wil[ox]   = __nv_bfloat162(xl[0], xl[1]);
    *(__nv_bfloat162*)&g_Wil[ox+2] = __nv_bfloat162(xl[2], xl[3]);
}

// out_w [k][n] -> g_Woh/g_Wol [n][k], coalesced tiled transpose + split
__global__ void convert_wout_split(const float* __restrict__ ow) {
    __shared__ float s[32][33];
    const int c0 = blockIdx.x * 32, k0 = blockIdx.y * 32;
    const int tx = threadIdx.x, ty = threadIdx.y;
    s[ty][tx] = ow[(size_t)(k0 + ty) * CH + c0 + tx];
    __syncthreads();
    __nv_bfloat16 h, l;
    bf16_split(s[tx][ty], h, l);
    g_Woh[(size_t)(c0 + ty) * 1024 + k0 + tx] = h;
    g_Wol[(size_t)(c0 + ty) * 1024 + k0 + tx] = l;
}

// ============================================================================
// bf16 mma.sync GEMM (single 64KB buffer, KC=64, 2 syncs).  Frozen mainloop.
// MODE 0: in_proj. A = g_Xh/l [m][k]. Epilogue transposes -> g_Vcm/g_X2t.
// MODE 1: out proj. A = g_Gh/l [k][m], ldmatrix.trans. Epilogue -> out.
// ============================================================================
#define GSM_BYTES 65536

template<int MODE>
__global__ __launch_bounds__(256, 2) void gemm_bf16_tc(
    const float* __restrict__ bias, float* __restrict__ out)
{
    extern __shared__ char dsm[];
    const uint32_t sb  = smem_u32(dsm);
    const uint32_t sAh = sb, sBh = sb + 32768;

    const int tid  = threadIdx.x;
    const int lane = tid & 31;
    const int wid  = tid >> 5;
    const int wm   = wid >> 1;
    const int wn   = wid & 1;
    const int m0   = blockIdx.y * 128;
    const int bx   = blockIdx.x;
    const int n0   = bx * 128;

    const __nv_bfloat16* Ah = (MODE == 0) ? g_Xh : g_Gh;
    const __nv_bfloat16* Al = (MODE == 0) ? g_Xl : g_Gl;
    const __nv_bfloat16* Bh = (MODE == 0) ? g_Wih : g_Woh;
    const __nv_bfloat16* Bl = (MODE == 0) ? g_Wil : g_Wol;

    float acc[2][8][4];
    #pragma unroll
    for (int i = 0; i < 2; i++)
        #pragma unroll
        for (int j = 0; j < 8; j++)
            #pragma unroll
            for (int q = 0; q < 4; q++) acc[i][j][q] = 0.f;

    for (int it = 0; it < 16; ++it) {
        const size_t kc0 = (size_t)it * 64;
        if (MODE == 0) {
            #pragma unroll
            for (int u = 0; u < 4; u++) {
                const int s = tid + u * 256;
                const int row = s >> 3, seg = s & 7;
                const uint32_t so = (uint32_t)(row * 128 + ((seg * 16) ^ ((row & 7) << 4)));
                const size_t ga = (size_t)(m0 + row) * 1024 + kc0 + seg * 8;
                const size_t gb = (size_t)(n0 + row) * 1024 + kc0 + seg * 8;
                CP_ASYNC16(sAh + so, Ah + ga);
                CP_ASYNC16(sAh + 16384 + so, Al + ga);
                CP_ASYNC16(sBh + so, Bh + gb);
                CP_ASYNC16(sBh + 16384 + so, Bl + gb);
            }
        } else {
            #pragma unroll
            for (int u = 0; u < 4; u++) {
                const int s = tid + u * 256;
                const int row = s >> 4, seg = s & 15;
                const uint32_t so = (uint32_t)(row * 256 + ((seg * 16) ^ ((row & 7) << 4)));
                const size_t ga = (size_t)(kc0 + row) * MTOT + m0 + seg * 8;
                CP_ASYNC16(sAh + so, Ah + ga);
                CP_ASYNC16(sAh + 16384 + so, Al + ga);
            }
            #pragma unroll
            for (int u = 0; u < 4; u++) {
                const int s = tid + u * 256;
                const int row = s >> 3, seg = s & 7;
                const uint32_t so = (uint32_t)(row * 128 + ((seg * 16) ^ ((row & 7) << 4)));
                const size_t gb = (size_t)(n0 + row) * 1024 + kc0 + seg * 8;
                CP_ASYNC16(sBh + so, Bh + gb);
                CP_ASYNC16(sBh + 16384 + so, Bl + gb);
            }
        }
        CP_COMMIT();
        CP_WAIT0();
        __syncthreads();

        #pragma unroll
        for (int ks = 0; ks < 4; ks++) {
            uint32_t ah[2][4], al[2][4];
            #pragma unroll
            for (int mt = 0; mt < 2; mt++) {
                if (MODE == 0) {
                    const int row = wm * 32 + mt * 16 + (lane & 15);
                    const uint32_t r4 = (row & 7) << 4;
                    const uint32_t cb = (uint32_t)(ks * 32 + ((lane >> 4) << 4));
                    const uint32_t ad = sAh + row * 128 + (cb ^ r4);
                    LDSM4(ah[mt][0], ah[mt][1], ah[mt][2], ah[mt][3], ad);
                    LDSM4(al[mt][0], al[mt][1], al[mt][2], al[mt][3], ad + 16384);
                } else {
                    const int rowk = ks * 16 + (lane & 7) + ((lane >> 4) << 3);
                    const int mcol = wm * 32 + mt * 16 + (((lane >> 3) & 1) << 3);
                    const uint32_t ad = sAh + rowk * 256 +
                        (((uint32_t)(2 * mcol)) ^ ((uint32_t)(rowk & 7) << 4));
                    LDSM4T(ah[mt][0], ah[mt][1], ah[mt][2], ah[mt][3], ad);
                    LDSM4T(al[mt][0], al[mt][1], al[mt][2], al[mt][3], ad + 16384);
                }
            }
            uint32_t bh[8][2], bl[8][2];
            #pragma unroll
            for (int nt2 = 0; nt2 < 4; nt2++) {
                const int n = wn * 64 + nt2 * 16 + (lane & 7) + ((lane >> 4) << 3);
                const uint32_t r4 = (n & 7) << 4;
                const uint32_t cb = (uint32_t)(ks * 32 + (((lane >> 3) & 1) << 4));
                const uint32_t ad = sBh + n * 128 + (cb ^ r4);
                LDSM4(bh[2*nt2][0], bh[2*nt2][1], bh[2*nt2+1][0], bh[2*nt2+1][1], ad);
                LDSM4(bl[2*nt2][0], bl[2*nt2][1], bl[2*nt2+1][0], bl[2*nt2+1][1], ad + 16384);
            }
            #pragma unroll
            for (int mt = 0; mt < 2; mt++)
                #pragma unroll
                for (int nt = 0; nt < 8; nt++) {
                    mma_bf16(acc[mt][nt], ah[mt], bh[nt]);
                    mma_bf16(acc[mt][nt], ah[mt], bl[nt]);
                    mma_bf16(acc[mt][nt], al[mt], bh[nt]);
                }
        }
        __syncthreads();
    }

    if (MODE == 0) {
        float* stage = (float*)dsm;          // [128][65] floats = 33 KB
        const bool is_v = (bx < 8);
        const int cbase = (is_v ? bx : bx - 8) * 128;
        #pragma unroll
        for (int h = 0; h < 2; h++) {
            __syncthreads();
            if (wn == h) {
                #pragma unroll
                for (int mt = 0; mt < 2; mt++) {
                    const int rl = wm * 32 + mt * 16 + (lane >> 2);
                    #pragma unroll
                    for (int nt = 0; nt < 8; nt++) {
                        const int cl = nt * 8 + ((lane & 3) << 1);
                        stage[rl * 65 + cl]           = acc[mt][nt][0];
                        stage[rl * 65 + cl + 1]       = acc[mt][nt][1];
                        stage[(rl + 8) * 65 + cl]     = acc[mt][nt][2];
                        stage[(rl + 8) * 65 + cl + 1] = acc[mt][nt][3];
                    }
                }
            }
            __syncthreads();
            const int cl  = tid >> 2;
            const int mch = (tid & 3) << 5;
            const int c   = cbase + h * 64 + cl;
            const float b = is_v ? bias[3*c] : bias[3*c + 2];
            float* dst = (is_v ? g_Vcm : g_X2t) + (size_t)c * MTOT + m0 + mch;
            #pragma unroll
            for (int j = 0; j < 32; j += 4) {
                float4 o = make_float4(stage[(mch+j)*65   + cl] + b,
                                       stage[(mch+j+1)*65 + cl] + b,
                                       stage[(mch+j+2)*65 + cl] + b,
                                       stage[(mch+j+3)*65 + cl] + b);
                *(float4*)&dst[j] = o;
            }
        }
    } else {
        #pragma unroll
        for (int mt = 0; mt < 2; mt++) {
            const int r = m0 + wm * 32 + mt * 16 + (lane >> 2);
            #pragma unroll
            for (int nt = 0; nt < 8; nt++) {
                const int c = n0 + wn * 64 + nt * 8 + ((lane & 3) << 1);
                const float b0 = bias[c], b1 = bias[c + 1];
                *(float2*)&out[(size_t)r * CH + c] =
                    make_float2(acc[mt][nt][0] + b0, acc[mt][nt][1] + b1);
                *(float2*)&out[(size_t)(r + 8) * CH + c] =
                    make_float2(acc[mt][nt][2] + b0, acc[mt][nt][3] + b1);
            }
        }
    }
}

// ============================================================================
// Filter MLP (unchanged)
// ============================================================================
__global__ void filter_h2(const float* __restrict__ fw1, const float* __restrict__ fb1,
                          const float* __restrict__ fw2, const float* __restrict__ fb2)
{
    __shared__ float h1[64];
    const int l = blockIdx.x;
    const int t = threadIdx.x;
    const float pos = (float)l / (float)(LSEQ - 1);
    if (t < 64) h1[t] = gelu_exact(pos * fw1[t] + fb1[t]);
    __syncthreads();
    float s = fb2[t];
    #pragma unroll 8
    for (int j = 0; j < 64; j++) s += h1[j] * fw2[j*128 + t];
    g_H2[(size_t)l*128 + t] = gelu_exact(s);
}

// ============================================================================
// GEMM coef: COEFt[c][l] = (h2 @ fw3[:,2c+1] + fb3[2c+1]) TRANSPOSED epilogue
// ============================================================================
__global__ __launch_bounds__(256) void gemm_coef(
    const float* __restrict__ fw3, const float* __restrict__ fb3)
{
    __shared__ float As[8][128];
    __shared__ float Bs[8][128];
    __shared__ float stage[128 * 65];     // 33 KB transpose stage
    const int tid = threadIdx.x;
    const int tx = tid & 15, ty = tid >> 4;
    const int m0 = blockIdx.y * 128;
    const int n0 = blockIdx.x * 128;

    float acc[8][8];
    #pragma unroll
    for (int i = 0; i < 8; i++)
        #pragma unroll
        for (int j = 0; j < 8; j++) acc[i][j] = 0.f;

    const int arow = tid >> 1, akq = (tid & 1) * 4;
    const int bn = tid & 127;
    const int jm = 2 * (n0 + bn) + 1;
    const int kk0 = (tid >> 7) * 4;

    for (int k0 = 0; k0 < 128; k0 += 8) {
        float4 av = *(const float4*)&g_H2[(size_t)(m0 + arow) * 128 + k0 + akq];
        As[akq+0][arow] = av.x; As[akq+1][arow] = av.y;
        As[akq+2][arow] = av.z; As[akq+3][arow] = av.w;
        #pragma unroll
        for (int r = 0; r < 4; r++)
            Bs[kk0 + r][bn] = fw3[(size_t)(k0 + kk0 + r) * 2048 + jm];
        __syncthreads();
        #pragma unroll
        for (int kk = 0; kk < 8; kk++) {
            float a[8], b[8];
            #pragma unroll
            for (int i = 0; i < 8; i++) a[i] = As[kk][ty*8 + i];
            #pragma unroll
            for (int j = 0; j < 8; j++) b[j] = Bs[kk][tx*8 + j];
            #pragma unroll
            for (int i = 0; i < 8; i++)
                #pragma unroll
                for (int j = 0; j < 8; j++) acc[i][j] += a[i] * b[j];
        }
        __syncthreads();
    }

    float bo[8];
    #pragma unroll
    for (int j = 0; j < 8; j++) bo[j] = fb3[2*(n0 + tx*8 + j) + 1];

    // transposed epilogue: stage 128l x 64c half-tiles, write [c][l] coalesced
    #pragma unroll
    for (int h = 0; h < 2; h++) {
        __syncthreads();
        if ((tx >> 3) == h) {
            #pragma unroll
            for (int i = 0; i < 8; i++)
                #pragma unroll
                for (int j = 0; j < 8; j++)
                    stage[(ty*8 + i) * 65 + (tx & 7) * 8 + j] = acc[i][j] + bo[j];
        }
        __syncthreads();
        const int cl  = tid >> 2;            // 0..63
        const int lch = (tid & 3) << 5;      // 0,32,64,96
        const int c   = n0 + h * 64 + cl;
        float* dst = g_COEFt + (size_t)c * LSEQ + m0 + lch;
        #pragma unroll
        for (int j = 0; j < 32; j += 4) {
            float4 o = make_float4(stage[(lch+j)*65   + cl],
                                   stage[(lch+j+1)*65 + cl],
                                   stage[(lch+j+2)*65 + cl],
                                   stage[(lch+j+3)*65 + cl]);
            *(float4*)&dst[j] = o;
        }
    }
}

// ============================================================================
// FFT convolution — radix-16 passes, padded smem, smem Hermitian half-
// spectrum; filter stash fused into the filter FFT's final pass.
// ============================================================================
#define FFT_T    512
#define ZI(i) ((i) + ((i) >> 4))
#define Z_PAD_SZ  17408                 // float2
#define HS_PAD_SZ 8232                  // float2
#define COS_SZ    4104                  // floats
#define HsI(k) ((k) + ((k) >> 8))
#define FFT_SMEM ((Z_PAD_SZ + HS_PAD_SZ) * 8 + COS_SZ * 4)

// base-4 digit reversal of a 14-bit index (7 digits)
__device__ __forceinline__ int digrev4_14(int j) {
    unsigned r = __brev((unsigned)j) >> 18;
    return (int)(((r & 0x2AAAu) >> 1) | ((r & 0x1555u) << 1));
}
// base-4 digit reversal of a 10-bit index (5 digits)
__device__ __forceinline__ int digrev4_10(int g) {
    unsigned r = __brev((unsigned)g) >> 22;
    return (int)(((r & 0x155u) << 1) | ((r >> 1) & 0x155u));
}

// W(k) = e^{-2pi i k/N} for k in [0,4096]: cos-only quarter table
__device__ __forceinline__ float2 twc(const float* __restrict__ C, int k) {
    return make_float2(C[k], -C[4096 - k]);
}

__device__ __forceinline__ float conv3(const float* __restrict__ q, int l,
                                       float w0, float w1, float w2, float b) {
    float s = w1 * q[l] + b;
    if (l > 0)        s += w0 * q[l-1];
    if (l < LSEQ - 1) s += w2 * q[l+1];
    return s;
}

// Fused: zero-padded load + first forward-DIF stage (len 16384, radix-4)
__device__ void fft_dif_first(float2* Z, const float* C,
                              const float* __restrict__ re, int tid) {
    for (int p = tid; p < 4096; p += FFT_T) {
        float2 a = make_float2(re[p], 0.f);
        float2 b = make_float2(re[p + 4096], 0.f);
        float2 w1 = twc(C, p);
        float2 w2 = cmulf(w1, w1);
        float2 w3 = cmulf(w2, w1);
        Z[ZI(p)]         = caddf(a, b);
        Z[ZI(p + 4096)]  = cmulf(make_float2(a.x + b.y, a.y - b.x), w1);
        Z[ZI(p + 8192)]  = cmulf(csubf(a, b),                       w2);
        Z[ZI(p + 12288)] = cmulf(make_float2(a.x - b.y, a.y + b.x), w3);
    }
    __syncthreads();
}

// Fused: short-conv + packed load (b0 in re, b1 in im) + first DIF stage
__device__ void fft_dif_first_conv(float2* Z, const float* C,
                                   const float* __restrict__ v0,
                                   float w0, float w1, float w2, float cb, int tid) {
    const float* v1 = v0 + LSEQ;
    for (int p = tid; p < 4096; p += FFT_T) {
        float2 a = make_float2(conv3(v0, p, w0, w1, w2, cb),
                               conv3(v1, p, w0, w1, w2, cb));
        float2 b = make_float2(conv3(v0, p + 4096, w0, w1, w2, cb),
                               conv3(v1, p + 4096, w0, w1, w2, cb));
        float2 t1 = twc(C, p);
        float2 t2 = cmulf(t1, t1);
        float2 t3 = cmulf(t2, t1);
        Z[ZI(p)]         = caddf(a, b);
        Z[ZI(p + 4096)]  = cmulf(make_float2(a.x + b.y, a.y - b.x), t1);
        Z[ZI(p + 8192)]  = cmulf(csubf(a, b),                       t2);
        Z[ZI(p + 12288)] = cmulf(make_float2(a.x - b.y, a.y + b.x), t3);
    }
    __syncthreads();
}

// Forward DIF paired radix-16 pass: stage (len=LA) then (len=LA/4).
template<int LA, int TWA>
__device__ void fft_dif_pass16(float2* Z, const float* C, int tid) {
    constexpr int qA = LA / 4, qB = LA / 16;
    constexpr int TWB = TWA + 2;
    const int p2 = tid & (qB - 1);
    float2 wA1[4], wA2[4], wA3[4];
    #pragma unroll
    for (int a = 0; a < 4; a++) {
        const int k = (p2 + a*qB) << TWA;
        wA1[a] = twc(C, k);
        wA2[a] = cmulf(wA1[a], wA1[a]);
        wA3[a] = cmulf(wA2[a], wA1[a]);
    }
    const int k2 = p2 << TWB;
    const float2 wB1 = twc(C, k2);
    const float2 wB2 = cmulf(wB1, wB1);
    const float2 wB3 = cmulf(wB2, wB1);
    #pragma unroll
    for (int half = 0; half < 2; half++) {
        const int g = tid + half * FFT_T;
        const int base = (g / qB) * LA + p2;
        float2 x[4][4];
        #pragma unroll
        for (int b = 0; b < 4; b++)
            #pragma unroll
            for (int a = 0; a < 4; a++)
                x[b][a] = Z[ZI(base + a*qB + b*qA)];
        #pragma unroll
        for (int a = 0; a < 4; a++) {
            float2 t0 = caddf(x[0][a], x[2][a]);
            float2 t1 = csubf(x[0][a], x[2][a]);
            float2 t2 = caddf(x[1][a], x[3][a]);
            float2 bd = csubf(x[1][a], x[3][a]);
            float2 t3 = make_float2(bd.y, -bd.x);
            x[0][a] = caddf(t0, t2);
            x[1][a] = cmulf(caddf(t1, t3), wA1[a]);
            x[2][a] = cmulf(csubf(t0, t2), wA2[a]);
            x[3][a] = cmulf(csubf(t1, t3), wA3[a]);
        }
        #pragma unroll
        for (int b = 0; b < 4; b++) {
            float2 t0 = caddf(x[b][0], x[b][2]);
            float2 t1 = csubf(x[b][0], x[b][2]);
            float2 t2 = caddf(x[b][1], x[b][3]);
            float2 bd = csubf(x[b][1], x[b][3]);
            float2 t3 = make_float2(bd.y, -bd.x);
            Z[ZI(base + 0*qB + b*qA)] = caddf(t0, t2);
            Z[ZI(base + 1*qB + b*qA)] = cmulf(caddf(t1, t3), wB1);
            Z[ZI(base + 2*qB + b*qA)] = cmulf(csubf(t0, t2), wB2);
            Z[ZI(base + 3*qB + b*qA)] = cmulf(csubf(t1, t3), wB3);
        }
    }
    __syncthreads();
}

// Final FILTER pass (LA=16, qB=1, stage-B twiddles = 1) with the Hermitian
// half-spectrum stash fused: outputs go straight to Hs at natural-order k,
// Z is not written (the filter transform is not needed afterwards).
// j = 16g + o + 4b  ->  k = digrev5(g) + b*1024 + o*4096.
__device__ void fft_dif_pass16_stash(float2* Z, const float* C,
                                     float2* __restrict__ Hs, int tid) {
    float2 wA1[4], wA2[4], wA3[4];
    #pragma unroll
    for (int a = 0; a < 4; a++) {
        const int k = a << 10;
        wA1[a] = twc(C, k);
        wA2[a] = cmulf(wA1[a], wA1[a]);
        wA3[a] = cmulf(wA2[a], wA1[a]);
    }
    #pragma unroll
    for (int half = 0; half < 2; half++) {
        const int g = tid + half * FFT_T;
        const int base = g * 16;
        const int kg = digrev4_10(g);
        float2 x[4][4];
        #pragma unroll
        for (int b = 0; b < 4; b++)
            #pragma unroll
            for (int a = 0; a < 4; a++)
                x[b][a] = Z[ZI(base + a + 4*b)];
        #pragma unroll
        for (int a = 0; a < 4; a++) {
            float2 t0 = caddf(x[0][a], x[2][a]);
            float2 t1 = csubf(x[0][a], x[2][a]);
            float2 t2 = caddf(x[1][a], x[3][a]);
            float2 bd = csubf(x[1][a], x[3][a]);
            float2 t3 = make_float2(bd.y, -bd.x);
            x[0][a] = caddf(t0, t2);
            x[1][a] = cmulf(caddf(t1, t3), wA1[a]);
            x[2][a] = cmulf(csubf(t0, t2), wA2[a]);
            x[3][a] = cmulf(csubf(t1, t3), wA3[a]);
        }
        #pragma unroll
        for (int b = 0; b < 4; b++) {
            float2 t0 = caddf(x[b][0], x[b][2]);
            float2 t1 = csubf(x[b][0], x[b][2]);
            float2 t2 = caddf(x[b][1], x[b][3]);
            float2 bd = csubf(x[b][1], x[b][3]);
            float2 t3 = make_float2(bd.y, -bd.x);
            const int k0 = kg + b * 1024;
            Hs[HsI(k0)]        = caddf(t0, t2);      // o=0
            Hs[HsI(k0 + 4096)] = caddf(t1, t3);      // o=1
            if (k0 == 0) Hs[HsI(8192)] = csubf(t0, t2);  // o=2 edge (k=8192)
        }
    }
    __syncthreads();
}

// First inverse stage (len=4, unit twiddles) fused with spectral multiply.
__device__ void ifft_first_mult(float2* Z, const float2* __restrict__ Hs, int tid) {
    for (int b = tid; b < NFFT/4; b += FFT_T) {
        const int i0 = 4*b;
        const int kb = digrev4_14(i0);
        float2 zz[4];
        #pragma unroll
        for (int s2 = 0; s2 < 4; s2++) {
            const int k = kb + s2 * 4096;
            float2 H;
            if (k <= 8192) H = Hs[HsI(k)];
            else { const int kc = 16384 - k; H = Hs[HsI(kc)]; H.y = -H.y; }
            zz[s2] = cmulf(Z[ZI(i0 + s2)], H);
        }
        float2 t0 = caddf(zz[0], zz[2]), t1 = csubf(zz[0], zz[2]);
        float2 t2 = caddf(zz[1], zz[3]);
        float2 bd = csubf(zz[1], zz[3]);
        float2 t3 = make_float2(-bd.y, bd.x);
        Z[ZI(i0)]     = caddf(t0, t2);
        Z[ZI(i0 + 1)] = caddf(t1, t3);
        Z[ZI(i0 + 2)] = csubf(t0, t2);
        Z[ZI(i0 + 3)] = csubf(t1, t3);
    }
    __syncthreads();
}

// Inverse DIT paired radix-16 pass: stage (len=L1) then (len=4*L1).
template<int L1, int TW1>
__device__ void ifft_dit_pass16(float2* Z, const float* C, int tid) {
    constexpr int q1 = L1 / 4, L2 = 4 * L1;
    constexpr int TW2 = TW1 - 2;
    const int p = tid & (q1 - 1);
    const int k1 = p << TW1;
    const float2 u1 = twc(C, k1);
    const float2 u2 = cmulf(u1, u1);
    const float2 u3 = cmulf(u2, u1);
    float2 v1[4], v2[4], v3[4];
    #pragma unroll
    for (int a = 0; a < 4; a++) {
        const int kk = (p + a*q1) << TW2;
        v1[a] = twc(C, kk);
        v2[a] = cmulf(v1[a], v1[a]);
        v3[a] = cmulf(v2[a], v1[a]);
    }
    #pragma unroll
    for (int half = 0; half < 2; half++) {
        const int g = tid + half * FFT_T;
        const int base = (g / q1) * L2 + p;
        float2 x[4][4];
        #pragma unroll
        for (int b = 0; b < 4; b++)
            #pragma unroll
            for (int a = 0; a < 4; a++)
                x[b][a] = Z[ZI(base + a*q1 + b*L1)];
        #pragma unroll
        for (int b = 0; b < 4; b++) {
            float2 a0 = x[b][0];
            float2 a1 = cmulconjf(x[b][1], u1);
            float2 a2 = cmulconjf(x[b][2], u2);
            float2 a3 = cmulconjf(x[b][3], u3);
            float2 t0 = caddf(a0, a2), t1 = csubf(a0, a2);
            float2 t2 = caddf(a1, a3);
            float2 bd = csubf(a1, a3);
            float2 t3 = make_float2(-bd.y, bd.x);
            x[b][0] = caddf(t0, t2);
            x[b][1] = caddf(t1, t3);
            x[b][2] = csubf(t0, t2);
            x[b][3] = csubf(t1, t3);
        }
        #pragma unroll
        for (int a = 0; a < 4; a++) {
            float2 b0 = x[0][a];
            float2 b1 = cmulconjf(x[1][a], v1[a]);
            float2 b2 = cmulconjf(x[2][a], v2[a]);
            float2 b3 = cmulconjf(x[3][a], v3[a]);
            float2 t0 = caddf(b0, b2), t1 = csubf(b0, b2);
            float2 t2 = caddf(b1, b3);
            float2 bd = csubf(b1, b3);
            float2 t3 = make_float2(-bd.y, bd.x);
            Z[ZI(base + a*q1 + 0*L1)] = caddf(t0, t2);
            Z[ZI(base + a*q1 + 1*L1)] = caddf(t1, t3);
            Z[ZI(base + a*q1 + 2*L1)] = csubf(t0, t2);
            Z[ZI(base + a*q1 + 3*L1)] = csubf(t1, t3);
        }
    }
    __syncthreads();
}

__global__ __launch_bounds__(FFT_T, 1) void fft_conv_kernel(
    const float* __restrict__ sw, const float* __restrict__ sb)
{
    extern __shared__ float2 sm[];
    float2* Z  = sm;
    float2* Hs = sm + Z_PAD_SZ;
    float*  C  = (float*)(sm + Z_PAD_SZ + HS_PAD_SZ);
    const int c   = blockIdx.x;
    const int tid = threadIdx.x;

    for (int k = tid; k <= 4096; k += FFT_T)
        C[k] = cosf(3.834951969714103e-4f * (float)k);   // cos(2*pi*k/16384)
    __syncthreads();

    // ---- filter FFT; final pass writes half-spectrum straight to smem Hs ----
    fft_dif_first(Z, C, g_COEFt + (size_t)c * LSEQ, tid);
    fft_dif_pass16<4096, 2>(Z, C, tid);
    fft_dif_pass16<256, 6>(Z, C, tid);
    fft_dif_pass16_stash(Z, C, Hs, tid);

    // ---- v FFT with fused depthwise short-conv ----
    const float w0 = sw[c*3], w1 = sw[c*3+1], w2 = sw[c*3+2], cb = sb[c];
    fft_dif_first_conv(Z, C, g_Vcm + (size_t)c * MTOT, w0, w1, w2, cb, tid);
    fft_dif_pass16<4096, 2>(Z, C, tid);
    fft_dif_pass16<256, 6>(Z, C, tid);
    fft_dif_pass16<16, 10>(Z, C, tid);

    // ---- inverse: multiply (from smem half-spectrum) fused into len-4 stage
    ifft_first_mult(Z, Hs, tid);
    ifft_dit_pass16<16, 10>(Z, C, tid);
    ifft_dit_pass16<256, 6>(Z, C, tid);

    // ---- final paired pass fused with gate + bf16 hi/lo store ([c][m]) ----
    const float* x2 = g_X2t + (size_t)c * MTOT;
    __nv_bfloat16* goh = g_Gh + (size_t)c * MTOT;
    __nv_bfloat16* gol = g_Gl + (size_t)c * MTOT;
    const float scale = 1.0f / (float)NFFT;
    for (int p = tid; p < 1024; p += FFT_T) {
        float2 x[4][4];
        #pragma unroll
        for (int b = 0; b < 4; b++)
            #pragma unroll
            for (int a = 0; a < 4; a++)
                x[b][a] = Z[ZI(p + a*1024 + b*4096)];
        const float2 u1 = twc(C, p << 2);
        const float2 u2 = cmulf(u1, u1);
        const float2 u3 = cmulf(u2, u1);
        #pragma unroll
        for (int b = 0; b < 4; b++) {
            float2 a0 = x[b][0];
            float2 a1 = cmulconjf(x[b][1], u1);
            float2 a2 = cmulconjf(x[b][2], u2);
            float2 a3 = cmulconjf(x[b][3], u3);
            float2 t0 = caddf(a0, a2), t1 = csubf(a0, a2);
            float2 t2 = caddf(a1, a3);
            float2 bd = csubf(a1, a3);
            float2 t3 = make_float2(-bd.y, bd.x);
            x[b][0] = caddf(t0, t2);
            x[b][1] = caddf(t1, t3);
            x[b][2] = csubf(t0, t2);
            x[b][3] = csubf(t1, t3);
        }
        #pragma unroll
        for (int a = 0; a < 4; a++) {
            const int k2 = p + a*1024;
            const float2 q1 = twc(C, k2);
            const float2 q2 = cmulf(q1, q1);
            const float2 q3 = cmulf(q2, q1);
            float2 b0 = x[0][a];
            float2 b1 = cmulconjf(x[1][a], q1);
            float2 b2 = cmulconjf(x[2][a], q2);
            float2 b3 = cmulconjf(x[3][a], q3);
            float2 t0 = caddf(b0, b2), t1 = csubf(b0, b2);
            float2 t2 = caddf(b1, b3);
            float2 bd = csubf(b1, b3);
            float2 t3 = make_float2(-bd.y, bd.x);
            float2 o0 = caddf(t0, t2);         // time t
            float2 o1 = caddf(t1, t3);         // time t+4096
            const int t = p + a*1024;
            float gv;
            __nv_bfloat16 hh, ll;
            gv = x2[t]               * (o0.x * scale); bf16_split(gv, hh, ll);
            goh[t] = hh;               gol[t] = ll;
            gv = x2[LSEQ + t]        * (o0.y * scale); bf16_split(gv, hh, ll);
            goh[LSEQ + t] = hh;        gol[LSEQ + t] = ll;
            gv = x2[t + 4096]        * (o1.x * scale); bf16_split(gv, hh, ll);
            goh[t + 4096] = hh;        gol[t + 4096] = ll;
            gv = x2[LSEQ + t + 4096] * (o1.y * scale); bf16_split(gv, hh, ll);
            goh[LSEQ + t + 4096] = hh; gol[LSEQ + t + 4096] = ll;
        }
    }
}

// ============================================================================
extern "C" void kernel_launch(void* const* d_in, const int* in_sizes, int n_in,
                              void* d_out, int out_size)
{
    const float* x   = (const float*)d_in[0];
    const float* ipw = (const float*)d_in[1];
    const float* ipb = (const float*)d_in[2];
    const float* sw  = (const float*)d_in[3];
    const float* sb  = (const float*)d_in[4];
    const float* fw1 = (const float*)d_in[5];
    const float* fb1 = (const float*)d_in[6];
    const float* fw2 = (const float*)d_in[7];
    const float* fb2 = (const float*)d_in[8];
    const float* fw3 = (const float*)d_in[9];
    const float* fb3 = (const float*)d_in[10];
    const float* ow  = (const float*)d_in[11];
    const float* ob  = (const float*)d_in[12];
    float* out = (float*)d_out;

    cudaFuncSetAttribute(fft_conv_kernel,
                         cudaFuncAttributeMaxDynamicSharedMemorySize, FFT_SMEM);
    cudaFuncSetAttribute(gemm_bf16_tc<0>,
                         cudaFuncAttributeMaxDynamicSharedMemorySize, GSM_BYTES);
    cudaFuncSetAttribute(gemm_bf16_tc<1>,
                         cudaFuncAttributeMaxDynamicSharedMemorySize, GSM_BYTES);

    // 1) split x and weights into bf16 hi/lo (coalesced gathers)
    convert_x_split<<<MTOT*CH/4/256, 256>>>(x);
    convert_wip_split<<<dim3(32, 32), 256>>>(ipw);
    convert_wout_split<<<dim3(32, 32), dim3(32, 32)>>>(ow);
    // 2) in_proj GEMM; epilogue writes v/x2 directly in channel-major
    gemm_bf16_tc<0><<<dim3(16, 128), 256, GSM_BYTES>>>(ipb, nullptr);
    // 3) filter MLP hidden + coef GEMM (transposed epilogue -> COEFt)
    filter_h2<<<LSEQ, 128>>>(fw1, fb1, fw2, fb2);
    gemm_coef<<<dim3(8, 64), 256>>>(fw3, fb3);
    // 4) FFT long conv (fused short-conv, stash, mult, gate, bf16 split out)
    fft_conv_kernel<<<CH, FFT_T, FFT_SMEM>>>(sw, sb);
    // 5) out GEMM reads gated activations k-major via ldmatrix.trans
    gemm_bf16_tc<1><<<dim3(8, 128), 256, GSM_BYTES>>>(ob, out);
}